// round 4
// baseline (speedup 1.0000x reference)
#include <cuda_runtime.h>
#include <cuda_fp16.h>
#include <cstdint>

#define NV 65536
#define KK 27
#define CH 128

// tcgen05 fast path only in the arch-specific sm_103a pass (plain compute_103
// rejects tcgen05 in ptxas).
#if defined(__CUDA_ARCH__) && (defined(__CUDA_ARCH_FEAT_SM103_ALL) || \
    (defined(__CUDA_ARCH_SPECIFIC__) && (__CUDA_ARCH_SPECIFIC__ == 1030)))
#define TC_PATH 1
#else
#define TC_PATH 0
#endif

// ---------------- scratch (static __device__, no allocs) ----------------
// g_nbr holds (input_row + 1); 0 means "no neighbor" -> reads g_f16 row 0,
// which is statically zero and never written (k_prep writes rows 1..NV).
__device__ __align__(256) int    g_nbr[KK * NV];            // 7 MB, zero-init
__device__ __align__(256) __half g_f16[(NV + 1) * CH];      // row 0 = zeros
__device__ __align__(256) __half g_w16[KK * CH * CH];       // 864 KB, per-path layout

// ---------------- common helpers ----------------
__device__ __forceinline__ uint32_t smem_to_u32(const void* smem_ptr) {
    uint32_t addr;
    asm("{ .reg .u64 tmp; cvta.to.shared.u64 tmp, %1; cvt.u32.u64 %0, tmp; }"
        : "=r"(addr) : "l"(smem_ptr));
    return addr;
}

#define SMEM_BYTES 225280

// cp.async (LDGSTS) helpers -- legal on both compile passes (sm_80+)
#define CP_ASYNC16(dst, src) \
    asm volatile("cp.async.cg.shared.global [%0], [%1], 16;" \
                 :: "r"(dst), "l"(src) : "memory")
#define CP_COMMIT() asm volatile("cp.async.commit_group;" ::: "memory")
#define CP_WAIT(n)  asm volatile("cp.async.wait_group %0;" :: "n"(n) : "memory")

#if TC_PATH
// ---------------- tcgen05 helpers ----------------
__device__ __forceinline__ uint32_t elect_one_pred() {
    uint32_t pred;
    asm volatile(
        "{\n\t.reg .pred p;\n\t"
        "elect.sync _|p, 0xFFFFFFFF;\n\t"
        "selp.b32 %0, 1, 0, p;\n\t}"
        : "=r"(pred));
    return pred;
}

#define TCGEN05_ALLOC(smem_result_addr, nCols) \
    asm volatile("tcgen05.alloc.cta_group::1.sync.aligned.shared::cta.b32 [%0], %1;" \
                 :: "r"((uint32_t)(smem_result_addr)), "r"((uint32_t)(nCols)) : "memory")
#define TCGEN05_DEALLOC(tmem_addr, nCols) \
    asm volatile("tcgen05.dealloc.cta_group::1.sync.aligned.b32 %0, %1;" \
                 :: "r"(tmem_addr), "r"((uint32_t)(nCols)))
#define TCGEN05_RELINQUISH_ALLOC_PERMIT() \
    asm volatile("tcgen05.relinquish_alloc_permit.cta_group::1.sync.aligned;")
#define TCGEN05_WAIT_LD() asm volatile("tcgen05.wait::ld.sync.aligned;" ::: "memory")
#define TCGEN05_FENCE_AFTER()  asm volatile("tcgen05.fence::after_thread_sync;" ::: "memory")
#define TCGEN05_COMMIT(mbar_smem_addr) \
    asm volatile("tcgen05.commit.cta_group::1.mbarrier::arrive::one.shared::cluster.b64 [%0];" \
                 :: "r"((uint32_t)(mbar_smem_addr)) : "memory")
#define FENCE_PROXY_ASYNC_SHARED_CTA() \
    asm volatile("fence.proxy.async.shared::cta;" ::: "memory")
#define MBARRIER_INIT(mbar_smem_addr, count) \
    asm volatile("mbarrier.init.shared.b64 [%0], %1;" \
                 :: "r"((uint32_t)(mbar_smem_addr)), "r"((uint32_t)(count)) : "memory")
#define MBARRIER_ARRIVE(mbar_smem_addr) \
    asm volatile("mbarrier.arrive.shared.b64 _, [%0];" \
                 :: "r"((uint32_t)(mbar_smem_addr)) : "memory")
#define MBARRIER_WAIT_PARITY(mbar_smem_addr, phase_parity) do { \
    uint32_t _mbar = (uint32_t)(mbar_smem_addr); \
    uint32_t _parity = (uint32_t)(phase_parity); \
    uint32_t _done; \
    asm volatile( \
        "{\n\t.reg .pred p;\n\t" \
        "mbarrier.try_wait.parity.acquire.cta.shared::cta.b64 p, [%1], %2;\n\t" \
        "selp.b32 %0, 1, 0, p;\n\t}" \
        : "=r"(_done) : "r"(_mbar), "r"(_parity) : "memory"); \
    if (!_done) { \
        asm volatile( \
            "{\n\t.reg .pred P1;\n\t" \
            "WAIT_LOOP_%=:\n\t" \
            "mbarrier.try_wait.parity.acquire.cta.shared::cta.b64 P1, [%0], %1, 0x989680;\n\t" \
            "@P1 bra.uni WAIT_DONE_%=;\n\t" \
            "bra.uni WAIT_LOOP_%=;\n\t" \
            "WAIT_DONE_%=:\n\t}" \
            :: "r"(_mbar), "r"(_parity) : "memory"); \
    } \
} while(0)

// SS-mode f16 MMA: both A and B as SMEM descriptors.
#define TCGEN05_MMA_F16_SS(d_tmem, a_desc, b_desc, idesc, enable_d) do { \
    uint32_t _enable = (enable_d) ? 1 : 0; \
    uint32_t _zero = 0; \
    asm volatile( \
        "{\n\t.reg .pred p;\n\t" \
        "setp.ne.u32 p, %6, 0;\n\t" \
        "tcgen05.mma.cta_group::1.kind::f16 [%0], %1, %2, %3, " \
        "{%4, %4, %4, %4}, p;\n\t}" \
        :: "r"(d_tmem), "l"(a_desc), "l"(b_desc), "r"(idesc), \
           "r"(_zero), "r"(_zero), "r"(_enable) \
        : "memory"); \
} while(0)

#define TCGEN05_LD_32X32B_X32(r, tmem_addr) \
    asm volatile( \
        "tcgen05.ld.sync.aligned.32x32b.x32.b32 " \
        "{%0, %1, %2, %3, %4, %5, %6, %7, " \
        " %8, %9, %10, %11, %12, %13, %14, %15, " \
        " %16, %17, %18, %19, %20, %21, %22, %23, " \
        " %24, %25, %26, %27, %28, %29, %30, %31}, [%32];" \
        : "=r"((r)[0]),  "=r"((r)[1]),  "=r"((r)[2]),  "=r"((r)[3]), \
          "=r"((r)[4]),  "=r"((r)[5]),  "=r"((r)[6]),  "=r"((r)[7]), \
          "=r"((r)[8]),  "=r"((r)[9]),  "=r"((r)[10]), "=r"((r)[11]), \
          "=r"((r)[12]), "=r"((r)[13]), "=r"((r)[14]), "=r"((r)[15]), \
          "=r"((r)[16]), "=r"((r)[17]), "=r"((r)[18]), "=r"((r)[19]), \
          "=r"((r)[20]), "=r"((r)[21]), "=r"((r)[22]), "=r"((r)[23]), \
          "=r"((r)[24]), "=r"((r)[25]), "=r"((r)[26]), "=r"((r)[27]), \
          "=r"((r)[28]), "=r"((r)[29]), "=r"((r)[30]), "=r"((r)[31]) \
        : "r"(tmem_addr))

static constexpr uint64_t SMEM_DESC_BASE_SW128 =
    (uint64_t(2) << 61) | (uint64_t(1) << 46) | (uint64_t(64) << 32) | (uint64_t(1) << 16);
#define MAKE_SMEM_DESC(base_addr) \
    (SMEM_DESC_BASE_SW128 | ((uint64_t)((base_addr) >> 4) & 0x3FFF))

// kind::f16, f16 inputs, f32 acc, M=128, N=128, K-major A and B
#define MMA_IDESC_F16 0x8200010u

// SMEM layout (TC): [0] tmem ptr, full mbar @8,16, empty mbar @24,32,
// bias @64..576, nbr cache @1024..28672 (27*256 ints),
// stage s: A @28672+s*98304 (64KB), W @+65536 (32KB). Total 225280.
#define NBR_OFF 1024
#define A_OFF(s) (28672u + (uint32_t)(s) * 98304u)
#define W_OFF(s) (A_OFF(s) + 65536u)
#define MB_FULL(s)  (8u + (uint32_t)(s) * 8u)
#define MB_EMPTY(s) (24u + (uint32_t)(s) * 8u)
#endif  // TC_PATH

// ---------------- fused prep kernel ----------------
// blocks [0, 6912): rulebook scatter (g_nbr = in_idx+1)
// blocks [6912, 23296): feature fp16 convert (shifted +1 row)
// blocks [23296, 25024): weight pack (per-path layout)
#define PREP_BLOCKS 25024

__global__ void k_prep(const float* __restrict__ f, const float* __restrict__ w,
                       const int* __restrict__ in_idx, const int* __restrict__ out_idx) {
    int b = blockIdx.x;
    if (b < 6912) {
        int i = b * 256 + threadIdx.x;            // [0, KK*NV)
        int o = out_idx[i];
        if (o < NV) g_nbr[(i / NV) * NV + o] = in_idx[i] + 1;
    } else if (b < 23296) {
        int i = (b - 6912) * 256 + threadIdx.x;   // [0, NV*64) half2 words
        float2 v = ((const float2*)f)[i];
        __half2 h;
        h.x = __float2half_rn(v.x);
        h.y = __float2half_rn(v.y);
        ((__half2*)g_f16)[i + 64] = h;            // +1 row shift (row 0 stays zero)
    } else {
        int i = (b - 23296) * 256 + threadIdx.x;
#if TC_PATH
        // W[k][cin][cout] -> B[k][cout(row)][cin(col)] fp16, SW128 blocked image
        if (i >= KK * CH * CH) return;
        int k = i >> 14;
        int r = (i >> 7) & 127;   // c_out (N row)
        int c = i & 127;          // c_in  (K col)
        float v = w[(k << 14) + (c << 7) + r];
        uint32_t atom = (uint32_t)(r >> 3) + ((uint32_t)(c >> 6) << 4);
        uint32_t off = atom * 1024u + (uint32_t)(r & 7) * 128u + (uint32_t)(c & 63) * 2u;
        off ^= (off >> 3) & 0x70u;
        g_w16[((uint32_t)k * 32768u + off) >> 1] = __float2half_rn(v);
#else
        // mma.sync B-fragment-ready image: [k][ktile(8)][ntile(16)][lane(32)][reg(2)] u32
        if (i >= KK * 8 * 16 * 32 * 2) return;
        int reg   = i & 1;
        int lane  = (i >> 1) & 31;
        int nt    = (i >> 6) & 15;
        int ktile = (i >> 10) & 7;
        int k     = i >> 13;
        int tig = lane & 3, gid = lane >> 2;
        int n    = nt * 8 + gid;
        int cin0 = ktile * 16 + tig * 2 + reg * 8;
        float w0 = w[(k * CH + cin0) * CH + n];
        float w1 = w[(k * CH + cin0 + 1) * CH + n];
        __half2 h;
        h.x = __float2half_rn(w0);
        h.y = __float2half_rn(w1);
        ((__half2*)g_w16)[i] = h;
#endif
    }
}

// ---------------- main kernel ----------------
#if TC_PATH

__global__ void __launch_bounds__(256, 1)
k_main(const float* __restrict__ bias, float* __restrict__ out) {
    extern __shared__ char smem[];
    uint32_t sb = smem_to_u32(smem);
    int tid = threadIdx.x;
    int wid = tid >> 5;
    int lid = tid & 31;
    int o0 = blockIdx.x * 256;

    if (wid == 0) TCGEN05_ALLOC(sb + 0, 256);
    if (tid == 0) {
        MBARRIER_INIT(sb + MB_FULL(0), 256);
        MBARRIER_INIT(sb + MB_FULL(1), 256);
        MBARRIER_INIT(sb + MB_EMPTY(0), 1);
        MBARRIER_INIT(sb + MB_EMPTY(1), 1);
    }
    if (tid < 128) ((float*)(smem + 64))[tid] = __ldg(&bias[tid]);
    // nbr cache: [k][r] for this CTA's 256 rows, coalesced
    {
        int* nc = (int*)(smem + NBR_OFF);
        #pragma unroll 9
        for (int j = 0; j < KK; ++j) nc[j * 256 + tid] = __ldg(&g_nbr[j * NV + o0 + tid]);
    }
    __syncthreads();
    uint32_t tmem;
    asm volatile("ld.shared.b32 %0, [%1];" : "=r"(tmem) : "r"(sb));
    if (wid == 0) TCGEN05_RELINQUISH_ALLOC_PERMIT();
    uint32_t leader = (wid == 0) ? elect_one_pred() : 0u;

    const int cchunk = tid & 15;                              // 16B chunk within row
    const uint32_t abase = ((uint32_t)(cchunk >> 3) << 15)    // slice * 32768
                         + (uint32_t)((cchunk & 7) << 4);     // (c&63)*2 bytes
    const char* fbase = (const char*)g_f16 + (size_t)cchunk * 16;

    int pe0 = 0, pe1 = 0;   // empty-barrier parities (producers)
    int pf0 = 0, pf1 = 0;   // full-barrier parities (leader)

    for (int k = 0; k < KK; ++k) {
        int s = k & 1;
        // producers: wait stage free (MMA k-2 complete)
        if (k >= 2) {
            if (s == 0) { MBARRIER_WAIT_PARITY(sb + MB_EMPTY(0), pe0); pe0 ^= 1; }
            else        { MBARRIER_WAIT_PARITY(sb + MB_EMPTY(1), pe1); pe1 ^= 1; }
        }
        // ---- issue A gather: 256 rows x 256B, 16 lanes per row, cp.async ----
        {
            const int* nc = (const int*)(smem + NBR_OFF) + k * 256;
            uint32_t As = sb + A_OFF(s);
            #pragma unroll
            for (int i = 0; i < 16; ++i) {
                int r = i * 16 + (tid >> 4);
                int nb = nc[r];                                   // LDS broadcast
                const char* src = fbase + ((size_t)nb << 8);      // nb*256B
                uint32_t off = abase + (uint32_t)r * 128u;
                off ^= (off >> 3) & 0x70u;                        // SW128 swizzle
                CP_ASYNC16(As + off, src);
            }
        }
        // ---- issue W copy: pre-swizzled 32KB image, verbatim ----
        {
            const char* wsrc = (const char*)g_w16 + (size_t)k * 32768;
            uint32_t Ws = sb + W_OFF(s);
            #pragma unroll
            for (int j = 0; j < 8; ++j) {
                uint32_t c16 = (uint32_t)(tid + j * 256) * 16u;
                CP_ASYNC16(Ws + c16, wsrc + c16);
            }
        }
        CP_COMMIT();
        if (k >= 1) {
            CP_WAIT(1);                      // stage for k-1 now complete
            FENCE_PROXY_ASYNC_SHARED_CTA();
            int t = s ^ 1;
            MBARRIER_ARRIVE(sb + MB_FULL(t));
            if (leader) {
                if (t == 0) { MBARRIER_WAIT_PARITY(sb + MB_FULL(0), pf0); pf0 ^= 1; }
                else        { MBARRIER_WAIT_PARITY(sb + MB_FULL(1), pf1); pf1 ^= 1; }
                int km1 = k - 1;
                uint64_t ad = MAKE_SMEM_DESC(sb + A_OFF(t));
                uint64_t bd = MAKE_SMEM_DESC(sb + W_OFF(t));
                #pragma unroll
                for (int mb = 0; mb < 2; ++mb) {
                    #pragma unroll
                    for (int ks = 0; ks < 8; ++ks) {
                        uint64_t aoff = (uint64_t)(mb * 1024)
                                      + ((ks < 4) ? (uint64_t)(2 * ks)
                                                  : (uint64_t)(2048 + 2 * (ks - 4)));
                        uint64_t boff = (ks < 4) ? (uint64_t)(2 * ks)
                                                 : (uint64_t)(1024 + 2 * (ks - 4));
                        TCGEN05_MMA_F16_SS(tmem + (uint32_t)(mb * 128), ad + aoff, bd + boff,
                                           MMA_IDESC_F16, !(km1 == 0 && ks == 0));
                    }
                }
                TCGEN05_COMMIT(sb + MB_EMPTY(t));
            }
        }
    }
    // ---- tail: k=26 (stage 0) ----
    CP_WAIT(0);
    FENCE_PROXY_ASYNC_SHARED_CTA();
    MBARRIER_ARRIVE(sb + MB_FULL(0));
    if (leader) {
        MBARRIER_WAIT_PARITY(sb + MB_FULL(0), pf0);
        uint64_t ad = MAKE_SMEM_DESC(sb + A_OFF(0));
        uint64_t bd = MAKE_SMEM_DESC(sb + W_OFF(0));
        #pragma unroll
        for (int mb = 0; mb < 2; ++mb) {
            #pragma unroll
            for (int ks = 0; ks < 8; ++ks) {
                uint64_t aoff = (uint64_t)(mb * 1024)
                              + ((ks < 4) ? (uint64_t)(2 * ks)
                                          : (uint64_t)(2048 + 2 * (ks - 4)));
                uint64_t boff = (ks < 4) ? (uint64_t)(2 * ks)
                                         : (uint64_t)(1024 + 2 * (ks - 4));
                TCGEN05_MMA_F16_SS(tmem + (uint32_t)(mb * 128), ad + aoff, bd + boff,
                                   MMA_IDESC_F16, true);
            }
        }
        TCGEN05_COMMIT(sb + MB_EMPTY(0));
    }
    // all threads: wait final MMA complete
    MBARRIER_WAIT_PARITY(sb + MB_EMPTY(0), pe0);
    TCGEN05_FENCE_AFTER();

    // ---- epilogue: warps 0-3 -> M-block0 (tmem cols 0-127), warps 4-7 -> +128 ----
    {
        int blk = wid >> 2;
        int row = blk * 128 + (wid & 3) * 32 + lid;
        uint32_t cbase = (uint32_t)(blk * 128);
        float* orow = out + (size_t)(o0 + row) * CH;
        const float* bsm = (const float*)(smem + 64);
        #pragma unroll
        for (int b = 0; b < 128; b += 32) {
            uint32_t d[32];
            TCGEN05_LD_32X32B_X32(d, tmem + cbase + (uint32_t)b);
            TCGEN05_WAIT_LD();
            #pragma unroll
            for (int c = 0; c < 32; c += 4) {
                float4 v;
                v.x = __uint_as_float(d[c + 0]) + bsm[b + c + 0];
                v.y = __uint_as_float(d[c + 1]) + bsm[b + c + 1];
                v.z = __uint_as_float(d[c + 2]) + bsm[b + c + 2];
                v.w = __uint_as_float(d[c + 3]) + bsm[b + c + 3];
                *(float4*)(orow + b + c) = v;
            }
        }
    }
    __syncthreads();
    if (wid == 0) TCGEN05_DEALLOC(tmem, 256);
}

#else  // ---------------- mma.sync fallback path ----------------
#define AW_OFF(s, w) (((s) * 8 + (w)) * 4096)
#define WW_OFF(s)    (65536 + (s) * 32768)
#define BIAS_OFF     131072

__device__ __forceinline__ void mma16816(float* c, uint32_t a0, uint32_t a1,
                                         uint32_t a2, uint32_t a3,
                                         uint32_t b0, uint32_t b1) {
    asm volatile(
        "mma.sync.aligned.m16n8k16.row.col.f32.f16.f16.f32 "
        "{%0,%1,%2,%3}, {%4,%5,%6,%7}, {%8,%9}, {%0,%1,%2,%3};"
        : "+f"(c[0]), "+f"(c[1]), "+f"(c[2]), "+f"(c[3])
        : "r"(a0), "r"(a1), "r"(a2), "r"(a3), "r"(b0), "r"(b1));
}

__global__ void __launch_bounds__(256, 1)
k_main(const float* __restrict__ bias, float* __restrict__ out) {
    extern __shared__ char smem[];
    uint32_t sb = smem_to_u32(smem);
    int tid = threadIdx.x;
    int wid = tid >> 5;
    int lane = tid & 31;

    if (tid < 128) ((float*)(smem + BIAS_OFF))[tid] = __ldg(&bias[tid]);

    for (int half = 0; half < 2; ++half) {
        int o0 = blockIdx.x * 256 + half * 128;
        float acc[16][4] = {};
        uint4 ra[8], rw[8];

        // prologue: load k=0
        {
            int nbl = (lane < 16) ? __ldg(&g_nbr[0 * NV + o0 + wid * 16 + lane]) : 0;
            #pragma unroll
            for (int i = 0; i < 8; ++i) {
                int row = i * 2 + (lane >> 4);
                int rn = __shfl_sync(0xffffffffu, nbl, row);
                ra[i] = __ldg((const uint4*)(g_f16 + (size_t)rn * CH) + (lane & 15));
            }
            const uint4* ws = (const uint4*)((const char*)g_w16) + wid * 256 + lane;
            #pragma unroll
            for (int i = 0; i < 8; ++i) rw[i] = __ldg(ws + i * 32);
            char* ab = smem + AW_OFF(0, wid);
            #pragma unroll
            for (int i = 0; i < 8; ++i) {
                int row = i * 2 + (lane >> 4);
                int c = lane & 15;
                *(uint4*)(ab + row * 256 + ((c ^ (row & 7)) << 4)) = ra[i];
            }
            uint4* wd = (uint4*)(smem + WW_OFF(0)) + wid * 256 + lane;
            #pragma unroll
            for (int i = 0; i < 8; ++i) wd[i * 32] = rw[i];
        }
        __syncthreads();

        int m = lane >> 3, rl = lane & 7;
        int lrow = rl + ((m & 1) << 3);

        for (int k = 0; k < KK; ++k) {
            int s = k & 1;
            if (k + 1 < KK) {
                int nbl = (lane < 16) ? __ldg(&g_nbr[(k + 1) * NV + o0 + wid * 16 + lane]) : 0;
                #pragma unroll
                for (int i = 0; i < 8; ++i) {
                    int row = i * 2 + (lane >> 4);
                    int rn = __shfl_sync(0xffffffffu, nbl, row);
                    ra[i] = __ldg((const uint4*)(g_f16 + (size_t)rn * CH) + (lane & 15));
                }
                const uint4* ws = (const uint4*)((const char*)g_w16 + (size_t)(k + 1) * 32768)
                                  + wid * 256 + lane;
                #pragma unroll
                for (int i = 0; i < 8; ++i) rw[i] = __ldg(ws + i * 32);
            }
            {
                uint32_t ab32 = sb + AW_OFF(s, wid);
                uint32_t wb32 = sb + WW_OFF(s);
                uint32_t arow = ab32 + (uint32_t)lrow * 256u;
                #pragma unroll
                for (int kt = 0; kt < 8; ++kt) {
                    int chunk = kt * 2 + (m >> 1);
                    uint32_t aaddr = arow + (uint32_t)((chunk ^ (lrow & 7)) << 4);
                    uint32_t a0, a1, a2, a3;
                    asm volatile(
                        "ldmatrix.sync.aligned.m8n8.x4.shared.b16 {%0,%1,%2,%3}, [%4];"
                        : "=r"(a0), "=r"(a1), "=r"(a2), "=r"(a3) : "r"(aaddr));
                    #pragma unroll
                    for (int nt = 0; nt < 16; ++nt) {
                        uint32_t baddr = wb32 + (uint32_t)((((kt << 4) + nt) << 8) + (lane << 3));
                        uint32_t b0, b1;
                        asm volatile("ld.shared.v2.b32 {%0,%1}, [%2];"
                                     : "=r"(b0), "=r"(b1) : "r"(baddr));
                        mma16816(acc[nt], a0, a1, a2, a3, b0, b1);
                    }
                }
            }
            if (k + 1 < KK) {
                char* ab = smem + AW_OFF(s ^ 1, wid);
                #pragma unroll
                for (int i = 0; i < 8; ++i) {
                    int row = i * 2 + (lane >> 4);
                    int c = lane & 15;
                    *(uint4*)(ab + row * 256 + ((c ^ (row & 7)) << 4)) = ra[i];
                }
                uint4* wd = (uint4*)(smem + WW_OFF(s ^ 1)) + wid * 256 + lane;
                #pragma unroll
                for (int i = 0; i < 8; ++i) wd[i * 32] = rw[i];
            }
            __syncthreads();
        }

        // epilogue
        {
            int gid = lane >> 2, tig = lane & 3;
            const float* bsm = (const float*)(smem + BIAS_OFF);
            size_t r0 = (size_t)(o0 + wid * 16 + gid);
            #pragma unroll
            for (int nt = 0; nt < 16; ++nt) {
                int col = nt * 8 + tig * 2;
                float2 bv = *(const float2*)(bsm + col);
                float2 v0 = make_float2(acc[nt][0] + bv.x, acc[nt][1] + bv.y);
                float2 v1 = make_float2(acc[nt][2] + bv.x, acc[nt][3] + bv.y);
                *(float2*)(out + r0 * CH + col) = v0;
                *(float2*)(out + (r0 + 8) * CH + col) = v1;
            }
        }
        __syncthreads();
    }
}
#endif  // TC_PATH

// ---------------- launch ----------------
extern "C" void kernel_launch(void* const* d_in, const int* in_sizes, int n_in,
                              void* d_out, int out_size) {
    const float* features = (const float*)d_in[0];
    const float* weight   = (const float*)d_in[1];
    const float* bias     = (const float*)d_in[2];
    const int*   in_idx   = (const int*)d_in[3];
    const int*   out_idx  = (const int*)d_in[4];
    float*       out      = (float*)d_out;

    cudaFuncSetAttribute(k_main, cudaFuncAttributeMaxDynamicSharedMemorySize, SMEM_BYTES);

    k_prep<<<PREP_BLOCKS, 256>>>(features, weight, in_idx, out_idx);
    k_main<<<NV / 256, 256, SMEM_BYTES>>>(bias, out);
}

// round 5
// speedup vs baseline: 3.1431x; 3.1431x over previous
#include <cuda_runtime.h>
#include <cuda_fp16.h>
#include <cstdint>

#define NV 65536
#define KK 27
#define CH 128

// tcgen05 fast path only in the arch-specific sm_103a pass (plain compute_103
// rejects tcgen05 in ptxas).
#if defined(__CUDA_ARCH__) && (defined(__CUDA_ARCH_FEAT_SM103_ALL) || \
    (defined(__CUDA_ARCH_SPECIFIC__) && (__CUDA_ARCH_SPECIFIC__ == 1030)))
#define TC_PATH 1
#else
#define TC_PATH 0
#endif

// ---------------- scratch (static __device__, no allocs) ----------------
// g_nbr holds (input_row + 1); 0 means "no neighbor" -> reads g_f16 row 0,
// which is statically zero and never written (k_prep writes rows 1..NV).
__device__ __align__(256) int    g_nbr[KK * NV];            // 7 MB, zero-init
__device__ __align__(256) __half g_f16[(NV + 1) * CH];      // row 0 = zeros
__device__ __align__(256) __half g_w16[KK * CH * CH];       // 864 KB, per-path layout

// ---------------- common helpers ----------------
__device__ __forceinline__ uint32_t smem_to_u32(const void* smem_ptr) {
    uint32_t addr;
    asm("{ .reg .u64 tmp; cvta.to.shared.u64 tmp, %1; cvt.u32.u64 %0, tmp; }"
        : "=r"(addr) : "l"(smem_ptr));
    return addr;
}

// TC path needs 80896 B; fallback fits in the same budget (66 KB).
#define SMEM_BYTES 80896

#if TC_PATH
// ---------------- tcgen05 helpers ----------------
__device__ __forceinline__ uint32_t elect_one_pred() {
    uint32_t pred;
    asm volatile(
        "{\n\t.reg .pred p;\n\t"
        "elect.sync _|p, 0xFFFFFFFF;\n\t"
        "selp.b32 %0, 1, 0, p;\n\t}"
        : "=r"(pred));
    return pred;
}

#define TCGEN05_ALLOC(smem_result_addr, nCols) \
    asm volatile("tcgen05.alloc.cta_group::1.sync.aligned.shared::cta.b32 [%0], %1;" \
                 :: "r"((uint32_t)(smem_result_addr)), "r"((uint32_t)(nCols)) : "memory")
#define TCGEN05_DEALLOC(tmem_addr, nCols) \
    asm volatile("tcgen05.dealloc.cta_group::1.sync.aligned.b32 %0, %1;" \
                 :: "r"(tmem_addr), "r"((uint32_t)(nCols)))
#define TCGEN05_RELINQUISH_ALLOC_PERMIT() \
    asm volatile("tcgen05.relinquish_alloc_permit.cta_group::1.sync.aligned;")
#define TCGEN05_WAIT_ST() asm volatile("tcgen05.wait::st.sync.aligned;" ::: "memory")
#define TCGEN05_WAIT_LD() asm volatile("tcgen05.wait::ld.sync.aligned;" ::: "memory")
#define TCGEN05_FENCE_BEFORE() asm volatile("tcgen05.fence::before_thread_sync;" ::: "memory")
#define TCGEN05_FENCE_AFTER()  asm volatile("tcgen05.fence::after_thread_sync;" ::: "memory")
#define TCGEN05_COMMIT(mbar_smem_addr) \
    asm volatile("tcgen05.commit.cta_group::1.mbarrier::arrive::one.shared::cluster.b64 [%0];" \
                 :: "r"((uint32_t)(mbar_smem_addr)) : "memory")
#define FENCE_PROXY_ASYNC_SHARED_CTA() \
    asm volatile("fence.proxy.async.shared::cta;" ::: "memory")
#define MBARRIER_INIT(mbar_smem_addr, count) \
    asm volatile("mbarrier.init.shared.b64 [%0], %1;" \
                 :: "r"((uint32_t)(mbar_smem_addr)), "r"((uint32_t)(count)) : "memory")
#define MBARRIER_WAIT_PARITY(mbar_smem_addr, phase_parity) do { \
    uint32_t _mbar = (uint32_t)(mbar_smem_addr); \
    uint32_t _parity = (uint32_t)(phase_parity); \
    uint32_t _done; \
    asm volatile( \
        "{\n\t.reg .pred p;\n\t" \
        "mbarrier.try_wait.parity.acquire.cta.shared::cta.b64 p, [%1], %2;\n\t" \
        "selp.b32 %0, 1, 0, p;\n\t}" \
        : "=r"(_done) : "r"(_mbar), "r"(_parity) : "memory"); \
    if (!_done) { \
        asm volatile( \
            "{\n\t.reg .pred P1;\n\t" \
            "WAIT_LOOP_%=:\n\t" \
            "mbarrier.try_wait.parity.acquire.cta.shared::cta.b64 P1, [%0], %1, 0x989680;\n\t" \
            "@P1 bra.uni WAIT_DONE_%=;\n\t" \
            "bra.uni WAIT_LOOP_%=;\n\t" \
            "WAIT_DONE_%=:\n\t}" \
            :: "r"(_mbar), "r"(_parity) : "memory"); \
    } \
} while(0)

// TS-mode f16 MMA: A in TMEM, B as SMEM descriptor.
#define TCGEN05_MMA_F16(d_tmem, a_tmem, b_smem_desc, idesc, enable_d) do { \
    uint32_t _enable = (enable_d) ? 1 : 0; \
    uint32_t _zero = 0; \
    asm volatile( \
        "{\n\t.reg .pred p;\n\t" \
        "setp.ne.u32 p, %6, 0;\n\t" \
        "tcgen05.mma.cta_group::1.kind::f16 [%0], [%1], %2, %3, " \
        "{%4, %4, %4, %4}, p;\n\t}" \
        :: "r"(d_tmem), "r"(a_tmem), "l"(b_smem_desc), "r"(idesc), \
           "r"(_zero), "r"(_zero), "r"(_enable) \
        : "memory"); \
} while(0)

#define TCGEN05_ST_32X32B_X64(tmem_addr, r) \
    asm volatile( \
        "tcgen05.st.sync.aligned.32x32b.x64.b32 [%0], " \
        "{%1, %2, %3, %4, %5, %6, %7, %8, " \
        " %9, %10, %11, %12, %13, %14, %15, %16, " \
        " %17, %18, %19, %20, %21, %22, %23, %24, " \
        " %25, %26, %27, %28, %29, %30, %31, %32, " \
        " %33, %34, %35, %36, %37, %38, %39, %40, " \
        " %41, %42, %43, %44, %45, %46, %47, %48, " \
        " %49, %50, %51, %52, %53, %54, %55, %56, " \
        " %57, %58, %59, %60, %61, %62, %63, %64};" \
        :: "r"(tmem_addr), \
           "r"((r)[0]),  "r"((r)[1]),  "r"((r)[2]),  "r"((r)[3]), \
           "r"((r)[4]),  "r"((r)[5]),  "r"((r)[6]),  "r"((r)[7]), \
           "r"((r)[8]),  "r"((r)[9]),  "r"((r)[10]), "r"((r)[11]), \
           "r"((r)[12]), "r"((r)[13]), "r"((r)[14]), "r"((r)[15]), \
           "r"((r)[16]), "r"((r)[17]), "r"((r)[18]), "r"((r)[19]), \
           "r"((r)[20]), "r"((r)[21]), "r"((r)[22]), "r"((r)[23]), \
           "r"((r)[24]), "r"((r)[25]), "r"((r)[26]), "r"((r)[27]), \
           "r"((r)[28]), "r"((r)[29]), "r"((r)[30]), "r"((r)[31]), \
           "r"((r)[32]), "r"((r)[33]), "r"((r)[34]), "r"((r)[35]), \
           "r"((r)[36]), "r"((r)[37]), "r"((r)[38]), "r"((r)[39]), \
           "r"((r)[40]), "r"((r)[41]), "r"((r)[42]), "r"((r)[43]), \
           "r"((r)[44]), "r"((r)[45]), "r"((r)[46]), "r"((r)[47]), \
           "r"((r)[48]), "r"((r)[49]), "r"((r)[50]), "r"((r)[51]), \
           "r"((r)[52]), "r"((r)[53]), "r"((r)[54]), "r"((r)[55]), \
           "r"((r)[56]), "r"((r)[57]), "r"((r)[58]), "r"((r)[59]), \
           "r"((r)[60]), "r"((r)[61]), "r"((r)[62]), "r"((r)[63]) \
        : "memory")

#define TCGEN05_LD_32X32B_X32(r, tmem_addr) \
    asm volatile( \
        "tcgen05.ld.sync.aligned.32x32b.x32.b32 " \
        "{%0, %1, %2, %3, %4, %5, %6, %7, " \
        " %8, %9, %10, %11, %12, %13, %14, %15, " \
        " %16, %17, %18, %19, %20, %21, %22, %23, " \
        " %24, %25, %26, %27, %28, %29, %30, %31}, [%32];" \
        : "=r"((r)[0]),  "=r"((r)[1]),  "=r"((r)[2]),  "=r"((r)[3]), \
          "=r"((r)[4]),  "=r"((r)[5]),  "=r"((r)[6]),  "=r"((r)[7]), \
          "=r"((r)[8]),  "=r"((r)[9]),  "=r"((r)[10]), "=r"((r)[11]), \
          "=r"((r)[12]), "=r"((r)[13]), "=r"((r)[14]), "=r"((r)[15]), \
          "=r"((r)[16]), "=r"((r)[17]), "=r"((r)[18]), "=r"((r)[19]), \
          "=r"((r)[20]), "=r"((r)[21]), "=r"((r)[22]), "=r"((r)[23]), \
          "=r"((r)[24]), "=r"((r)[25]), "=r"((r)[26]), "=r"((r)[27]), \
          "=r"((r)[28]), "=r"((r)[29]), "=r"((r)[30]), "=r"((r)[31]) \
        : "r"(tmem_addr))

static constexpr uint64_t SMEM_DESC_BASE_SW128 =
    (uint64_t(2) << 61) | (uint64_t(1) << 46) | (uint64_t(64) << 32) | (uint64_t(1) << 16);
#define MAKE_SMEM_DESC(base_addr) \
    (SMEM_DESC_BASE_SW128 | ((uint64_t)((base_addr) >> 4) & 0x3FFF))

// kind::f16, f16 inputs, f32 acc, M=128 (8<<24), N=128 (16<<17)
#define MMA_IDESC_F16 0x8200010u

// SMEM layout (TC, 79 KB -> 2 CTAs/SM):
// [0] tmem ptr, [8],[16] mbar[2], [64..576) bias,
// [1024..14848) nbr cache (27*128 ints), W stages @15360 (2 x 32KB).
// TMEM (256 cols -> 2 CTAs/SM): D f32 cols 0..127; A stage s: cols 128+64s.
#define NBR_OFF 1024
#define SM_W(s) (15360u + (uint32_t)(s) * 32768u)

__global__ void __launch_bounds__(256)
k_main(const float* __restrict__ bias, float* __restrict__ out) {
    extern __shared__ char smem[];
    uint32_t sb = smem_to_u32(smem);
    int tid = threadIdx.x;
    int wid = tid >> 5;
    int o0 = blockIdx.x * 128;

    if (wid == 4) TCGEN05_ALLOC(sb + 0, 256);
    if (tid == 0) { MBARRIER_INIT(sb + 8, 1); MBARRIER_INIT(sb + 16, 1); }
    if (tid < 128) ((float*)(smem + 64))[tid] = __ldg(&bias[tid]);
    // nbr cache: [k][r] for this CTA's 128 rows, coalesced
    if (tid < 128) {
        int* nc = (int*)(smem + NBR_OFF);
        #pragma unroll 9
        for (int j = 0; j < KK; ++j) nc[j * 128 + tid] = __ldg(&g_nbr[j * NV + o0 + tid]);
    }
    __syncthreads();
    uint32_t tmem;
    asm volatile("ld.shared.b32 %0, [%1];" : "=r"(tmem) : "r"(sb));
    if (wid == 4) TCGEN05_RELINQUISH_ALLOC_PERMIT();

    int pc0 = 0, pc1 = 0;
    for (int k = 0; k < KK; ++k) {
        int s = k & 1;
        if (k >= 2) {  // stage s reusable once MMA k-2 committed
            if (s == 0) { MBARRIER_WAIT_PARITY(sb + 8, pc0); pc0 ^= 1; }
            else        { MBARRIER_WAIT_PARITY(sb + 16, pc1); pc1 ^= 1; }
        }
        if (tid < 128) {
            // WG0: gather one fp16 feature row (or zero row) straight into TMEM
            int nb = ((const int*)(smem + NBR_OFF))[k * 128 + tid];
            uint32_t adst = tmem + 128u + (uint32_t)s * 64u + (((uint32_t)tid >> 5) << 21);
            const uint4* src = (const uint4*)(g_f16 + (size_t)nb * CH);
            uint32_t a[64];
            #pragma unroll
            for (int i = 0; i < 16; ++i) {
                uint4 v = __ldg(src + i);
                a[4*i] = v.x; a[4*i+1] = v.y; a[4*i+2] = v.z; a[4*i+3] = v.w;
            }
            TCGEN05_ST_32X32B_X64(adst, a);
            TCGEN05_WAIT_ST();
            TCGEN05_FENCE_BEFORE();
        } else {
            // WG1: copy pre-swizzled W[k] image (32KB) into stage-s SMEM
            int t = tid - 128;
            const uint4* sh = (const uint4*)((const char*)g_w16 + (size_t)k * 32768);
            uint4* dh = (uint4*)(smem + SM_W(s));
            #pragma unroll
            for (int i = 0; i < 16; ++i) dh[t + i * 128] = __ldg(sh + t + i * 128);
            FENCE_PROXY_ASYNC_SHARED_CTA();
        }
        __syncthreads();
        if (wid == 4) {
            TCGEN05_FENCE_AFTER();
            if (elect_one_pred()) {
                uint32_t ah = tmem + 128u + (uint32_t)s * 64u;
                uint64_t bh = MAKE_SMEM_DESC(sb + SM_W(s));
                #pragma unroll
                for (int ks = 0; ks < 8; ++ks) {
                    // K-step: 16 fp16 = 32B = 2 desc units; atom-col 1 at 16KB = 1024 units
                    uint64_t doff = (ks < 4) ? (uint64_t)(2 * ks)
                                             : (uint64_t)(1024 + 2 * (ks - 4));
                    TCGEN05_MMA_F16(tmem, ah + (uint32_t)ks * 8u, bh + doff, MMA_IDESC_F16,
                                    (k > 0 || ks > 0));
                }
                TCGEN05_COMMIT(sb + 8u + (uint32_t)s * 8u);
            }
        }
    }
    MBARRIER_WAIT_PARITY(sb + 16, pc1);   // k=25 (stage 1)
    MBARRIER_WAIT_PARITY(sb + 8, pc0);    // k=26 (stage 0)
    TCGEN05_FENCE_AFTER();

    if (tid < 128) {
        float* orow = out + (size_t)(o0 + tid) * CH;
        const float* bsm = (const float*)(smem + 64);
        #pragma unroll
        for (int b = 0; b < 128; b += 32) {
            uint32_t d[32];
            TCGEN05_LD_32X32B_X32(d, tmem + (uint32_t)b);
            TCGEN05_WAIT_LD();
            #pragma unroll
            for (int c = 0; c < 32; c += 4) {
                float4 v;
                v.x = __uint_as_float(d[c + 0]) + bsm[b + c + 0];
                v.y = __uint_as_float(d[c + 1]) + bsm[b + c + 1];
                v.z = __uint_as_float(d[c + 2]) + bsm[b + c + 2];
                v.w = __uint_as_float(d[c + 3]) + bsm[b + c + 3];
                *(float4*)(orow + b + c) = v;
            }
        }
    }
    __syncthreads();
    if (wid == 4) TCGEN05_DEALLOC(tmem, 256);
}

#else  // ---------------- mma.sync fallback path (single-buffered, fits 66KB) ----
#define A_FB(w)  ((w) * 4096)
#define W_FB     32768
#define BIAS_FB  65536

__device__ __forceinline__ void mma16816(float* c, uint32_t a0, uint32_t a1,
                                         uint32_t a2, uint32_t a3,
                                         uint32_t b0, uint32_t b1) {
    asm volatile(
        "mma.sync.aligned.m16n8k16.row.col.f32.f16.f16.f32 "
        "{%0,%1,%2,%3}, {%4,%5,%6,%7}, {%8,%9}, {%0,%1,%2,%3};"
        : "+f"(c[0]), "+f"(c[1]), "+f"(c[2]), "+f"(c[3])
        : "r"(a0), "r"(a1), "r"(a2), "r"(a3), "r"(b0), "r"(b1));
}

__global__ void __launch_bounds__(256)
k_main(const float* __restrict__ bias, float* __restrict__ out) {
    extern __shared__ char smem[];
    uint32_t sb = smem_to_u32(smem);
    int tid = threadIdx.x;
    int wid = tid >> 5;
    int lane = tid & 31;
    int o0 = blockIdx.x * 128;

    if (tid < 128) ((float*)(smem + BIAS_FB))[tid] = __ldg(&bias[tid]);

    float acc[16][4] = {};
    int m = lane >> 3, rl = lane & 7;
    int lrow = rl + ((m & 1) << 3);

    for (int k = 0; k < KK; ++k) {
        __syncthreads();   // previous iteration's MMA reads done
        // load A rows (16 per warp) + W image into SMEM
        {
            int nbl = (lane < 16) ? __ldg(&g_nbr[k * NV + o0 + wid * 16 + lane]) : 0;
            char* ab = smem + A_FB(wid);
            #pragma unroll
            for (int i = 0; i < 8; ++i) {
                int row = i * 2 + (lane >> 4);
                int rn = __shfl_sync(0xffffffffu, nbl, row);
                uint4 v = __ldg((const uint4*)(g_f16 + (size_t)rn * CH) + (lane & 15));
                int c = lane & 15;
                *(uint4*)(ab + row * 256 + ((c ^ (row & 7)) << 4)) = v;
            }
            const uint4* ws = (const uint4*)((const char*)g_w16 + (size_t)k * 32768)
                              + wid * 256 + lane;
            uint4* wd = (uint4*)(smem + W_FB) + wid * 256 + lane;
            #pragma unroll
            for (int i = 0; i < 8; ++i) wd[i * 32] = __ldg(ws + i * 32);
        }
        __syncthreads();
        {
            uint32_t ab32 = sb + A_FB(wid);
            uint32_t wb32 = sb + W_FB;
            uint32_t arow = ab32 + (uint32_t)lrow * 256u;
            #pragma unroll
            for (int kt = 0; kt < 8; ++kt) {
                int chunk = kt * 2 + (m >> 1);
                uint32_t aaddr = arow + (uint32_t)((chunk ^ (lrow & 7)) << 4);
                uint32_t a0, a1, a2, a3;
                asm volatile(
                    "ldmatrix.sync.aligned.m8n8.x4.shared.b16 {%0,%1,%2,%3}, [%4];"
                    : "=r"(a0), "=r"(a1), "=r"(a2), "=r"(a3) : "r"(aaddr));
                #pragma unroll
                for (int nt = 0; nt < 16; ++nt) {
                    uint32_t baddr = wb32 + (uint32_t)((((kt << 4) + nt) << 8) + (lane << 3));
                    uint32_t b0, b1;
                    asm volatile("ld.shared.v2.b32 {%0,%1}, [%2];"
                                 : "=r"(b0), "=r"(b1) : "r"(baddr));
                    mma16816(acc[nt], a0, a1, a2, a3, b0, b1);
                }
            }
        }
    }

    // epilogue
    {
        int gid = lane >> 2, tig = lane & 3;
        const float* bsm = (const float*)(smem + BIAS_FB);
        size_t r0 = (size_t)(o0 + wid * 16 + gid);
        #pragma unroll
        for (int nt = 0; nt < 16; ++nt) {
            int col = nt * 8 + tig * 2;
            float2 bv = *(const float2*)(bsm + col);
            float2 v0 = make_float2(acc[nt][0] + bv.x, acc[nt][1] + bv.y);
            float2 v1 = make_float2(acc[nt][2] + bv.x, acc[nt][3] + bv.y);
            *(float2*)(out + r0 * CH + col) = v0;
            *(float2*)(out + (r0 + 8) * CH + col) = v1;
        }
    }
}
#endif  // TC_PATH

// ---------------- fused prep kernel ----------------
// blocks [0, 6912): rulebook scatter (g_nbr = in_idx+1)
// blocks [6912, 23296): feature fp16 convert (shifted +1 row)
// blocks [23296, 25024): weight pack (per-path layout)
#define PREP_BLOCKS 25024

__global__ void k_prep(const float* __restrict__ f, const float* __restrict__ w,
                       const int* __restrict__ in_idx, const int* __restrict__ out_idx) {
    int b = blockIdx.x;
    if (b < 6912) {
        int i = b * 256 + threadIdx.x;            // [0, KK*NV)
        int o = out_idx[i];
        if (o < NV) g_nbr[(i / NV) * NV + o] = in_idx[i] + 1;
    } else if (b < 23296) {
        int i = (b - 6912) * 256 + threadIdx.x;   // [0, NV*64) half2 words
        float2 v = ((const float2*)f)[i];
        __half2 h;
        h.x = __float2half_rn(v.x);
        h.y = __float2half_rn(v.y);
        ((__half2*)g_f16)[i + 64] = h;            // +1 row shift (row 0 stays zero)
    } else {
        int i = (b - 23296) * 256 + threadIdx.x;
#if TC_PATH
        // W[k][cin][cout] -> B[k][cout(row)][cin(col)] fp16, SW128 blocked image
        if (i >= KK * CH * CH) return;
        int k = i >> 14;
        int r = (i >> 7) & 127;   // c_out (N row)
        int c = i & 127;          // c_in  (K col)
        float v = w[(k << 14) + (c << 7) + r];
        uint32_t atom = (uint32_t)(r >> 3) + ((uint32_t)(c >> 6) << 4);
        uint32_t off = atom * 1024u + (uint32_t)(r & 7) * 128u + (uint32_t)(c & 63) * 2u;
        off ^= (off >> 3) & 0x70u;
        g_w16[((uint32_t)k * 32768u + off) >> 1] = __float2half_rn(v);
#else
        // mma.sync B-fragment-ready image: [k][ktile(8)][ntile(16)][lane(32)][reg(2)] u32
        if (i >= KK * 8 * 16 * 32 * 2) return;
        int reg   = i & 1;
        int lane  = (i >> 1) & 31;
        int nt    = (i >> 6) & 15;
        int ktile = (i >> 10) & 7;
        int k     = i >> 13;
        int tig = lane & 3, gid = lane >> 2;
        int n    = nt * 8 + gid;
        int cin0 = ktile * 16 + tig * 2 + reg * 8;
        float w0 = w[(k * CH + cin0) * CH + n];
        float w1 = w[(k * CH + cin0 + 1) * CH + n];
        __half2 h;
        h.x = __float2half_rn(w0);
        h.y = __float2half_rn(w1);
        ((__half2*)g_w16)[i] = h;
#endif
    }
}

// ---------------- launch ----------------
extern "C" void kernel_launch(void* const* d_in, const int* in_sizes, int n_in,
                              void* d_out, int out_size) {
    const float* features = (const float*)d_in[0];
    const float* weight   = (const float*)d_in[1];
    const float* bias     = (const float*)d_in[2];
    const int*   in_idx   = (const int*)d_in[3];
    const int*   out_idx  = (const int*)d_in[4];
    float*       out      = (float*)d_out;

    cudaFuncSetAttribute(k_main, cudaFuncAttributeMaxDynamicSharedMemorySize, SMEM_BYTES);

    k_prep<<<PREP_BLOCKS, 256>>>(features, weight, in_idx, out_idx);
    k_main<<<NV / 128, 256, SMEM_BYTES>>>(bias, out);
}

// round 6
// speedup vs baseline: 3.2875x; 1.0459x over previous
#include <cuda_runtime.h>
#include <cuda_fp16.h>
#include <cstdint>

#define NV 65536
#define KK 27
#define CH 128

// tcgen05 fast path only in the arch-specific sm_103a pass (plain compute_103
// rejects tcgen05 in ptxas).
#if defined(__CUDA_ARCH__) && (defined(__CUDA_ARCH_FEAT_SM103_ALL) || \
    (defined(__CUDA_ARCH_SPECIFIC__) && (__CUDA_ARCH_SPECIFIC__ == 1030)))
#define TC_PATH 1
#else
#define TC_PATH 0
#endif

// ---------------- scratch (static __device__, no allocs) ----------------
// g_nbr holds (input_row + 1); 0 means "no neighbor" -> reads g_f16 row 0,
// which is statically zero and never written (k_prep writes rows 1..NV).
__device__ __align__(256) int    g_nbr[KK * NV];            // 7 MB, zero-init
__device__ __align__(256) __half g_f16[(NV + 1) * CH];      // row 0 = zeros
__device__ __align__(256) __half g_w16[KK * CH * CH];       // 864 KB, per-path layout

// ---------------- common helpers ----------------
__device__ __forceinline__ uint32_t smem_to_u32(const void* smem_ptr) {
    uint32_t addr;
    asm("{ .reg .u64 tmp; cvta.to.shared.u64 tmp, %1; cvt.u32.u64 %0, tmp; }"
        : "=r"(addr) : "l"(smem_ptr));
    return addr;
}

// TC path: nbr cache + A tile (32KB) + W tile (32KB) = 80896 B -> 2 CTAs/SM.
#define SMEM_BYTES 80896

#if TC_PATH
// ---------------- tcgen05 helpers ----------------
__device__ __forceinline__ uint32_t elect_one_pred() {
    uint32_t pred;
    asm volatile(
        "{\n\t.reg .pred p;\n\t"
        "elect.sync _|p, 0xFFFFFFFF;\n\t"
        "selp.b32 %0, 1, 0, p;\n\t}"
        : "=r"(pred));
    return pred;
}

#define TCGEN05_ALLOC(smem_result_addr, nCols) \
    asm volatile("tcgen05.alloc.cta_group::1.sync.aligned.shared::cta.b32 [%0], %1;" \
                 :: "r"((uint32_t)(smem_result_addr)), "r"((uint32_t)(nCols)) : "memory")
#define TCGEN05_DEALLOC(tmem_addr, nCols) \
    asm volatile("tcgen05.dealloc.cta_group::1.sync.aligned.b32 %0, %1;" \
                 :: "r"(tmem_addr), "r"((uint32_t)(nCols)))
#define TCGEN05_RELINQUISH_ALLOC_PERMIT() \
    asm volatile("tcgen05.relinquish_alloc_permit.cta_group::1.sync.aligned;")
#define TCGEN05_WAIT_LD() asm volatile("tcgen05.wait::ld.sync.aligned;" ::: "memory")
#define TCGEN05_FENCE_AFTER()  asm volatile("tcgen05.fence::after_thread_sync;" ::: "memory")
#define TCGEN05_COMMIT(mbar_smem_addr) \
    asm volatile("tcgen05.commit.cta_group::1.mbarrier::arrive::one.shared::cluster.b64 [%0];" \
                 :: "r"((uint32_t)(mbar_smem_addr)) : "memory")
#define FENCE_PROXY_ASYNC_SHARED_CTA() \
    asm volatile("fence.proxy.async.shared::cta;" ::: "memory")
#define MBARRIER_INIT(mbar_smem_addr, count) \
    asm volatile("mbarrier.init.shared.b64 [%0], %1;" \
                 :: "r"((uint32_t)(mbar_smem_addr)), "r"((uint32_t)(count)) : "memory")
#define MBARRIER_WAIT_PARITY(mbar_smem_addr, phase_parity) do { \
    uint32_t _mbar = (uint32_t)(mbar_smem_addr); \
    uint32_t _parity = (uint32_t)(phase_parity); \
    uint32_t _done; \
    asm volatile( \
        "{\n\t.reg .pred p;\n\t" \
        "mbarrier.try_wait.parity.acquire.cta.shared::cta.b64 p, [%1], %2;\n\t" \
        "selp.b32 %0, 1, 0, p;\n\t}" \
        : "=r"(_done) : "r"(_mbar), "r"(_parity) : "memory"); \
    if (!_done) { \
        asm volatile( \
            "{\n\t.reg .pred P1;\n\t" \
            "WAIT_LOOP_%=:\n\t" \
            "mbarrier.try_wait.parity.acquire.cta.shared::cta.b64 P1, [%0], %1, 0x989680;\n\t" \
            "@P1 bra.uni WAIT_DONE_%=;\n\t" \
            "bra.uni WAIT_LOOP_%=;\n\t" \
            "WAIT_DONE_%=:\n\t}" \
            :: "r"(_mbar), "r"(_parity) : "memory"); \
    } \
} while(0)

// SS-mode f16 MMA: both A and B as SMEM descriptors (numerically validated R3).
#define TCGEN05_MMA_F16_SS(d_tmem, a_desc, b_desc, idesc, enable_d) do { \
    uint32_t _enable = (enable_d) ? 1 : 0; \
    uint32_t _zero = 0; \
    asm volatile( \
        "{\n\t.reg .pred p;\n\t" \
        "setp.ne.u32 p, %6, 0;\n\t" \
        "tcgen05.mma.cta_group::1.kind::f16 [%0], %1, %2, %3, " \
        "{%4, %4, %4, %4}, p;\n\t}" \
        :: "r"(d_tmem), "l"(a_desc), "l"(b_desc), "r"(idesc), \
           "r"(_zero), "r"(_zero), "r"(_enable) \
        : "memory"); \
} while(0)

#define TCGEN05_LD_32X32B_X32(r, tmem_addr) \
    asm volatile( \
        "tcgen05.ld.sync.aligned.32x32b.x32.b32 " \
        "{%0, %1, %2, %3, %4, %5, %6, %7, " \
        " %8, %9, %10, %11, %12, %13, %14, %15, " \
        " %16, %17, %18, %19, %20, %21, %22, %23, " \
        " %24, %25, %26, %27, %28, %29, %30, %31}, [%32];" \
        : "=r"((r)[0]),  "=r"((r)[1]),  "=r"((r)[2]),  "=r"((r)[3]), \
          "=r"((r)[4]),  "=r"((r)[5]),  "=r"((r)[6]),  "=r"((r)[7]), \
          "=r"((r)[8]),  "=r"((r)[9]),  "=r"((r)[10]), "=r"((r)[11]), \
          "=r"((r)[12]), "=r"((r)[13]), "=r"((r)[14]), "=r"((r)[15]), \
          "=r"((r)[16]), "=r"((r)[17]), "=r"((r)[18]), "=r"((r)[19]), \
          "=r"((r)[20]), "=r"((r)[21]), "=r"((r)[22]), "=r"((r)[23]), \
          "=r"((r)[24]), "=r"((r)[25]), "=r"((r)[26]), "=r"((r)[27]), \
          "=r"((r)[28]), "=r"((r)[29]), "=r"((r)[30]), "=r"((r)[31]) \
        : "r"(tmem_addr))

static constexpr uint64_t SMEM_DESC_BASE_SW128 =
    (uint64_t(2) << 61) | (uint64_t(1) << 46) | (uint64_t(64) << 32) | (uint64_t(1) << 16);
#define MAKE_SMEM_DESC(base_addr) \
    (SMEM_DESC_BASE_SW128 | ((uint64_t)((base_addr) >> 4) & 0x3FFF))

// kind::f16, f16 inputs, f32 acc, M=128 (8<<24), N=128 (16<<17)
#define MMA_IDESC_F16 0x8200010u

// SMEM layout (TC): [0] tmem ptr, [8] mbar, [64..576) bias,
// [1024..14848) nbr cache (27*128 ints), A tile @15360 (32KB), W tile @48128 (32KB).
// Both tiles: 2 slices of 16KB (K cols 0..63 / 64..127), SW128 blocked atoms.
// TMEM: 128 cols (D f32) -> up to 4 CTAs worth of TMEM; SMEM limits to 2/SM.
#define NBR_OFF 1024
#define A_OFF 15360u
#define W_OFF 48128u

__global__ void __launch_bounds__(256)
k_main(const float* __restrict__ bias, float* __restrict__ out) {
    extern __shared__ char smem[];
    uint32_t sb = smem_to_u32(smem);
    int tid = threadIdx.x;
    int wid = tid >> 5;
    int o0 = blockIdx.x * 128;

    if (wid == 4) TCGEN05_ALLOC(sb + 0, 128);
    if (tid == 0) MBARRIER_INIT(sb + 8, 1);
    if (tid < 128) ((float*)(smem + 64))[tid] = __ldg(&bias[tid]);
    // nbr cache: [k][r] for this CTA's 128 rows, coalesced
    if (tid < 128) {
        int* nc = (int*)(smem + NBR_OFF);
        #pragma unroll 9
        for (int j = 0; j < KK; ++j) nc[j * 128 + tid] = __ldg(&g_nbr[j * NV + o0 + tid]);
    }
    __syncthreads();
    uint32_t tmem;
    asm volatile("ld.shared.b32 %0, [%1];" : "=r"(tmem) : "r"(sb));
    if (wid == 4) TCGEN05_RELINQUISH_ALLOC_PERMIT();

    int ph = 0;
    for (int k = 0; k < KK; ++k) {
        // ---- issue all global loads first (coalesced; overlap MMA k-1 drain) ----
        uint4 aR[8], wR[8];
        {
            const int* nc = (const int*)(smem + NBR_OFF) + k * 128;
            #pragma unroll
            for (int j = 0; j < 8; ++j) {
                int g = tid + 256 * j;          // linear 16B-chunk id, [0, 2048)
                int row = g >> 4;
                int c = g & 15;
                int nb = nc[row];               // LDS, 2 addrs per warp (broadcast)
                aR[j] = __ldg((const uint4*)(g_f16 + (size_t)nb * CH) + c);
            }
            const uint4* ws = (const uint4*)((const char*)g_w16 + (size_t)k * 32768);
            #pragma unroll
            for (int j = 0; j < 8; ++j) wR[j] = __ldg(ws + tid + 256 * j);
        }
        // ---- wait: MMA k-1 (and all earlier) complete -> tiles reusable ----
        if (k > 0) { MBARRIER_WAIT_PARITY(sb + 8, ph); ph ^= 1; }
        // ---- stores into SW128 tiles ----
        {
            char* As = smem + A_OFF;
            #pragma unroll
            for (int j = 0; j < 8; ++j) {
                int g = tid + 256 * j;
                int row = g >> 4;
                int c = g & 15;
                uint32_t off = ((uint32_t)(c >> 3) << 14)      // 16KB slice
                             + (uint32_t)row * 128u
                             + (uint32_t)((c & 7) << 4);
                off ^= (off >> 3) & 0x70u;                     // SW128 swizzle
                *(uint4*)(As + off) = aR[j];
            }
            uint4* Wd = (uint4*)(smem + W_OFF);                // pre-swizzled image
            #pragma unroll
            for (int j = 0; j < 8; ++j) Wd[tid + 256 * j] = wR[j];
        }
        FENCE_PROXY_ASYNC_SHARED_CTA();
        __syncthreads();
        if (wid == 4) {
            TCGEN05_FENCE_AFTER();
            if (elect_one_pred()) {
                uint64_t ad = MAKE_SMEM_DESC(sb + A_OFF);
                uint64_t bd = MAKE_SMEM_DESC(sb + W_OFF);
                #pragma unroll
                for (int ks = 0; ks < 8; ++ks) {
                    // K-step: 16 fp16 = 32B = 2 desc units; slice 1 at 16KB = 1024 units
                    uint64_t doff = (ks < 4) ? (uint64_t)(2 * ks)
                                             : (uint64_t)(1024 + 2 * (ks - 4));
                    TCGEN05_MMA_F16_SS(tmem, ad + doff, bd + doff, MMA_IDESC_F16,
                                       !(k == 0 && ks == 0));
                }
                TCGEN05_COMMIT(sb + 8);
            }
        }
    }
    // final wait: commit #27 completes parity 0 (26 toggles -> ph == 0)
    MBARRIER_WAIT_PARITY(sb + 8, ph);
    TCGEN05_FENCE_AFTER();

    if (tid < 128) {
        float* orow = out + (size_t)(o0 + tid) * CH;
        const float* bsm = (const float*)(smem + 64);
        #pragma unroll
        for (int b = 0; b < 128; b += 32) {
            uint32_t d[32];
            TCGEN05_LD_32X32B_X32(d, tmem + (uint32_t)b);
            TCGEN05_WAIT_LD();
            #pragma unroll
            for (int c = 0; c < 32; c += 4) {
                float4 v;
                v.x = __uint_as_float(d[c + 0]) + bsm[b + c + 0];
                v.y = __uint_as_float(d[c + 1]) + bsm[b + c + 1];
                v.z = __uint_as_float(d[c + 2]) + bsm[b + c + 2];
                v.w = __uint_as_float(d[c + 3]) + bsm[b + c + 3];
                *(float4*)(orow + b + c) = v;
            }
        }
    }
    __syncthreads();
    if (wid == 4) TCGEN05_DEALLOC(tmem, 128);
}

#else  // ---------------- mma.sync fallback path (single-buffered, fits 66KB) ----
#define A_FB(w)  ((w) * 4096)
#define W_FB     32768
#define BIAS_FB  65536

__device__ __forceinline__ void mma16816(float* c, uint32_t a0, uint32_t a1,
                                         uint32_t a2, uint32_t a3,
                                         uint32_t b0, uint32_t b1) {
    asm volatile(
        "mma.sync.aligned.m16n8k16.row.col.f32.f16.f16.f32 "
        "{%0,%1,%2,%3}, {%4,%5,%6,%7}, {%8,%9}, {%0,%1,%2,%3};"
        : "+f"(c[0]), "+f"(c[1]), "+f"(c[2]), "+f"(c[3])
        : "r"(a0), "r"(a1), "r"(a2), "r"(a3), "r"(b0), "r"(b1));
}

__global__ void __launch_bounds__(256)
k_main(const float* __restrict__ bias, float* __restrict__ out) {
    extern __shared__ char smem[];
    uint32_t sb = smem_to_u32(smem);
    int tid = threadIdx.x;
    int wid = tid >> 5;
    int lane = tid & 31;
    int o0 = blockIdx.x * 128;

    if (tid < 128) ((float*)(smem + BIAS_FB))[tid] = __ldg(&bias[tid]);

    float acc[16][4] = {};
    int m = lane >> 3, rl = lane & 7;
    int lrow = rl + ((m & 1) << 3);

    for (int k = 0; k < KK; ++k) {
        __syncthreads();   // previous iteration's MMA reads done
        {
            int nbl = (lane < 16) ? __ldg(&g_nbr[k * NV + o0 + wid * 16 + lane]) : 0;
            char* ab = smem + A_FB(wid);
            #pragma unroll
            for (int i = 0; i < 8; ++i) {
                int row = i * 2 + (lane >> 4);
                int rn = __shfl_sync(0xffffffffu, nbl, row);
                uint4 v = __ldg((const uint4*)(g_f16 + (size_t)rn * CH) + (lane & 15));
                int c = lane & 15;
                *(uint4*)(ab + row * 256 + ((c ^ (row & 7)) << 4)) = v;
            }
            const uint4* ws = (const uint4*)((const char*)g_w16 + (size_t)k * 32768)
                              + wid * 256 + lane;
            uint4* wd = (uint4*)(smem + W_FB) + wid * 256 + lane;
            #pragma unroll
            for (int i = 0; i < 8; ++i) wd[i * 32] = __ldg(ws + i * 32);
        }
        __syncthreads();
        {
            uint32_t ab32 = sb + A_FB(wid);
            uint32_t wb32 = sb + W_FB;
            uint32_t arow = ab32 + (uint32_t)lrow * 256u;
            #pragma unroll
            for (int kt = 0; kt < 8; ++kt) {
                int chunk = kt * 2 + (m >> 1);
                uint32_t aaddr = arow + (uint32_t)((chunk ^ (lrow & 7)) << 4);
                uint32_t a0, a1, a2, a3;
                asm volatile(
                    "ldmatrix.sync.aligned.m8n8.x4.shared.b16 {%0,%1,%2,%3}, [%4];"
                    : "=r"(a0), "=r"(a1), "=r"(a2), "=r"(a3) : "r"(aaddr));
                #pragma unroll
                for (int nt = 0; nt < 16; ++nt) {
                    uint32_t baddr = wb32 + (uint32_t)((((kt << 4) + nt) << 8) + (lane << 3));
                    uint32_t b0, b1;
                    asm volatile("ld.shared.v2.b32 {%0,%1}, [%2];"
                                 : "=r"(b0), "=r"(b1) : "r"(baddr));
                    mma16816(acc[nt], a0, a1, a2, a3, b0, b1);
                }
            }
        }
    }

    // epilogue
    {
        int gid = lane >> 2, tig = lane & 3;
        const float* bsm = (const float*)(smem + BIAS_FB);
        size_t r0 = (size_t)(o0 + wid * 16 + gid);
        #pragma unroll
        for (int nt = 0; nt < 16; ++nt) {
            int col = nt * 8 + tig * 2;
            float2 bv = *(const float2*)(bsm + col);
            float2 v0 = make_float2(acc[nt][0] + bv.x, acc[nt][1] + bv.y);
            float2 v1 = make_float2(acc[nt][2] + bv.x, acc[nt][3] + bv.y);
            *(float2*)(out + r0 * CH + col) = v0;
            *(float2*)(out + (r0 + 8) * CH + col) = v1;
        }
    }
}
#endif  // TC_PATH

// ---------------- fused prep kernel ----------------
// blocks [0, 6912): rulebook scatter (g_nbr = in_idx+1)
// blocks [6912, 15104): feature fp16 convert, float4-vectorized (+1 row shift)
// blocks [15104, 16832): weight pack (per-path layout)
#define PREP_BLOCKS 16832

__global__ void k_prep(const float* __restrict__ f, const float* __restrict__ w,
                       const int* __restrict__ in_idx, const int* __restrict__ out_idx) {
    int b = blockIdx.x;
    if (b < 6912) {
        int i = b * 256 + threadIdx.x;            // [0, KK*NV)
        int o = out_idx[i];
        if (o < NV) g_nbr[(i / NV) * NV + o] = in_idx[i] + 1;
    } else if (b < 15104) {
        int i = (b - 6912) * 256 + threadIdx.x;   // [0, NV*32) float4 words
        float4 v = ((const float4*)f)[i];
        __half2 h0, h1;
        h0.x = __float2half_rn(v.x); h0.y = __float2half_rn(v.y);
        h1.x = __float2half_rn(v.z); h1.y = __float2half_rn(v.w);
        uint2 pk;
        pk.x = *(uint32_t*)&h0; pk.y = *(uint32_t*)&h1;
        ((uint2*)g_f16)[i + 32] = pk;             // +1 row shift (row 0 stays zero)
    } else {
        int i = (b - 15104) * 256 + threadIdx.x;
#if TC_PATH
        // W[k][cin][cout] -> B[k][cout(row)][cin(col)] fp16, SW128 blocked image
        if (i >= KK * CH * CH) return;
        int k = i >> 14;
        int r = (i >> 7) & 127;   // c_out (N row)
        int c = i & 127;          // c_in  (K col)
        float v = w[(k << 14) + (c << 7) + r];
        uint32_t atom = (uint32_t)(r >> 3) + ((uint32_t)(c >> 6) << 4);
        uint32_t off = atom * 1024u + (uint32_t)(r & 7) * 128u + (uint32_t)(c & 63) * 2u;
        off ^= (off >> 3) & 0x70u;
        g_w16[((uint32_t)k * 32768u + off) >> 1] = __float2half_rn(v);
#else
        // mma.sync B-fragment-ready image: [k][ktile(8)][ntile(16)][lane(32)][reg(2)] u32
        if (i >= KK * 8 * 16 * 32 * 2) return;
        int reg   = i & 1;
        int lane  = (i >> 1) & 31;
        int nt    = (i >> 6) & 15;
        int ktile = (i >> 10) & 7;
        int k     = i >> 13;
        int tig = lane & 3, gid = lane >> 2;
        int n    = nt * 8 + gid;
        int cin0 = ktile * 16 + tig * 2 + reg * 8;
        float w0 = w[(k * CH + cin0) * CH + n];
        float w1 = w[(k * CH + cin0 + 1) * CH + n];
        __half2 h;
        h.x = __float2half_rn(w0);
        h.y = __float2half_rn(w1);
        ((__half2*)g_w16)[i] = h;
#endif
    }
}

// ---------------- launch ----------------
extern "C" void kernel_launch(void* const* d_in, const int* in_sizes, int n_in,
                              void* d_out, int out_size) {
    const float* features = (const float*)d_in[0];
    const float* weight   = (const float*)d_in[1];
    const float* bias     = (const float*)d_in[2];
    const int*   in_idx   = (const int*)d_in[3];
    const int*   out_idx  = (const int*)d_in[4];
    float*       out      = (float*)d_out;

    cudaFuncSetAttribute(k_main, cudaFuncAttributeMaxDynamicSharedMemorySize, SMEM_BYTES);

    k_prep<<<PREP_BLOCKS, 256>>>(features, weight, in_idx, out_idx);
    k_main<<<NV / 128, 256, SMEM_BYTES>>>(bias, out);
}

// round 7
// speedup vs baseline: 4.0586x; 1.2345x over previous
#include <cuda_runtime.h>
#include <cuda_fp16.h>
#include <cstdint>

#define NV 65536
#define KK 27
#define CH 128

// tcgen05 fast path only in the arch-specific sm_103a pass (plain compute_103
// rejects tcgen05 in ptxas).
#if defined(__CUDA_ARCH__) && (defined(__CUDA_ARCH_FEAT_SM103_ALL) || \
    (defined(__CUDA_ARCH_SPECIFIC__) && (__CUDA_ARCH_SPECIFIC__ == 1030)))
#define TC_PATH 1
#else
#define TC_PATH 0
#endif

// ---------------- scratch (static __device__, no allocs) ----------------
// g_nbr holds (input_row + 1); 0 means "no neighbor" -> reads g_f16 row 0,
// which is statically zero and never written (k_prep writes rows 1..NV).
__device__ __align__(256) int    g_nbr[KK * NV];            // 7 MB, zero-init
__device__ __align__(256) __half g_f16[(NV + 1) * CH];      // row 0 = zeros
__device__ __align__(256) __half g_w16[KK * CH * CH];       // 864 KB, per-path layout

// ---------------- common helpers ----------------
__device__ __forceinline__ uint32_t smem_to_u32(const void* smem_ptr) {
    uint32_t addr;
    asm("{ .reg .u64 tmp; cvta.to.shared.u64 tmp, %1; cvt.u32.u64 %0, tmp; }"
        : "=r"(addr) : "l"(smem_ptr));
    return addr;
}

// TC path: hdr + A tile (32KB) + W tile (32KB) = 66560 B -> 3 CTAs/SM.
#define SMEM_BYTES 66560

#if TC_PATH
// ---------------- tcgen05 helpers ----------------
__device__ __forceinline__ uint32_t elect_one_pred() {
    uint32_t pred;
    asm volatile(
        "{\n\t.reg .pred p;\n\t"
        "elect.sync _|p, 0xFFFFFFFF;\n\t"
        "selp.b32 %0, 1, 0, p;\n\t}"
        : "=r"(pred));
    return pred;
}

#define TCGEN05_ALLOC(smem_result_addr, nCols) \
    asm volatile("tcgen05.alloc.cta_group::1.sync.aligned.shared::cta.b32 [%0], %1;" \
                 :: "r"((uint32_t)(smem_result_addr)), "r"((uint32_t)(nCols)) : "memory")
#define TCGEN05_DEALLOC(tmem_addr, nCols) \
    asm volatile("tcgen05.dealloc.cta_group::1.sync.aligned.b32 %0, %1;" \
                 :: "r"(tmem_addr), "r"((uint32_t)(nCols)))
#define TCGEN05_RELINQUISH_ALLOC_PERMIT() \
    asm volatile("tcgen05.relinquish_alloc_permit.cta_group::1.sync.aligned;")
#define TCGEN05_WAIT_LD() asm volatile("tcgen05.wait::ld.sync.aligned;" ::: "memory")
#define TCGEN05_FENCE_AFTER()  asm volatile("tcgen05.fence::after_thread_sync;" ::: "memory")
#define TCGEN05_COMMIT(mbar_smem_addr) \
    asm volatile("tcgen05.commit.cta_group::1.mbarrier::arrive::one.shared::cluster.b64 [%0];" \
                 :: "r"((uint32_t)(mbar_smem_addr)) : "memory")
#define FENCE_PROXY_ASYNC_SHARED_CTA() \
    asm volatile("fence.proxy.async.shared::cta;" ::: "memory")
#define MBARRIER_INIT(mbar_smem_addr, count) \
    asm volatile("mbarrier.init.shared.b64 [%0], %1;" \
                 :: "r"((uint32_t)(mbar_smem_addr)), "r"((uint32_t)(count)) : "memory")
#define MBARRIER_EXPECT_TX(mbar_smem_addr, tx_bytes) \
    asm volatile("mbarrier.arrive.expect_tx.shared.b64 _, [%0], %1;" \
                 :: "r"((uint32_t)(mbar_smem_addr)), "r"((uint32_t)(tx_bytes)) : "memory")
#define CP_BULK_G2S(dst_smem, src_gmem, nbytes, mbar_smem_addr) \
    asm volatile("cp.async.bulk.shared::cluster.global.mbarrier::complete_tx::bytes " \
                 "[%0], [%1], %2, [%3];" \
                 :: "r"((uint32_t)(dst_smem)), "l"(src_gmem), "r"((uint32_t)(nbytes)), \
                    "r"((uint32_t)(mbar_smem_addr)) : "memory")
#define MBARRIER_WAIT_PARITY(mbar_smem_addr, phase_parity) do { \
    uint32_t _mbar = (uint32_t)(mbar_smem_addr); \
    uint32_t _parity = (uint32_t)(phase_parity); \
    uint32_t _done; \
    asm volatile( \
        "{\n\t.reg .pred p;\n\t" \
        "mbarrier.try_wait.parity.acquire.cta.shared::cta.b64 p, [%1], %2;\n\t" \
        "selp.b32 %0, 1, 0, p;\n\t}" \
        : "=r"(_done) : "r"(_mbar), "r"(_parity) : "memory"); \
    if (!_done) { \
        asm volatile( \
            "{\n\t.reg .pred P1;\n\t" \
            "WAIT_LOOP_%=:\n\t" \
            "mbarrier.try_wait.parity.acquire.cta.shared::cta.b64 P1, [%0], %1, 0x989680;\n\t" \
            "@P1 bra.uni WAIT_DONE_%=;\n\t" \
            "bra.uni WAIT_LOOP_%=;\n\t" \
            "WAIT_DONE_%=:\n\t}" \
            :: "r"(_mbar), "r"(_parity) : "memory"); \
    } \
} while(0)

// SS-mode f16 MMA: both A and B as SMEM descriptors.
#define TCGEN05_MMA_F16_SS(d_tmem, a_desc, b_desc, idesc, enable_d) do { \
    uint32_t _enable = (enable_d) ? 1 : 0; \
    uint32_t _zero = 0; \
    asm volatile( \
        "{\n\t.reg .pred p;\n\t" \
        "setp.ne.u32 p, %6, 0;\n\t" \
        "tcgen05.mma.cta_group::1.kind::f16 [%0], %1, %2, %3, " \
        "{%4, %4, %4, %4}, p;\n\t}" \
        :: "r"(d_tmem), "l"(a_desc), "l"(b_desc), "r"(idesc), \
           "r"(_zero), "r"(_zero), "r"(_enable) \
        : "memory"); \
} while(0)

#define TCGEN05_LD_32X32B_X32(r, tmem_addr) \
    asm volatile( \
        "tcgen05.ld.sync.aligned.32x32b.x32.b32 " \
        "{%0, %1, %2, %3, %4, %5, %6, %7, " \
        " %8, %9, %10, %11, %12, %13, %14, %15, " \
        " %16, %17, %18, %19, %20, %21, %22, %23, " \
        " %24, %25, %26, %27, %28, %29, %30, %31}, [%32];" \
        : "=r"((r)[0]),  "=r"((r)[1]),  "=r"((r)[2]),  "=r"((r)[3]), \
          "=r"((r)[4]),  "=r"((r)[5]),  "=r"((r)[6]),  "=r"((r)[7]), \
          "=r"((r)[8]),  "=r"((r)[9]),  "=r"((r)[10]), "=r"((r)[11]), \
          "=r"((r)[12]), "=r"((r)[13]), "=r"((r)[14]), "=r"((r)[15]), \
          "=r"((r)[16]), "=r"((r)[17]), "=r"((r)[18]), "=r"((r)[19]), \
          "=r"((r)[20]), "=r"((r)[21]), "=r"((r)[22]), "=r"((r)[23]), \
          "=r"((r)[24]), "=r"((r)[25]), "=r"((r)[26]), "=r"((r)[27]), \
          "=r"((r)[28]), "=r"((r)[29]), "=r"((r)[30]), "=r"((r)[31]) \
        : "r"(tmem_addr))

static constexpr uint64_t SMEM_DESC_BASE_SW128 =
    (uint64_t(2) << 61) | (uint64_t(1) << 46) | (uint64_t(64) << 32) | (uint64_t(1) << 16);
#define MAKE_SMEM_DESC(base_addr) \
    (SMEM_DESC_BASE_SW128 | ((uint64_t)((base_addr) >> 4) & 0x3FFF))

// kind::f16, f16 inputs, f32 acc, M=128 (8<<24), N=128 (16<<17)
#define MMA_IDESC_F16 0x8200010u

// SMEM layout (TC): [0] tmem ptr, [8] mma mbar, [16] W mbar, [64..576) bias,
// A tile @1024 (32KB), W tile @33792 (32KB). Total 66560 -> 3 CTAs/SM.
// Tiles: 2 slices of 16KB (K cols 0..63 / 64..127), SW128 blocked atoms.
#define A_OFF 1024u
#define W_OFF 33792u

__global__ void __launch_bounds__(256)
k_main(const float* __restrict__ bias, float* __restrict__ out) {
    extern __shared__ char smem[];
    uint32_t sb = smem_to_u32(smem);
    int tid = threadIdx.x;
    int wid = tid >> 5;
    int o0 = blockIdx.x * 128;

    if (wid == 4) TCGEN05_ALLOC(sb + 0, 128);
    if (tid == 0) { MBARRIER_INIT(sb + 8, 1); MBARRIER_INIT(sb + 16, 1); }
    if (tid < 128) ((float*)(smem + 64))[tid] = __ldg(&bias[tid]);
    __syncthreads();
    uint32_t tmem;
    asm volatile("ld.shared.b32 %0, [%1];" : "=r"(tmem) : "r"(sb));
    if (wid == 4) TCGEN05_RELINQUISH_ALLOC_PERMIT();

    int ph = 0;   // mma mbar parity (all threads)
    int pw = 0;   // W mbar parity (leader)
    for (int k = 0; k < KK; ++k) {
        // ---- issue A gather loads (coalesced, overlap MMA k-1 drain) ----
        uint4 aR[8];
        {
            const int* nbk = g_nbr + k * NV + o0;
            #pragma unroll
            for (int j = 0; j < 8; ++j) {
                int g = tid + 256 * j;          // linear 16B-chunk id, [0, 2048)
                int row = g >> 4;
                int c = g & 15;
                int nb = __ldg(nbk + row);      // L2-resident, 2 addrs/warp
                aR[j] = __ldg((const uint4*)(g_f16 + (size_t)nb * CH) + c);
            }
        }
        // ---- wait: MMA k-1 complete -> both tiles reusable ----
        if (k > 0) { MBARRIER_WAIT_PARITY(sb + 8, ph); ph ^= 1; }
        // ---- W tile: one bulk async copy (bypasses L1/registers) ----
        if (tid == 0) {
            MBARRIER_EXPECT_TX(sb + 16, 32768);
            CP_BULK_G2S(sb + W_OFF, (const char*)g_w16 + (size_t)k * 32768, 32768, sb + 16);
        }
        // ---- A stores into SW128 tile ----
        {
            char* As = smem + A_OFF;
            #pragma unroll
            for (int j = 0; j < 8; ++j) {
                int g = tid + 256 * j;
                int row = g >> 4;
                int c = g & 15;
                uint32_t off = ((uint32_t)(c >> 3) << 14)      // 16KB slice
                             + (uint32_t)row * 128u
                             + (uint32_t)((c & 7) << 4);
                off ^= (off >> 3) & 0x70u;                     // SW128 swizzle
                *(uint4*)(As + off) = aR[j];
            }
        }
        FENCE_PROXY_ASYNC_SHARED_CTA();
        __syncthreads();
        if (wid == 4) {
            TCGEN05_FENCE_AFTER();
            if (elect_one_pred()) {
                MBARRIER_WAIT_PARITY(sb + 16, pw);             // W bulk done
                uint64_t ad = MAKE_SMEM_DESC(sb + A_OFF);
                uint64_t bd = MAKE_SMEM_DESC(sb + W_OFF);
                #pragma unroll
                for (int ks = 0; ks < 8; ++ks) {
                    // K-step: 16 fp16 = 32B = 2 desc units; slice 1 at 16KB = 1024 units
                    uint64_t doff = (ks < 4) ? (uint64_t)(2 * ks)
                                             : (uint64_t)(1024 + 2 * (ks - 4));
                    TCGEN05_MMA_F16_SS(tmem, ad + doff, bd + doff, MMA_IDESC_F16,
                                       !(k == 0 && ks == 0));
                }
                TCGEN05_COMMIT(sb + 8);
            }
        }
        pw ^= 1;
    }
    // final wait: last commit flips parity ph
    MBARRIER_WAIT_PARITY(sb + 8, ph);
    TCGEN05_FENCE_AFTER();

    if (tid < 128) {
        float* orow = out + (size_t)(o0 + tid) * CH;
        const float* bsm = (const float*)(smem + 64);
        #pragma unroll
        for (int b = 0; b < 128; b += 32) {
            uint32_t d[32];
            TCGEN05_LD_32X32B_X32(d, tmem + (uint32_t)b);
            TCGEN05_WAIT_LD();
            #pragma unroll
            for (int c = 0; c < 32; c += 4) {
                float4 v;
                v.x = __uint_as_float(d[c + 0]) + bsm[b + c + 0];
                v.y = __uint_as_float(d[c + 1]) + bsm[b + c + 1];
                v.z = __uint_as_float(d[c + 2]) + bsm[b + c + 2];
                v.w = __uint_as_float(d[c + 3]) + bsm[b + c + 3];
                *(float4*)(orow + b + c) = v;
            }
        }
    }
    __syncthreads();
    if (wid == 4) TCGEN05_DEALLOC(tmem, 128);
}

#else  // ---------------- mma.sync fallback path (single-buffered, fits 65KB) ----
#define A_FB(w)  ((w) * 4096)
#define W_FB     32768
#define BIAS_FB  65536

__device__ __forceinline__ void mma16816(float* c, uint32_t a0, uint32_t a1,
                                         uint32_t a2, uint32_t a3,
                                         uint32_t b0, uint32_t b1) {
    asm volatile(
        "mma.sync.aligned.m16n8k16.row.col.f32.f16.f16.f32 "
        "{%0,%1,%2,%3}, {%4,%5,%6,%7}, {%8,%9}, {%0,%1,%2,%3};"
        : "+f"(c[0]), "+f"(c[1]), "+f"(c[2]), "+f"(c[3])
        : "r"(a0), "r"(a1), "r"(a2), "r"(a3), "r"(b0), "r"(b1));
}

__global__ void __launch_bounds__(256)
k_main(const float* __restrict__ bias, float* __restrict__ out) {
    extern __shared__ char smem[];
    uint32_t sb = smem_to_u32(smem);
    int tid = threadIdx.x;
    int wid = tid >> 5;
    int lane = tid & 31;
    int o0 = blockIdx.x * 128;

    if (tid < 128) ((float*)(smem + BIAS_FB))[tid] = __ldg(&bias[tid]);

    float acc[16][4] = {};
    int m = lane >> 3, rl = lane & 7;
    int lrow = rl + ((m & 1) << 3);

    for (int k = 0; k < KK; ++k) {
        __syncthreads();   // previous iteration's MMA reads done
        {
            int nbl = (lane < 16) ? __ldg(&g_nbr[k * NV + o0 + wid * 16 + lane]) : 0;
            char* ab = smem + A_FB(wid);
            #pragma unroll
            for (int i = 0; i < 8; ++i) {
                int row = i * 2 + (lane >> 4);
                int rn = __shfl_sync(0xffffffffu, nbl, row);
                uint4 v = __ldg((const uint4*)(g_f16 + (size_t)rn * CH) + (lane & 15));
                int c = lane & 15;
                *(uint4*)(ab + row * 256 + ((c ^ (row & 7)) << 4)) = v;
            }
            const uint4* ws = (const uint4*)((const char*)g_w16 + (size_t)k * 32768)
                              + wid * 256 + lane;
            uint4* wd = (uint4*)(smem + W_FB) + wid * 256 + lane;
            #pragma unroll
            for (int i = 0; i < 8; ++i) wd[i * 32] = __ldg(ws + i * 32);
        }
        __syncthreads();
        {
            uint32_t ab32 = sb + A_FB(wid);
            uint32_t wb32 = sb + W_FB;
            uint32_t arow = ab32 + (uint32_t)lrow * 256u;
            #pragma unroll
            for (int kt = 0; kt < 8; ++kt) {
                int chunk = kt * 2 + (m >> 1);
                uint32_t aaddr = arow + (uint32_t)((chunk ^ (lrow & 7)) << 4);
                uint32_t a0, a1, a2, a3;
                asm volatile(
                    "ldmatrix.sync.aligned.m8n8.x4.shared.b16 {%0,%1,%2,%3}, [%4];"
                    : "=r"(a0), "=r"(a1), "=r"(a2), "=r"(a3) : "r"(aaddr));
                #pragma unroll
                for (int nt = 0; nt < 16; ++nt) {
                    uint32_t baddr = wb32 + (uint32_t)((((kt << 4) + nt) << 8) + (lane << 3));
                    uint32_t b0, b1;
                    asm volatile("ld.shared.v2.b32 {%0,%1}, [%2];"
                                 : "=r"(b0), "=r"(b1) : "r"(baddr));
                    mma16816(acc[nt], a0, a1, a2, a3, b0, b1);
                }
            }
        }
    }

    // epilogue
    {
        int gid = lane >> 2, tig = lane & 3;
        const float* bsm = (const float*)(smem + BIAS_FB);
        size_t r0 = (size_t)(o0 + wid * 16 + gid);
        #pragma unroll
        for (int nt = 0; nt < 16; ++nt) {
            int col = nt * 8 + tig * 2;
            float2 bv = *(const float2*)(bsm + col);
            float2 v0 = make_float2(acc[nt][0] + bv.x, acc[nt][1] + bv.y);
            float2 v1 = make_float2(acc[nt][2] + bv.x, acc[nt][3] + bv.y);
            *(float2*)(out + r0 * CH + col) = v0;
            *(float2*)(out + (r0 + 8) * CH + col) = v1;
        }
    }
}
#endif  // TC_PATH

// ---------------- fused prep kernel ----------------
// blocks [0, 6912): rulebook scatter (g_nbr = in_idx+1)
// blocks [6912, 15104): feature fp16 convert, float4-vectorized (+1 row shift)
// blocks [15104, 16832): weight pack (per-path layout)
#define PREP_BLOCKS 16832

__global__ void k_prep(const float* __restrict__ f, const float* __restrict__ w,
                       const int* __restrict__ in_idx, const int* __restrict__ out_idx) {
    int b = blockIdx.x;
    if (b < 6912) {
        int i = b * 256 + threadIdx.x;            // [0, KK*NV)
        int o = out_idx[i];
        if (o < NV) g_nbr[(i / NV) * NV + o] = in_idx[i] + 1;
    } else if (b < 15104) {
        int i = (b - 6912) * 256 + threadIdx.x;   // [0, NV*32) float4 words
        float4 v = ((const float4*)f)[i];
        __half2 h0, h1;
        h0.x = __float2half_rn(v.x); h0.y = __float2half_rn(v.y);
        h1.x = __float2half_rn(v.z); h1.y = __float2half_rn(v.w);
        uint2 pk;
        pk.x = *(uint32_t*)&h0; pk.y = *(uint32_t*)&h1;
        ((uint2*)g_f16)[i + 32] = pk;             // +1 row shift (row 0 stays zero)
    } else {
        int i = (b - 15104) * 256 + threadIdx.x;
#if TC_PATH
        // W[k][cin][cout] -> B[k][cout(row)][cin(col)] fp16, SW128 blocked image
        if (i >= KK * CH * CH) return;
        int k = i >> 14;
        int r = (i >> 7) & 127;   // c_out (N row)
        int c = i & 127;          // c_in  (K col)
        float v = w[(k << 14) + (c << 7) + r];
        uint32_t atom = (uint32_t)(r >> 3) + ((uint32_t)(c >> 6) << 4);
        uint32_t off = atom * 1024u + (uint32_t)(r & 7) * 128u + (uint32_t)(c & 63) * 2u;
        off ^= (off >> 3) & 0x70u;
        g_w16[((uint32_t)k * 32768u + off) >> 1] = __float2half_rn(v);
#else
        // mma.sync B-fragment-ready image: [k][ktile(8)][ntile(16)][lane(32)][reg(2)] u32
        if (i >= KK * 8 * 16 * 32 * 2) return;
        int reg   = i & 1;
        int lane  = (i >> 1) & 31;
        int nt    = (i >> 6) & 15;
        int ktile = (i >> 10) & 7;
        int k     = i >> 13;
        int tig = lane & 3, gid = lane >> 2;
        int n    = nt * 8 + gid;
        int cin0 = ktile * 16 + tig * 2 + reg * 8;
        float w0 = w[(k * CH + cin0) * CH + n];
        float w1 = w[(k * CH + cin0 + 1) * CH + n];
        __half2 h;
        h.x = __float2half_rn(w0);
        h.y = __float2half_rn(w1);
        ((__half2*)g_w16)[i] = h;
#endif
    }
}

// ---------------- launch ----------------
extern "C" void kernel_launch(void* const* d_in, const int* in_sizes, int n_in,
                              void* d_out, int out_size) {
    const float* features = (const float*)d_in[0];
    const float* weight   = (const float*)d_in[1];
    const float* bias     = (const float*)d_in[2];
    const int*   in_idx   = (const int*)d_in[3];
    const int*   out_idx  = (const int*)d_in[4];
    float*       out      = (float*)d_out;

    cudaFuncSetAttribute(k_main, cudaFuncAttributeMaxDynamicSharedMemorySize, SMEM_BYTES);

    k_prep<<<PREP_BLOCKS, 256>>>(features, weight, in_idx, out_idx);
    k_main<<<NV / 128, 256, SMEM_BYTES>>>(bias, out);
}

// round 8
// speedup vs baseline: 4.1278x; 1.0171x over previous
#include <cuda_runtime.h>
#include <cuda_fp16.h>
#include <cstdint>

#define NV 65536
#define KK 27
#define CH 128

// tcgen05 fast path only in the arch-specific sm_103a pass (plain compute_103
// rejects tcgen05 in ptxas).
#if defined(__CUDA_ARCH__) && (defined(__CUDA_ARCH_FEAT_SM103_ALL) || \
    (defined(__CUDA_ARCH_SPECIFIC__) && (__CUDA_ARCH_SPECIFIC__ == 1030)))
#define TC_PATH 1
#else
#define TC_PATH 0
#endif

// ---------------- scratch (static __device__, no allocs) ----------------
// g_nbr holds (input_row + 1); 0 means "no neighbor" -> reads g_f16 row 0,
// which is statically zero and never written (k_prep writes rows 1..NV).
__device__ __align__(256) int    g_nbr[KK * NV];            // 7 MB, zero-init
__device__ __align__(256) __half g_f16[(NV + 1) * CH];      // row 0 = zeros
__device__ __align__(256) __half g_w16[KK * CH * CH];       // 864 KB, per-path layout

// ---------------- common helpers ----------------
__device__ __forceinline__ uint32_t smem_to_u32(const void* smem_ptr) {
    uint32_t addr;
    asm("{ .reg .u64 tmp; cvta.to.shared.u64 tmp, %1; cvt.u32.u64 %0, tmp; }"
        : "=r"(addr) : "l"(smem_ptr));
    return addr;
}

// TC path: hdr + A tile (32KB) + W tiles (2x32KB) = 99328 B -> 2 CTAs/SM.
#define SMEM_BYTES 99328

#if TC_PATH
// ---------------- tcgen05 helpers ----------------
__device__ __forceinline__ uint32_t elect_one_pred() {
    uint32_t pred;
    asm volatile(
        "{\n\t.reg .pred p;\n\t"
        "elect.sync _|p, 0xFFFFFFFF;\n\t"
        "selp.b32 %0, 1, 0, p;\n\t}"
        : "=r"(pred));
    return pred;
}

#define TCGEN05_ALLOC(smem_result_addr, nCols) \
    asm volatile("tcgen05.alloc.cta_group::1.sync.aligned.shared::cta.b32 [%0], %1;" \
                 :: "r"((uint32_t)(smem_result_addr)), "r"((uint32_t)(nCols)) : "memory")
#define TCGEN05_DEALLOC(tmem_addr, nCols) \
    asm volatile("tcgen05.dealloc.cta_group::1.sync.aligned.b32 %0, %1;" \
                 :: "r"(tmem_addr), "r"((uint32_t)(nCols)))
#define TCGEN05_RELINQUISH_ALLOC_PERMIT() \
    asm volatile("tcgen05.relinquish_alloc_permit.cta_group::1.sync.aligned;")
#define TCGEN05_WAIT_LD() asm volatile("tcgen05.wait::ld.sync.aligned;" ::: "memory")
#define TCGEN05_FENCE_AFTER()  asm volatile("tcgen05.fence::after_thread_sync;" ::: "memory")
#define TCGEN05_COMMIT(mbar_smem_addr) \
    asm volatile("tcgen05.commit.cta_group::1.mbarrier::arrive::one.shared::cluster.b64 [%0];" \
                 :: "r"((uint32_t)(mbar_smem_addr)) : "memory")
#define FENCE_PROXY_ASYNC_SHARED_CTA() \
    asm volatile("fence.proxy.async.shared::cta;" ::: "memory")
#define MBARRIER_INIT(mbar_smem_addr, count) \
    asm volatile("mbarrier.init.shared.b64 [%0], %1;" \
                 :: "r"((uint32_t)(mbar_smem_addr)), "r"((uint32_t)(count)) : "memory")
#define MBARRIER_EXPECT_TX(mbar_smem_addr, tx_bytes) \
    asm volatile("mbarrier.arrive.expect_tx.shared.b64 _, [%0], %1;" \
                 :: "r"((uint32_t)(mbar_smem_addr)), "r"((uint32_t)(tx_bytes)) : "memory")
#define CP_BULK_G2S(dst_smem, src_gmem, nbytes, mbar_smem_addr) \
    asm volatile("cp.async.bulk.shared::cluster.global.mbarrier::complete_tx::bytes " \
                 "[%0], [%1], %2, [%3];" \
                 :: "r"((uint32_t)(dst_smem)), "l"(src_gmem), "r"((uint32_t)(nbytes)), \
                    "r"((uint32_t)(mbar_smem_addr)) : "memory")
#define MBARRIER_WAIT_PARITY(mbar_smem_addr, phase_parity) do { \
    uint32_t _mbar = (uint32_t)(mbar_smem_addr); \
    uint32_t _parity = (uint32_t)(phase_parity); \
    uint32_t _done; \
    asm volatile( \
        "{\n\t.reg .pred p;\n\t" \
        "mbarrier.try_wait.parity.acquire.cta.shared::cta.b64 p, [%1], %2;\n\t" \
        "selp.b32 %0, 1, 0, p;\n\t}" \
        : "=r"(_done) : "r"(_mbar), "r"(_parity) : "memory"); \
    if (!_done) { \
        asm volatile( \
            "{\n\t.reg .pred P1;\n\t" \
            "WAIT_LOOP_%=:\n\t" \
            "mbarrier.try_wait.parity.acquire.cta.shared::cta.b64 P1, [%0], %1, 0x989680;\n\t" \
            "@P1 bra.uni WAIT_DONE_%=;\n\t" \
            "bra.uni WAIT_LOOP_%=;\n\t" \
            "WAIT_DONE_%=:\n\t}" \
            :: "r"(_mbar), "r"(_parity) : "memory"); \
    } \
} while(0)

// SS-mode f16 MMA: both A and B as SMEM descriptors.
#define TCGEN05_MMA_F16_SS(d_tmem, a_desc, b_desc, idesc, enable_d) do { \
    uint32_t _enable = (enable_d) ? 1 : 0; \
    uint32_t _zero = 0; \
    asm volatile( \
        "{\n\t.reg .pred p;\n\t" \
        "setp.ne.u32 p, %6, 0;\n\t" \
        "tcgen05.mma.cta_group::1.kind::f16 [%0], %1, %2, %3, " \
        "{%4, %4, %4, %4}, p;\n\t}" \
        :: "r"(d_tmem), "l"(a_desc), "l"(b_desc), "r"(idesc), \
           "r"(_zero), "r"(_zero), "r"(_enable) \
        : "memory"); \
} while(0)

#define TCGEN05_LD_32X32B_X32(r, tmem_addr) \
    asm volatile( \
        "tcgen05.ld.sync.aligned.32x32b.x32.b32 " \
        "{%0, %1, %2, %3, %4, %5, %6, %7, " \
        " %8, %9, %10, %11, %12, %13, %14, %15, " \
        " %16, %17, %18, %19, %20, %21, %22, %23, " \
        " %24, %25, %26, %27, %28, %29, %30, %31}, [%32];" \
        : "=r"((r)[0]),  "=r"((r)[1]),  "=r"((r)[2]),  "=r"((r)[3]), \
          "=r"((r)[4]),  "=r"((r)[5]),  "=r"((r)[6]),  "=r"((r)[7]), \
          "=r"((r)[8]),  "=r"((r)[9]),  "=r"((r)[10]), "=r"((r)[11]), \
          "=r"((r)[12]), "=r"((r)[13]), "=r"((r)[14]), "=r"((r)[15]), \
          "=r"((r)[16]), "=r"((r)[17]), "=r"((r)[18]), "=r"((r)[19]), \
          "=r"((r)[20]), "=r"((r)[21]), "=r"((r)[22]), "=r"((r)[23]), \
          "=r"((r)[24]), "=r"((r)[25]), "=r"((r)[26]), "=r"((r)[27]), \
          "=r"((r)[28]), "=r"((r)[29]), "=r"((r)[30]), "=r"((r)[31]) \
        : "r"(tmem_addr))

static constexpr uint64_t SMEM_DESC_BASE_SW128 =
    (uint64_t(2) << 61) | (uint64_t(1) << 46) | (uint64_t(64) << 32) | (uint64_t(1) << 16);
#define MAKE_SMEM_DESC(base_addr) \
    (SMEM_DESC_BASE_SW128 | ((uint64_t)((base_addr) >> 4) & 0x3FFF))

// kind::f16, f16 inputs, f32 acc, M=128 (8<<24), N=128 (16<<17)
#define MMA_IDESC_F16 0x8200010u

// SMEM layout (TC): [0] tmem ptr, [8] mma mbar, [16],[24] W mbars,
// [64..576) bias, A tile @1024 (32KB), W stages @33792 (2 x 32KB).
// Total 99328 -> 2 CTAs/SM. Tiles: 2 slices of 16KB, SW128 blocked atoms.
#define A_OFF 1024u
#define W_OFF(s) (33792u + (uint32_t)(s) * 32768u)

__global__ void __launch_bounds__(256)
k_main(const float* __restrict__ bias, float* __restrict__ out) {
    extern __shared__ char smem[];
    uint32_t sb = smem_to_u32(smem);
    int tid = threadIdx.x;
    int wid = tid >> 5;
    int o0 = blockIdx.x * 128;

    if (wid == 4) TCGEN05_ALLOC(sb + 0, 128);
    if (tid == 0) {
        MBARRIER_INIT(sb + 8, 1);
        MBARRIER_INIT(sb + 16, 1);
        MBARRIER_INIT(sb + 24, 1);
    }
    if (tid < 128) ((float*)(smem + 64))[tid] = __ldg(&bias[tid]);
    __syncthreads();
    // prologue: W(0) into stage 0 (transfers while we set up / gather k=0)
    if (tid == 0) {
        MBARRIER_EXPECT_TX(sb + 16, 32768);
        CP_BULK_G2S(sb + W_OFF(0), (const char*)g_w16, 32768, sb + 16);
    }
    uint32_t tmem;
    asm volatile("ld.shared.b32 %0, [%1];" : "=r"(tmem) : "r"(sb));
    if (wid == 4) TCGEN05_RELINQUISH_ALLOC_PERMIT();

    // loop-invariant A-gather addressing: chunk c = tid&15, rows tid>>4 + 16j
    const int c = tid & 15;
    const uint4* fbase = (const uint4*)g_f16 + c;
    uint32_t aoff[8];
    #pragma unroll
    for (int j = 0; j < 8; ++j) {
        uint32_t row = (uint32_t)(tid >> 4) + 16u * j;
        uint32_t off = ((uint32_t)(c >> 3) << 14)       // 16KB K-slice
                     + row * 128u
                     + (uint32_t)((c & 7) << 4);
        off ^= (off >> 3) & 0x70u;                      // SW128 swizzle
        aoff[j] = A_OFF + off;
    }

    int ph = 0;   // mma mbar parity
    for (int k = 0; k < KK; ++k) {
        // ---- issue A gather loads (coalesced; overlap MMA k-1 drain) ----
        uint4 aR[8];
        {
            const int* nbk = g_nbr + k * NV + o0 + (tid >> 4);
            #pragma unroll
            for (int j = 0; j < 8; ++j) {
                int nb = __ldg(nbk + 16 * j);
                aR[j] = __ldg(fbase + (size_t)nb * 16);
            }
        }
        // ---- wait: MMA k-1 complete -> A tile + W stage (k+1)&1 reusable ----
        if (k > 0) { MBARRIER_WAIT_PARITY(sb + 8, ph); ph ^= 1; }
        // ---- prefetch W(k+1) into the stage MMA k-1 just finished reading ----
        if (tid == 0 && k + 1 < KK) {
            uint32_t s1 = (uint32_t)(k + 1) & 1u;
            MBARRIER_EXPECT_TX(sb + 16 + 8 * s1, 32768);
            CP_BULK_G2S(sb + W_OFF(s1), (const char*)g_w16 + (size_t)(k + 1) * 32768,
                        32768, sb + 16 + 8 * s1);
        }
        // ---- A stores into SW128 tile (precomputed addresses) ----
        {
            #pragma unroll
            for (int j = 0; j < 8; ++j) *(uint4*)(smem + aoff[j]) = aR[j];
        }
        FENCE_PROXY_ASYNC_SHARED_CTA();
        __syncthreads();
        if (wid == 4) {
            TCGEN05_FENCE_AFTER();
            if (elect_one_pred()) {
                // W(k) was issued one iteration ago -> latency hidden
                MBARRIER_WAIT_PARITY(sb + 16 + 8 * ((uint32_t)k & 1u), (k >> 1) & 1);
                uint64_t ad = MAKE_SMEM_DESC(sb + A_OFF);
                uint64_t bd = MAKE_SMEM_DESC(sb + W_OFF((uint32_t)k & 1u));
                #pragma unroll
                for (int ks = 0; ks < 8; ++ks) {
                    // K-step: 16 fp16 = 32B = 2 desc units; slice 1 at 16KB = 1024 units
                    uint64_t doff = (ks < 4) ? (uint64_t)(2 * ks)
                                             : (uint64_t)(1024 + 2 * (ks - 4));
                    TCGEN05_MMA_F16_SS(tmem, ad + doff, bd + doff, MMA_IDESC_F16,
                                       !(k == 0 && ks == 0));
                }
                TCGEN05_COMMIT(sb + 8);
            }
        }
    }
    // final wait: last commit flips parity ph
    MBARRIER_WAIT_PARITY(sb + 8, ph);
    TCGEN05_FENCE_AFTER();

    if (tid < 128) {
        float* orow = out + (size_t)(o0 + tid) * CH;
        const float* bsm = (const float*)(smem + 64);
        #pragma unroll
        for (int b = 0; b < 128; b += 32) {
            uint32_t d[32];
            TCGEN05_LD_32X32B_X32(d, tmem + (uint32_t)b);
            TCGEN05_WAIT_LD();
            #pragma unroll
            for (int cc = 0; cc < 32; cc += 4) {
                float4 v;
                v.x = __uint_as_float(d[cc + 0]) + bsm[b + cc + 0];
                v.y = __uint_as_float(d[cc + 1]) + bsm[b + cc + 1];
                v.z = __uint_as_float(d[cc + 2]) + bsm[b + cc + 2];
                v.w = __uint_as_float(d[cc + 3]) + bsm[b + cc + 3];
                *(float4*)(orow + b + cc) = v;
            }
        }
    }
    __syncthreads();
    if (wid == 4) TCGEN05_DEALLOC(tmem, 128);
}

#else  // ---------------- mma.sync fallback path (single-buffered) ----------------
#define A_FB(w)  ((w) * 4096)
#define W_FB     32768
#define BIAS_FB  65536

__device__ __forceinline__ void mma16816(float* c, uint32_t a0, uint32_t a1,
                                         uint32_t a2, uint32_t a3,
                                         uint32_t b0, uint32_t b1) {
    asm volatile(
        "mma.sync.aligned.m16n8k16.row.col.f32.f16.f16.f32 "
        "{%0,%1,%2,%3}, {%4,%5,%6,%7}, {%8,%9}, {%0,%1,%2,%3};"
        : "+f"(c[0]), "+f"(c[1]), "+f"(c[2]), "+f"(c[3])
        : "r"(a0), "r"(a1), "r"(a2), "r"(a3), "r"(b0), "r"(b1));
}

__global__ void __launch_bounds__(256)
k_main(const float* __restrict__ bias, float* __restrict__ out) {
    extern __shared__ char smem[];
    uint32_t sb = smem_to_u32(smem);
    int tid = threadIdx.x;
    int wid = tid >> 5;
    int lane = tid & 31;
    int o0 = blockIdx.x * 128;

    if (tid < 128) ((float*)(smem + BIAS_FB))[tid] = __ldg(&bias[tid]);

    float acc[16][4] = {};
    int m = lane >> 3, rl = lane & 7;
    int lrow = rl + ((m & 1) << 3);

    for (int k = 0; k < KK; ++k) {
        __syncthreads();   // previous iteration's MMA reads done
        {
            int nbl = (lane < 16) ? __ldg(&g_nbr[k * NV + o0 + wid * 16 + lane]) : 0;
            char* ab = smem + A_FB(wid);
            #pragma unroll
            for (int i = 0; i < 8; ++i) {
                int row = i * 2 + (lane >> 4);
                int rn = __shfl_sync(0xffffffffu, nbl, row);
                uint4 v = __ldg((const uint4*)(g_f16 + (size_t)rn * CH) + (lane & 15));
                int c = lane & 15;
                *(uint4*)(ab + row * 256 + ((c ^ (row & 7)) << 4)) = v;
            }
            const uint4* ws = (const uint4*)((const char*)g_w16 + (size_t)k * 32768)
                              + wid * 256 + lane;
            uint4* wd = (uint4*)(smem + W_FB) + wid * 256 + lane;
            #pragma unroll
            for (int i = 0; i < 8; ++i) wd[i * 32] = __ldg(ws + i * 32);
        }
        __syncthreads();
        {
            uint32_t ab32 = sb + A_FB(wid);
            uint32_t wb32 = sb + W_FB;
            uint32_t arow = ab32 + (uint32_t)lrow * 256u;
            #pragma unroll
            for (int kt = 0; kt < 8; ++kt) {
                int chunk = kt * 2 + (m >> 1);
                uint32_t aaddr = arow + (uint32_t)((chunk ^ (lrow & 7)) << 4);
                uint32_t a0, a1, a2, a3;
                asm volatile(
                    "ldmatrix.sync.aligned.m8n8.x4.shared.b16 {%0,%1,%2,%3}, [%4];"
                    : "=r"(a0), "=r"(a1), "=r"(a2), "=r"(a3) : "r"(aaddr));
                #pragma unroll
                for (int nt = 0; nt < 16; ++nt) {
                    uint32_t baddr = wb32 + (uint32_t)((((kt << 4) + nt) << 8) + (lane << 3));
                    uint32_t b0, b1;
                    asm volatile("ld.shared.v2.b32 {%0,%1}, [%2];"
                                 : "=r"(b0), "=r"(b1) : "r"(baddr));
                    mma16816(acc[nt], a0, a1, a2, a3, b0, b1);
                }
            }
        }
    }

    // epilogue
    {
        int gid = lane >> 2, tig = lane & 3;
        const float* bsm = (const float*)(smem + BIAS_FB);
        size_t r0 = (size_t)(o0 + wid * 16 + gid);
        #pragma unroll
        for (int nt = 0; nt < 16; ++nt) {
            int col = nt * 8 + tig * 2;
            float2 bv = *(const float2*)(bsm + col);
            float2 v0 = make_float2(acc[nt][0] + bv.x, acc[nt][1] + bv.y);
            float2 v1 = make_float2(acc[nt][2] + bv.x, acc[nt][3] + bv.y);
            *(float2*)(out + r0 * CH + col) = v0;
            *(float2*)(out + (r0 + 8) * CH + col) = v1;
        }
    }
}
#endif  // TC_PATH

// ---------------- fused prep kernel ----------------
// blocks [0, 6912): rulebook scatter (g_nbr = in_idx+1)
// blocks [6912, 15104): feature fp16 convert, float4-vectorized (+1 row shift)
// blocks [15104, 16832): weight pack (per-path layout)
#define PREP_BLOCKS 16832

__global__ void k_prep(const float* __restrict__ f, const float* __restrict__ w,
                       const int* __restrict__ in_idx, const int* __restrict__ out_idx) {
    int b = blockIdx.x;
    if (b < 6912) {
        int i = b * 256 + threadIdx.x;            // [0, KK*NV)
        int o = out_idx[i];
        if (o < NV) g_nbr[(i / NV) * NV + o] = in_idx[i] + 1;
    } else if (b < 15104) {
        int i = (b - 6912) * 256 + threadIdx.x;   // [0, NV*32) float4 words
        float4 v = ((const float4*)f)[i];
        __half2 h0, h1;
        h0.x = __float2half_rn(v.x); h0.y = __float2half_rn(v.y);
        h1.x = __float2half_rn(v.z); h1.y = __float2half_rn(v.w);
        uint2 pk;
        pk.x = *(uint32_t*)&h0; pk.y = *(uint32_t*)&h1;
        ((uint2*)g_f16)[i + 32] = pk;             // +1 row shift (row 0 stays zero)
    } else {
        int i = (b - 15104) * 256 + threadIdx.x;
#if TC_PATH
        // W[k][cin][cout] -> B[k][cout(row)][cin(col)] fp16, SW128 blocked image
        if (i >= KK * CH * CH) return;
        int k = i >> 14;
        int r = (i >> 7) & 127;   // c_out (N row)
        int c = i & 127;          // c_in  (K col)
        float v = w[(k << 14) + (c << 7) + r];
        uint32_t atom = (uint32_t)(r >> 3) + ((uint32_t)(c >> 6) << 4);
        uint32_t off = atom * 1024u + (uint32_t)(r & 7) * 128u + (uint32_t)(c & 63) * 2u;
        off ^= (off >> 3) & 0x70u;
        g_w16[((uint32_t)k * 32768u + off) >> 1] = __float2half_rn(v);
#else
        // mma.sync B-fragment-ready image: [k][ktile(8)][ntile(16)][lane(32)][reg(2)] u32
        if (i >= KK * 8 * 16 * 32 * 2) return;
        int reg   = i & 1;
        int lane  = (i >> 1) & 31;
        int nt    = (i >> 6) & 15;
        int ktile = (i >> 10) & 7;
        int k     = i >> 13;
        int tig = lane & 3, gid = lane >> 2;
        int n    = nt * 8 + gid;
        int cin0 = ktile * 16 + tig * 2 + reg * 8;
        float w0 = w[(k * CH + cin0) * CH + n];
        float w1 = w[(k * CH + cin0 + 1) * CH + n];
        __half2 h;
        h.x = __float2half_rn(w0);
        h.y = __float2half_rn(w1);
        ((__half2*)g_w16)[i] = h;
#endif
    }
}

// ---------------- launch ----------------
extern "C" void kernel_launch(void* const* d_in, const int* in_sizes, int n_in,
                              void* d_out, int out_size) {
    const float* features = (const float*)d_in[0];
    const float* weight   = (const float*)d_in[1];
    const float* bias     = (const float*)d_in[2];
    const int*   in_idx   = (const int*)d_in[3];
    const int*   out_idx  = (const int*)d_in[4];
    float*       out      = (float*)d_out;

    cudaFuncSetAttribute(k_main, cudaFuncAttributeMaxDynamicSharedMemorySize, SMEM_BYTES);

    k_prep<<<PREP_BLOCKS, 256>>>(features, weight, in_idx, out_idx);
    k_main<<<NV / 128, 256, SMEM_BYTES>>>(bias, out);
}

// round 9
// speedup vs baseline: 4.5953x; 1.1133x over previous
#include <cuda_runtime.h>
#include <cuda_fp16.h>
#include <cstdint>

#define NV 65536
#define KK 27
#define CH 128

// tcgen05 fast path only in the arch-specific sm_103a pass (plain compute_103
// rejects tcgen05 in ptxas).
#if defined(__CUDA_ARCH__) && (defined(__CUDA_ARCH_FEAT_SM103_ALL) || \
    (defined(__CUDA_ARCH_SPECIFIC__) && (__CUDA_ARCH_SPECIFIC__ == 1030)))
#define TC_PATH 1
#else
#define TC_PATH 0
#endif

// ---------------- scratch (static __device__, no allocs) ----------------
// g_nbr holds (input_row + 1); 0 means "no neighbor" -> reads g_f16 row 0,
// which is statically zero and never written (k_prep writes rows 1..NV).
__device__ __align__(256) int    g_nbr[KK * NV];            // 7 MB, zero-init
__device__ __align__(256) __half g_f16[(NV + 1) * CH];      // row 0 = zeros
__device__ __align__(256) __half g_w16[KK * CH * CH];       // 864 KB, per-path layout

// ---------------- common helpers ----------------
__device__ __forceinline__ uint32_t smem_to_u32(const void* smem_ptr) {
    uint32_t addr;
    asm("{ .reg .u64 tmp; cvta.to.shared.u64 tmp, %1; cvt.u32.u64 %0, tmp; }"
        : "=r"(addr) : "l"(smem_ptr));
    return addr;
}

// TC path: hdr + A stages (2x64KB) + W stages (2x32KB) = 197632 B -> 1 CTA/SM.
#define SMEM_BYTES 197632
#define NTHREADS 288

#if TC_PATH
// ---------------- tcgen05 helpers ----------------
__device__ __forceinline__ uint32_t elect_one_pred() {
    uint32_t pred;
    asm volatile(
        "{\n\t.reg .pred p;\n\t"
        "elect.sync _|p, 0xFFFFFFFF;\n\t"
        "selp.b32 %0, 1, 0, p;\n\t}"
        : "=r"(pred));
    return pred;
}

#define TCGEN05_ALLOC(smem_result_addr, nCols) \
    asm volatile("tcgen05.alloc.cta_group::1.sync.aligned.shared::cta.b32 [%0], %1;" \
                 :: "r"((uint32_t)(smem_result_addr)), "r"((uint32_t)(nCols)) : "memory")
#define TCGEN05_DEALLOC(tmem_addr, nCols) \
    asm volatile("tcgen05.dealloc.cta_group::1.sync.aligned.b32 %0, %1;" \
                 :: "r"(tmem_addr), "r"((uint32_t)(nCols)))
#define TCGEN05_RELINQUISH_ALLOC_PERMIT() \
    asm volatile("tcgen05.relinquish_alloc_permit.cta_group::1.sync.aligned;")
#define TCGEN05_WAIT_LD() asm volatile("tcgen05.wait::ld.sync.aligned;" ::: "memory")
#define TCGEN05_FENCE_AFTER()  asm volatile("tcgen05.fence::after_thread_sync;" ::: "memory")
#define TCGEN05_COMMIT(mbar_smem_addr) \
    asm volatile("tcgen05.commit.cta_group::1.mbarrier::arrive::one.shared::cluster.b64 [%0];" \
                 :: "r"((uint32_t)(mbar_smem_addr)) : "memory")
#define FENCE_PROXY_ASYNC_SHARED_CTA() \
    asm volatile("fence.proxy.async.shared::cta;" ::: "memory")
#define MBARRIER_INIT(mbar_smem_addr, count) \
    asm volatile("mbarrier.init.shared.b64 [%0], %1;" \
                 :: "r"((uint32_t)(mbar_smem_addr)), "r"((uint32_t)(count)) : "memory")
#define MBARRIER_ARRIVE(mbar_smem_addr) \
    asm volatile("mbarrier.arrive.shared.b64 _, [%0];" \
                 :: "r"((uint32_t)(mbar_smem_addr)) : "memory")
#define MBARRIER_EXPECT_TX(mbar_smem_addr, tx_bytes) \
    asm volatile("mbarrier.arrive.expect_tx.shared.b64 _, [%0], %1;" \
                 :: "r"((uint32_t)(mbar_smem_addr)), "r"((uint32_t)(tx_bytes)) : "memory")
#define CP_BULK_G2S(dst_smem, src_gmem, nbytes, mbar_smem_addr) \
    asm volatile("cp.async.bulk.shared::cluster.global.mbarrier::complete_tx::bytes " \
                 "[%0], [%1], %2, [%3];" \
                 :: "r"((uint32_t)(dst_smem)), "l"(src_gmem), "r"((uint32_t)(nbytes)), \
                    "r"((uint32_t)(mbar_smem_addr)) : "memory")
#define MBARRIER_WAIT_PARITY(mbar_smem_addr, phase_parity) do { \
    uint32_t _mbar = (uint32_t)(mbar_smem_addr); \
    uint32_t _parity = (uint32_t)(phase_parity); \
    uint32_t _done; \
    asm volatile( \
        "{\n\t.reg .pred p;\n\t" \
        "mbarrier.try_wait.parity.acquire.cta.shared::cta.b64 p, [%1], %2;\n\t" \
        "selp.b32 %0, 1, 0, p;\n\t}" \
        : "=r"(_done) : "r"(_mbar), "r"(_parity) : "memory"); \
    if (!_done) { \
        asm volatile( \
            "{\n\t.reg .pred P1;\n\t" \
            "WAIT_LOOP_%=:\n\t" \
            "mbarrier.try_wait.parity.acquire.cta.shared::cta.b64 P1, [%0], %1, 0x989680;\n\t" \
            "@P1 bra.uni WAIT_DONE_%=;\n\t" \
            "bra.uni WAIT_LOOP_%=;\n\t" \
            "WAIT_DONE_%=:\n\t}" \
            :: "r"(_mbar), "r"(_parity) : "memory"); \
    } \
} while(0)

// SS-mode f16 MMA: both A and B as SMEM descriptors.
#define TCGEN05_MMA_F16_SS(d_tmem, a_desc, b_desc, idesc, enable_d) do { \
    uint32_t _enable = (enable_d) ? 1 : 0; \
    uint32_t _zero = 0; \
    asm volatile( \
        "{\n\t.reg .pred p;\n\t" \
        "setp.ne.u32 p, %6, 0;\n\t" \
        "tcgen05.mma.cta_group::1.kind::f16 [%0], %1, %2, %3, " \
        "{%4, %4, %4, %4}, p;\n\t}" \
        :: "r"(d_tmem), "l"(a_desc), "l"(b_desc), "r"(idesc), \
           "r"(_zero), "r"(_zero), "r"(_enable) \
        : "memory"); \
} while(0)

#define TCGEN05_LD_32X32B_X32(r, tmem_addr) \
    asm volatile( \
        "tcgen05.ld.sync.aligned.32x32b.x32.b32 " \
        "{%0, %1, %2, %3, %4, %5, %6, %7, " \
        " %8, %9, %10, %11, %12, %13, %14, %15, " \
        " %16, %17, %18, %19, %20, %21, %22, %23, " \
        " %24, %25, %26, %27, %28, %29, %30, %31}, [%32];" \
        : "=r"((r)[0]),  "=r"((r)[1]),  "=r"((r)[2]),  "=r"((r)[3]), \
          "=r"((r)[4]),  "=r"((r)[5]),  "=r"((r)[6]),  "=r"((r)[7]), \
          "=r"((r)[8]),  "=r"((r)[9]),  "=r"((r)[10]), "=r"((r)[11]), \
          "=r"((r)[12]), "=r"((r)[13]), "=r"((r)[14]), "=r"((r)[15]), \
          "=r"((r)[16]), "=r"((r)[17]), "=r"((r)[18]), "=r"((r)[19]), \
          "=r"((r)[20]), "=r"((r)[21]), "=r"((r)[22]), "=r"((r)[23]), \
          "=r"((r)[24]), "=r"((r)[25]), "=r"((r)[26]), "=r"((r)[27]), \
          "=r"((r)[28]), "=r"((r)[29]), "=r"((r)[30]), "=r"((r)[31]) \
        : "r"(tmem_addr))

static constexpr uint64_t SMEM_DESC_BASE_SW128 =
    (uint64_t(2) << 61) | (uint64_t(1) << 46) | (uint64_t(64) << 32) | (uint64_t(1) << 16);
#define MAKE_SMEM_DESC(base_addr) \
    (SMEM_DESC_BASE_SW128 | ((uint64_t)((base_addr) >> 4) & 0x3FFF))

// kind::f16, f16 inputs, f32 acc, M=128 (8<<24), N=128 (16<<17)
#define MMA_IDESC_F16 0x8200010u

// SMEM layout (TC): [0] tmem ptr, full mbar @16,24 (count 256),
// empty mbar @32,40 (commit), W mbars @48,56, bias @64..576,
// A stages @1024 (2 x 64KB), W stages @132096 (2 x 32KB). Total 197632.
// A stage: [slice(c>>3)][row 0..255][chunk]: slice stride 32KB; M-block1 at +16KB.
#define MB_FULL(s)  (16u + (uint32_t)(s) * 8u)
#define MB_EMPTY(s) (32u + (uint32_t)(s) * 8u)
#define MB_WMB(s)   (48u + (uint32_t)(s) * 8u)
#define A_OFF(s) (1024u + (uint32_t)(s) * 65536u)
#define W_OFF(s) (132096u + (uint32_t)(s) * 32768u)

__global__ void __launch_bounds__(NTHREADS, 1)
k_main(const float* __restrict__ bias, float* __restrict__ out) {
    extern __shared__ char smem[];
    uint32_t sb = smem_to_u32(smem);
    int tid = threadIdx.x;
    int wid = tid >> 5;
    int lid = tid & 31;
    int o0 = blockIdx.x * 256;

    if (wid == 8) TCGEN05_ALLOC(sb + 0, 256);
    if (tid == 0) {
        MBARRIER_INIT(sb + MB_FULL(0), 256);
        MBARRIER_INIT(sb + MB_FULL(1), 256);
        MBARRIER_INIT(sb + MB_EMPTY(0), 1);
        MBARRIER_INIT(sb + MB_EMPTY(1), 1);
        MBARRIER_INIT(sb + MB_WMB(0), 1);
        MBARRIER_INIT(sb + MB_WMB(1), 1);
    }
    if (tid < 128) ((float*)(smem + 64))[tid] = __ldg(&bias[tid]);
    __syncthreads();
    uint32_t tmem;
    asm volatile("ld.shared.b32 %0, [%1];" : "=r"(tmem) : "r"(sb));
    if (wid == 8) TCGEN05_RELINQUISH_ALLOC_PERMIT();

    if (tid < 256) {
        // ---------------- producers: 8 warps fill A stages ----------------
        const int c = tid & 15;              // 16B chunk within row
        const int row0 = tid >> 4;           // base row (0..15), step 16
        const uint4* fbase = (const uint4*)g_f16 + c;
        // swizzled byte offset within A stage for j=0; +2048 per j (row +16)
        uint32_t aswz;
        {
            uint32_t off = ((uint32_t)(c >> 3) << 15)      // 32KB K-slice
                         + (uint32_t)row0 * 128u
                         + (uint32_t)((c & 7) << 4);
            off ^= (off >> 3) & 0x70u;                     // SW128 swizzle
            aswz = off;
        }
        for (int k = 0; k < KK; ++k) {
            int s = k & 1, n = k >> 1;
            const int* nbk = g_nbr + k * NV + o0 + row0;
            // batch 0 loads issued before the empty wait (hide gather latency)
            uint4 v0[8];
            #pragma unroll
            for (int j = 0; j < 8; ++j)
                v0[j] = __ldg(fbase + (size_t)__ldg(nbk + 16 * j) * 16);
            if (k >= 2) MBARRIER_WAIT_PARITY(sb + MB_EMPTY(s), (n - 1) & 1);
            // batch 1 loads + both stores
            uint4 v1[8];
            #pragma unroll
            for (int j = 0; j < 8; ++j)
                v1[j] = __ldg(fbase + (size_t)__ldg(nbk + 16 * (j + 8)) * 16);
            char* As = smem + A_OFF(s) + aswz;
            #pragma unroll
            for (int j = 0; j < 8; ++j) *(uint4*)(As + j * 2048) = v0[j];
            #pragma unroll
            for (int j = 0; j < 8; ++j) *(uint4*)(As + (j + 8) * 2048) = v1[j];
            FENCE_PROXY_ASYNC_SHARED_CTA();
            MBARRIER_ARRIVE(sb + MB_FULL(s));
        }
        // wait for all MMAs: stage0 14 commits (parity 1), stage1 13 (parity 0)
        MBARRIER_WAIT_PARITY(sb + MB_EMPTY(0), 1);
        MBARRIER_WAIT_PARITY(sb + MB_EMPTY(1), 0);
        TCGEN05_FENCE_AFTER();
        // ---------------- epilogue: 256 rows, 2 D blocks ----------------
        {
            int blk = wid >> 2;
            int row = blk * 128 + (wid & 3) * 32 + lid;
            uint32_t cbase = (uint32_t)(blk * 128);
            float* orow = out + (size_t)(o0 + row) * CH;
            const float* bsm = (const float*)(smem + 64);
            #pragma unroll
            for (int b = 0; b < 128; b += 32) {
                uint32_t d[32];
                TCGEN05_LD_32X32B_X32(d, tmem + cbase + (uint32_t)b);
                TCGEN05_WAIT_LD();
                #pragma unroll
                for (int cc = 0; cc < 32; cc += 4) {
                    float4 v;
                    v.x = __uint_as_float(d[cc + 0]) + bsm[b + cc + 0];
                    v.y = __uint_as_float(d[cc + 1]) + bsm[b + cc + 1];
                    v.z = __uint_as_float(d[cc + 2]) + bsm[b + cc + 2];
                    v.w = __uint_as_float(d[cc + 3]) + bsm[b + cc + 3];
                    *(float4*)(orow + b + cc) = v;
                }
            }
        }
    } else {
        // ---------------- leader warp: W prefetch + MMA issue ----------------
        uint32_t lead = elect_one_pred();
        for (int k = 0; k < KK; ++k) {
            int s = k & 1, n = k >> 1;
            if (k >= 2) MBARRIER_WAIT_PARITY(sb + MB_EMPTY(s), (n - 1) & 1);
            if (lead) {
                MBARRIER_EXPECT_TX(sb + MB_WMB(s), 32768);
                CP_BULK_G2S(sb + W_OFF(s), (const char*)g_w16 + (size_t)k * 32768,
                            32768, sb + MB_WMB(s));
            }
            MBARRIER_WAIT_PARITY(sb + MB_FULL(s), n & 1);
            MBARRIER_WAIT_PARITY(sb + MB_WMB(s), n & 1);
            TCGEN05_FENCE_AFTER();
            if (lead) {
                uint64_t ad = MAKE_SMEM_DESC(sb + A_OFF(s));
                uint64_t bd = MAKE_SMEM_DESC(sb + W_OFF(s));
                #pragma unroll
                for (int mb = 0; mb < 2; ++mb) {
                    #pragma unroll
                    for (int ks = 0; ks < 8; ++ks) {
                        // A: K-slice1 at 32KB = 2048 units; M-block1 at 16KB = 1024
                        uint64_t aoff = (uint64_t)(mb * 1024)
                                      + ((ks < 4) ? (uint64_t)(2 * ks)
                                                  : (uint64_t)(2048 + 2 * (ks - 4)));
                        // W: K-slice1 at 16KB = 1024 units
                        uint64_t boff = (ks < 4) ? (uint64_t)(2 * ks)
                                                 : (uint64_t)(1024 + 2 * (ks - 4));
                        TCGEN05_MMA_F16_SS(tmem + (uint32_t)(mb * 128),
                                           ad + aoff, bd + boff, MMA_IDESC_F16,
                                           !(k == 0 && ks == 0));
                    }
                }
                TCGEN05_COMMIT(sb + MB_EMPTY(s));
            }
        }
    }
    __syncthreads();
    if (wid == 8) TCGEN05_DEALLOC(tmem, 256);
}

#else  // ---------------- mma.sync fallback path (M=256 via two halves) --------
#define A_FB(w)  ((w) * 4096)
#define W_FB     32768
#define BIAS_FB  65536

__device__ __forceinline__ void mma16816(float* c, uint32_t a0, uint32_t a1,
                                         uint32_t a2, uint32_t a3,
                                         uint32_t b0, uint32_t b1) {
    asm volatile(
        "mma.sync.aligned.m16n8k16.row.col.f32.f16.f16.f32 "
        "{%0,%1,%2,%3}, {%4,%5,%6,%7}, {%8,%9}, {%0,%1,%2,%3};"
        : "+f"(c[0]), "+f"(c[1]), "+f"(c[2]), "+f"(c[3])
        : "r"(a0), "r"(a1), "r"(a2), "r"(a3), "r"(b0), "r"(b1));
}

__global__ void __launch_bounds__(NTHREADS)
k_main(const float* __restrict__ bias, float* __restrict__ out) {
    extern __shared__ char smem[];
    uint32_t sb = smem_to_u32(smem);
    int tid = threadIdx.x;
    int wid = tid >> 5;
    int lane = tid & 31;

    if (tid < 128) ((float*)(smem + BIAS_FB))[tid] = __ldg(&bias[tid]);

    int m = lane >> 3, rl = lane & 7;
    int lrow = rl + ((m & 1) << 3);

    for (int half = 0; half < 2; ++half) {
        int o0 = blockIdx.x * 256 + half * 128;
        float acc[16][4] = {};
        for (int k = 0; k < KK; ++k) {
            __syncthreads();
            if (tid < 256) {
                int nbl = (lane < 16) ? __ldg(&g_nbr[k * NV + o0 + wid * 16 + lane]) : 0;
                char* ab = smem + A_FB(wid);
                #pragma unroll
                for (int i = 0; i < 8; ++i) {
                    int row = i * 2 + (lane >> 4);
                    int rn = __shfl_sync(0xffffffffu, nbl, row);
                    uint4 v = __ldg((const uint4*)(g_f16 + (size_t)rn * CH) + (lane & 15));
                    int c = lane & 15;
                    *(uint4*)(ab + row * 256 + ((c ^ (row & 7)) << 4)) = v;
                }
                const uint4* ws = (const uint4*)((const char*)g_w16 + (size_t)k * 32768)
                                  + wid * 256 + lane;
                uint4* wd = (uint4*)(smem + W_FB) + wid * 256 + lane;
                #pragma unroll
                for (int i = 0; i < 8; ++i) wd[i * 32] = __ldg(ws + i * 32);
            }
            __syncthreads();
            if (tid < 256) {
                uint32_t ab32 = sb + A_FB(wid);
                uint32_t wb32 = sb + W_FB;
                uint32_t arow = ab32 + (uint32_t)lrow * 256u;
                #pragma unroll
                for (int kt = 0; kt < 8; ++kt) {
                    int chunk = kt * 2 + (m >> 1);
                    uint32_t aaddr = arow + (uint32_t)((chunk ^ (lrow & 7)) << 4);
                    uint32_t a0, a1, a2, a3;
                    asm volatile(
                        "ldmatrix.sync.aligned.m8n8.x4.shared.b16 {%0,%1,%2,%3}, [%4];"
                        : "=r"(a0), "=r"(a1), "=r"(a2), "=r"(a3) : "r"(aaddr));
                    #pragma unroll
                    for (int nt = 0; nt < 16; ++nt) {
                        uint32_t baddr = wb32 + (uint32_t)((((kt << 4) + nt) << 8) + (lane << 3));
                        uint32_t b0, b1;
                        asm volatile("ld.shared.v2.b32 {%0,%1}, [%2];"
                                     : "=r"(b0), "=r"(b1) : "r"(baddr));
                        mma16816(acc[nt], a0, a1, a2, a3, b0, b1);
                    }
                }
            }
        }
        if (tid < 256) {
            int gid = lane >> 2, tig = lane & 3;
            const float* bsm = (const float*)(smem + BIAS_FB);
            size_t r0 = (size_t)(o0 + wid * 16 + gid);
            #pragma unroll
            for (int nt = 0; nt < 16; ++nt) {
                int col = nt * 8 + tig * 2;
                float2 bv = *(const float2*)(bsm + col);
                float2 v0 = make_float2(acc[nt][0] + bv.x, acc[nt][1] + bv.y);
                float2 v1 = make_float2(acc[nt][2] + bv.x, acc[nt][3] + bv.y);
                *(float2*)(out + r0 * CH + col) = v0;
                *(float2*)(out + (r0 + 8) * CH + col) = v1;
            }
        }
        __syncthreads();
    }
}
#endif  // TC_PATH

// ---------------- fused prep kernel ----------------
// blocks [0, 6912): rulebook scatter (g_nbr = in_idx+1)
// blocks [6912, 15104): feature fp16 convert, float4-vectorized (+1 row shift)
// blocks [15104, 16832): weight pack (per-path layout)
#define PREP_BLOCKS 16832

__global__ void k_prep(const float* __restrict__ f, const float* __restrict__ w,
                       const int* __restrict__ in_idx, const int* __restrict__ out_idx) {
    int b = blockIdx.x;
    if (b < 6912) {
        int i = b * 256 + threadIdx.x;            // [0, KK*NV)
        int o = out_idx[i];
        if (o < NV) g_nbr[(i / NV) * NV + o] = in_idx[i] + 1;
    } else if (b < 15104) {
        int i = (b - 6912) * 256 + threadIdx.x;   // [0, NV*32) float4 words
        float4 v = ((const float4*)f)[i];
        __half2 h0, h1;
        h0.x = __float2half_rn(v.x); h0.y = __float2half_rn(v.y);
        h1.x = __float2half_rn(v.z); h1.y = __float2half_rn(v.w);
        uint2 pk;
        pk.x = *(uint32_t*)&h0; pk.y = *(uint32_t*)&h1;
        ((uint2*)g_f16)[i + 32] = pk;             // +1 row shift (row 0 stays zero)
    } else {
        int i = (b - 15104) * 256 + threadIdx.x;
#if TC_PATH
        // W[k][cin][cout] -> B[k][cout(row)][cin(col)] fp16, SW128 blocked image
        if (i >= KK * CH * CH) return;
        int k = i >> 14;
        int r = (i >> 7) & 127;   // c_out (N row)
        int c = i & 127;          // c_in  (K col)
        float v = w[(k << 14) + (c << 7) + r];
        uint32_t atom = (uint32_t)(r >> 3) + ((uint32_t)(c >> 6) << 4);
        uint32_t off = atom * 1024u + (uint32_t)(r & 7) * 128u + (uint32_t)(c & 63) * 2u;
        off ^= (off >> 3) & 0x70u;
        g_w16[((uint32_t)k * 32768u + off) >> 1] = __float2half_rn(v);
#else
        // mma.sync B-fragment-ready image: [k][ktile(8)][ntile(16)][lane(32)][reg(2)] u32
        if (i >= KK * 8 * 16 * 32 * 2) return;
        int reg   = i & 1;
        int lane  = (i >> 1) & 31;
        int nt    = (i >> 6) & 15;
        int ktile = (i >> 10) & 7;
        int k     = i >> 13;
        int tig = lane & 3, gid = lane >> 2;
        int n    = nt * 8 + gid;
        int cin0 = ktile * 16 + tig * 2 + reg * 8;
        float w0 = w[(k * CH + cin0) * CH + n];
        float w1 = w[(k * CH + cin0 + 1) * CH + n];
        __half2 h;
        h.x = __float2half_rn(w0);
        h.y = __float2half_rn(w1);
        ((__half2*)g_w16)[i] = h;
#endif
    }
}

// ---------------- launch ----------------
extern "C" void kernel_launch(void* const* d_in, const int* in_sizes, int n_in,
                              void* d_out, int out_size) {
    const float* features = (const float*)d_in[0];
    const float* weight   = (const float*)d_in[1];
    const float* bias     = (const float*)d_in[2];
    const int*   in_idx   = (const int*)d_in[3];
    const int*   out_idx  = (const int*)d_in[4];
    float*       out      = (float*)d_out;

    cudaFuncSetAttribute(k_main, cudaFuncAttributeMaxDynamicSharedMemorySize, SMEM_BYTES);

    k_prep<<<PREP_BLOCKS, 256>>>(features, weight, in_idx, out_idx);
    k_main<<<NV / 256, NTHREADS, SMEM_BYTES>>>(bias, out);
}

// round 10
// speedup vs baseline: 4.6876x; 1.0201x over previous
#include <cuda_runtime.h>
#include <cuda_fp16.h>
#include <cstdint>

#define NV 65536
#define KK 27
#define CH 128

// tcgen05 fast path only in the arch-specific sm_103a pass (plain compute_103
// rejects tcgen05 in ptxas).
#if defined(__CUDA_ARCH__) && (defined(__CUDA_ARCH_FEAT_SM103_ALL) || \
    (defined(__CUDA_ARCH_SPECIFIC__) && (__CUDA_ARCH_SPECIFIC__ == 1030)))
#define TC_PATH 1
#else
#define TC_PATH 0
#endif

// ---------------- scratch (static __device__, no allocs) ----------------
// g_nbr holds (input_row + 1); 0 means "no neighbor" -> reads g_f16 row 0,
// which is statically zero and never written (k_prep writes rows 1..NV).
__device__ __align__(256) int    g_nbr[KK * NV];            // 7 MB, zero-init
__device__ __align__(256) __half g_f16[(NV + 1) * CH];      // row 0 = zeros
__device__ __align__(256) __half g_w16[KK * CH * CH];       // 864 KB, per-path layout

// ---------------- common helpers ----------------
__device__ __forceinline__ uint32_t smem_to_u32(const void* smem_ptr) {
    uint32_t addr;
    asm("{ .reg .u64 tmp; cvta.to.shared.u64 tmp, %1; cvt.u32.u64 %0, tmp; }"
        : "=r"(addr) : "l"(smem_ptr));
    return addr;
}

// TC path: hdr + A stages (2x64KB) + W stages (2x32KB) = 197632 B -> 1 CTA/SM.
#define SMEM_BYTES 197632
#define NTHREADS 288

// cp.async (L1-caching variant) + mbarrier-tracked completion (sm_80+)
#define CP_ASYNC_CA16(dst, src) \
    asm volatile("cp.async.ca.shared.global [%0], [%1], 16;" \
                 :: "r"((uint32_t)(dst)), "l"(src) : "memory")
#define CP_ASYNC_MBAR_ARRIVE_NOINC(mbar) \
    asm volatile("cp.async.mbarrier.arrive.noinc.shared.b64 [%0];" \
                 :: "r"((uint32_t)(mbar)) : "memory")

#if TC_PATH
// ---------------- tcgen05 helpers ----------------
__device__ __forceinline__ uint32_t elect_one_pred() {
    uint32_t pred;
    asm volatile(
        "{\n\t.reg .pred p;\n\t"
        "elect.sync _|p, 0xFFFFFFFF;\n\t"
        "selp.b32 %0, 1, 0, p;\n\t}"
        : "=r"(pred));
    return pred;
}

#define TCGEN05_ALLOC(smem_result_addr, nCols) \
    asm volatile("tcgen05.alloc.cta_group::1.sync.aligned.shared::cta.b32 [%0], %1;" \
                 :: "r"((uint32_t)(smem_result_addr)), "r"((uint32_t)(nCols)) : "memory")
#define TCGEN05_DEALLOC(tmem_addr, nCols) \
    asm volatile("tcgen05.dealloc.cta_group::1.sync.aligned.b32 %0, %1;" \
                 :: "r"(tmem_addr), "r"((uint32_t)(nCols)))
#define TCGEN05_RELINQUISH_ALLOC_PERMIT() \
    asm volatile("tcgen05.relinquish_alloc_permit.cta_group::1.sync.aligned;")
#define TCGEN05_WAIT_LD() asm volatile("tcgen05.wait::ld.sync.aligned;" ::: "memory")
#define TCGEN05_FENCE_AFTER()  asm volatile("tcgen05.fence::after_thread_sync;" ::: "memory")
#define TCGEN05_COMMIT(mbar_smem_addr) \
    asm volatile("tcgen05.commit.cta_group::1.mbarrier::arrive::one.shared::cluster.b64 [%0];" \
                 :: "r"((uint32_t)(mbar_smem_addr)) : "memory")
#define FENCE_PROXY_ASYNC_SHARED_CTA() \
    asm volatile("fence.proxy.async.shared::cta;" ::: "memory")
#define MBARRIER_INIT(mbar_smem_addr, count) \
    asm volatile("mbarrier.init.shared.b64 [%0], %1;" \
                 :: "r"((uint32_t)(mbar_smem_addr)), "r"((uint32_t)(count)) : "memory")
#define MBARRIER_ARRIVE(mbar_smem_addr) \
    asm volatile("mbarrier.arrive.shared.b64 _, [%0];" \
                 :: "r"((uint32_t)(mbar_smem_addr)) : "memory")
#define MBARRIER_EXPECT_TX(mbar_smem_addr, tx_bytes) \
    asm volatile("mbarrier.arrive.expect_tx.shared.b64 _, [%0], %1;" \
                 :: "r"((uint32_t)(mbar_smem_addr)), "r"((uint32_t)(tx_bytes)) : "memory")
#define CP_BULK_G2S(dst_smem, src_gmem, nbytes, mbar_smem_addr) \
    asm volatile("cp.async.bulk.shared::cluster.global.mbarrier::complete_tx::bytes " \
                 "[%0], [%1], %2, [%3];" \
                 :: "r"((uint32_t)(dst_smem)), "l"(src_gmem), "r"((uint32_t)(nbytes)), \
                    "r"((uint32_t)(mbar_smem_addr)) : "memory")
#define MBARRIER_WAIT_PARITY(mbar_smem_addr, phase_parity) do { \
    uint32_t _mbar = (uint32_t)(mbar_smem_addr); \
    uint32_t _parity = (uint32_t)(phase_parity); \
    uint32_t _done; \
    asm volatile( \
        "{\n\t.reg .pred p;\n\t" \
        "mbarrier.try_wait.parity.acquire.cta.shared::cta.b64 p, [%1], %2;\n\t" \
        "selp.b32 %0, 1, 0, p;\n\t}" \
        : "=r"(_done) : "r"(_mbar), "r"(_parity) : "memory"); \
    if (!_done) { \
        asm volatile( \
            "{\n\t.reg .pred P1;\n\t" \
            "WAIT_LOOP_%=:\n\t" \
            "mbarrier.try_wait.parity.acquire.cta.shared::cta.b64 P1, [%0], %1, 0x989680;\n\t" \
            "@P1 bra.uni WAIT_DONE_%=;\n\t" \
            "bra.uni WAIT_LOOP_%=;\n\t" \
            "WAIT_DONE_%=:\n\t}" \
            :: "r"(_mbar), "r"(_parity) : "memory"); \
    } \
} while(0)

// SS-mode f16 MMA: both A and B as SMEM descriptors.
#define TCGEN05_MMA_F16_SS(d_tmem, a_desc, b_desc, idesc, enable_d) do { \
    uint32_t _enable = (enable_d) ? 1 : 0; \
    uint32_t _zero = 0; \
    asm volatile( \
        "{\n\t.reg .pred p;\n\t" \
        "setp.ne.u32 p, %6, 0;\n\t" \
        "tcgen05.mma.cta_group::1.kind::f16 [%0], %1, %2, %3, " \
        "{%4, %4, %4, %4}, p;\n\t}" \
        :: "r"(d_tmem), "l"(a_desc), "l"(b_desc), "r"(idesc), \
           "r"(_zero), "r"(_zero), "r"(_enable) \
        : "memory"); \
} while(0)

#define TCGEN05_LD_32X32B_X32(r, tmem_addr) \
    asm volatile( \
        "tcgen05.ld.sync.aligned.32x32b.x32.b32 " \
        "{%0, %1, %2, %3, %4, %5, %6, %7, " \
        " %8, %9, %10, %11, %12, %13, %14, %15, " \
        " %16, %17, %18, %19, %20, %21, %22, %23, " \
        " %24, %25, %26, %27, %28, %29, %30, %31}, [%32];" \
        : "=r"((r)[0]),  "=r"((r)[1]),  "=r"((r)[2]),  "=r"((r)[3]), \
          "=r"((r)[4]),  "=r"((r)[5]),  "=r"((r)[6]),  "=r"((r)[7]), \
          "=r"((r)[8]),  "=r"((r)[9]),  "=r"((r)[10]), "=r"((r)[11]), \
          "=r"((r)[12]), "=r"((r)[13]), "=r"((r)[14]), "=r"((r)[15]), \
          "=r"((r)[16]), "=r"((r)[17]), "=r"((r)[18]), "=r"((r)[19]), \
          "=r"((r)[20]), "=r"((r)[21]), "=r"((r)[22]), "=r"((r)[23]), \
          "=r"((r)[24]), "=r"((r)[25]), "=r"((r)[26]), "=r"((r)[27]), \
          "=r"((r)[28]), "=r"((r)[29]), "=r"((r)[30]), "=r"((r)[31]) \
        : "r"(tmem_addr))

static constexpr uint64_t SMEM_DESC_BASE_SW128 =
    (uint64_t(2) << 61) | (uint64_t(1) << 46) | (uint64_t(64) << 32) | (uint64_t(1) << 16);
#define MAKE_SMEM_DESC(base_addr) \
    (SMEM_DESC_BASE_SW128 | ((uint64_t)((base_addr) >> 4) & 0x3FFF))

// kind::f16, f16 inputs, f32 acc, M=128 (8<<24), N=128 (16<<17)
#define MMA_IDESC_F16 0x8200010u

// SMEM layout (TC): [0] tmem ptr, full mbar @16,24 (count 256, cp.async-armed),
// empty mbar @32,40 (commit), W mbars @48,56, bias @64..576,
// A stages @1024 (2 x 64KB), W stages @132096 (2 x 32KB). Total 197632.
// A stage: [slice(c>>3)][row 0..255][chunk]: slice stride 32KB; M-block1 at +16KB.
#define MB_FULL(s)  (16u + (uint32_t)(s) * 8u)
#define MB_EMPTY(s) (32u + (uint32_t)(s) * 8u)
#define MB_WMB(s)   (48u + (uint32_t)(s) * 8u)
#define A_OFF(s) (1024u + (uint32_t)(s) * 65536u)
#define W_OFF(s) (132096u + (uint32_t)(s) * 32768u)

__global__ void __launch_bounds__(NTHREADS, 1)
k_main(const float* __restrict__ bias, float* __restrict__ out) {
    extern __shared__ char smem[];
    uint32_t sb = smem_to_u32(smem);
    int tid = threadIdx.x;
    int wid = tid >> 5;
    int lid = tid & 31;
    int o0 = blockIdx.x * 256;

    if (wid == 8) TCGEN05_ALLOC(sb + 0, 256);
    if (tid == 0) {
        MBARRIER_INIT(sb + MB_FULL(0), 256);
        MBARRIER_INIT(sb + MB_FULL(1), 256);
        MBARRIER_INIT(sb + MB_EMPTY(0), 1);
        MBARRIER_INIT(sb + MB_EMPTY(1), 1);
        MBARRIER_INIT(sb + MB_WMB(0), 1);
        MBARRIER_INIT(sb + MB_WMB(1), 1);
    }
    if (tid < 128) ((float*)(smem + 64))[tid] = __ldg(&bias[tid]);
    __syncthreads();
    uint32_t tmem;
    asm volatile("ld.shared.b32 %0, [%1];" : "=r"(tmem) : "r"(sb));
    if (wid == 8) TCGEN05_RELINQUISH_ALLOC_PERMIT();

    if (tid < 256) {
        // ------- producers: 8 warps, fire-and-forget cp.async A fills -------
        const int c = tid & 15;              // 16B chunk within row
        const int row0 = tid >> 4;           // base row (0..15), step 16
        const uint4* fbase = (const uint4*)g_f16 + c;
        // swizzled byte offset within A stage for j=0; +2048 per j (row +16)
        uint32_t aswz;
        {
            uint32_t off = ((uint32_t)(c >> 3) << 15)      // 32KB K-slice
                         + (uint32_t)row0 * 128u
                         + (uint32_t)((c & 7) << 4);
            off ^= (off >> 3) & 0x70u;                     // SW128 swizzle
            aswz = off;
        }
        for (int k = 0; k < KK; ++k) {
            int s = k & 1, n = k >> 1;
            if (k >= 2) MBARRIER_WAIT_PARITY(sb + MB_EMPTY(s), (n - 1) & 1);
            const int* nbk = g_nbr + k * NV + o0 + row0;
            uint32_t As = sb + A_OFF(s) + aswz;
            #pragma unroll
            for (int j = 0; j < 16; ++j) {
                int nb = __ldg(nbk + 16 * j);
                CP_ASYNC_CA16(As + (uint32_t)j * 2048u, fbase + (size_t)nb * 16);
            }
            // async arrive on full[s] once this thread's 16 copies complete
            CP_ASYNC_MBAR_ARRIVE_NOINC(sb + MB_FULL(s));
        }
        // wait for all MMAs: stage0 14 commits (parity 1), stage1 13 (parity 0)
        MBARRIER_WAIT_PARITY(sb + MB_EMPTY(0), 1);
        MBARRIER_WAIT_PARITY(sb + MB_EMPTY(1), 0);
        TCGEN05_FENCE_AFTER();
        // ---------------- epilogue: 256 rows, 2 D blocks ----------------
        {
            int blk = wid >> 2;
            int row = blk * 128 + (wid & 3) * 32 + lid;
            uint32_t cbase = (uint32_t)(blk * 128);
            float* orow = out + (size_t)(o0 + row) * CH;
            const float* bsm = (const float*)(smem + 64);
            #pragma unroll
            for (int b = 0; b < 128; b += 32) {
                uint32_t d[32];
                TCGEN05_LD_32X32B_X32(d, tmem + cbase + (uint32_t)b);
                TCGEN05_WAIT_LD();
                #pragma unroll
                for (int cc = 0; cc < 32; cc += 4) {
                    float4 v;
                    v.x = __uint_as_float(d[cc + 0]) + bsm[b + cc + 0];
                    v.y = __uint_as_float(d[cc + 1]) + bsm[b + cc + 1];
                    v.z = __uint_as_float(d[cc + 2]) + bsm[b + cc + 2];
                    v.w = __uint_as_float(d[cc + 3]) + bsm[b + cc + 3];
                    *(float4*)(orow + b + cc) = v;
                }
            }
        }
    } else {
        // ---------------- leader warp: W prefetch + MMA issue ----------------
        uint32_t lead = elect_one_pred();
        for (int k = 0; k < KK; ++k) {
            int s = k & 1, n = k >> 1;
            if (k >= 2) MBARRIER_WAIT_PARITY(sb + MB_EMPTY(s), (n - 1) & 1);
            if (lead) {
                MBARRIER_EXPECT_TX(sb + MB_WMB(s), 32768);
                CP_BULK_G2S(sb + W_OFF(s), (const char*)g_w16 + (size_t)k * 32768,
                            32768, sb + MB_WMB(s));
            }
            MBARRIER_WAIT_PARITY(sb + MB_FULL(s), n & 1);
            MBARRIER_WAIT_PARITY(sb + MB_WMB(s), n & 1);
            FENCE_PROXY_ASYNC_SHARED_CTA();   // publish cp.async fills to async proxy
            TCGEN05_FENCE_AFTER();
            if (lead) {
                uint64_t ad = MAKE_SMEM_DESC(sb + A_OFF(s));
                uint64_t bd = MAKE_SMEM_DESC(sb + W_OFF(s));
                #pragma unroll
                for (int mb = 0; mb < 2; ++mb) {
                    #pragma unroll
                    for (int ks = 0; ks < 8; ++ks) {
                        // A: K-slice1 at 32KB = 2048 units; M-block1 at 16KB = 1024
                        uint64_t aoff = (uint64_t)(mb * 1024)
                                      + ((ks < 4) ? (uint64_t)(2 * ks)
                                                  : (uint64_t)(2048 + 2 * (ks - 4)));
                        // W: K-slice1 at 16KB = 1024 units
                        uint64_t boff = (ks < 4) ? (uint64_t)(2 * ks)
                                                 : (uint64_t)(1024 + 2 * (ks - 4));
                        TCGEN05_MMA_F16_SS(tmem + (uint32_t)(mb * 128),
                                           ad + aoff, bd + boff, MMA_IDESC_F16,
                                           !(k == 0 && ks == 0));
                    }
                }
                TCGEN05_COMMIT(sb + MB_EMPTY(s));
            }
        }
    }
    __syncthreads();
    if (wid == 8) TCGEN05_DEALLOC(tmem, 256);
}

#else  // ---------------- mma.sync fallback path (M=256 via two halves) --------
#define A_FB(w)  ((w) * 4096)
#define W_FB     32768
#define BIAS_FB  65536

__device__ __forceinline__ void mma16816(float* c, uint32_t a0, uint32_t a1,
                                         uint32_t a2, uint32_t a3,
                                         uint32_t b0, uint32_t b1) {
    asm volatile(
        "mma.sync.aligned.m16n8k16.row.col.f32.f16.f16.f32 "
        "{%0,%1,%2,%3}, {%4,%5,%6,%7}, {%8,%9}, {%0,%1,%2,%3};"
        : "+f"(c[0]), "+f"(c[1]), "+f"(c[2]), "+f"(c[3])
        : "r"(a0), "r"(a1), "r"(a2), "r"(a3), "r"(b0), "r"(b1));
}

__global__ void __launch_bounds__(NTHREADS)
k_main(const float* __restrict__ bias, float* __restrict__ out) {
    extern __shared__ char smem[];
    uint32_t sb = smem_to_u32(smem);
    int tid = threadIdx.x;
    int wid = tid >> 5;
    int lane = tid & 31;

    if (tid < 128) ((float*)(smem + BIAS_FB))[tid] = __ldg(&bias[tid]);

    int m = lane >> 3, rl = lane & 7;
    int lrow = rl + ((m & 1) << 3);

    for (int half = 0; half < 2; ++half) {
        int o0 = blockIdx.x * 256 + half * 128;
        float acc[16][4] = {};
        for (int k = 0; k < KK; ++k) {
            __syncthreads();
            if (tid < 256) {
                int nbl = (lane < 16) ? __ldg(&g_nbr[k * NV + o0 + wid * 16 + lane]) : 0;
                char* ab = smem + A_FB(wid);
                #pragma unroll
                for (int i = 0; i < 8; ++i) {
                    int row = i * 2 + (lane >> 4);
                    int rn = __shfl_sync(0xffffffffu, nbl, row);
                    uint4 v = __ldg((const uint4*)(g_f16 + (size_t)rn * CH) + (lane & 15));
                    int c = lane & 15;
                    *(uint4*)(ab + row * 256 + ((c ^ (row & 7)) << 4)) = v;
                }
                const uint4* ws = (const uint4*)((const char*)g_w16 + (size_t)k * 32768)
                                  + wid * 256 + lane;
                uint4* wd = (uint4*)(smem + W_FB) + wid * 256 + lane;
                #pragma unroll
                for (int i = 0; i < 8; ++i) wd[i * 32] = __ldg(ws + i * 32);
            }
            __syncthreads();
            if (tid < 256) {
                uint32_t ab32 = sb + A_FB(wid);
                uint32_t wb32 = sb + W_FB;
                uint32_t arow = ab32 + (uint32_t)lrow * 256u;
                #pragma unroll
                for (int kt = 0; kt < 8; ++kt) {
                    int chunk = kt * 2 + (m >> 1);
                    uint32_t aaddr = arow + (uint32_t)((chunk ^ (lrow & 7)) << 4);
                    uint32_t a0, a1, a2, a3;
                    asm volatile(
                        "ldmatrix.sync.aligned.m8n8.x4.shared.b16 {%0,%1,%2,%3}, [%4];"
                        : "=r"(a0), "=r"(a1), "=r"(a2), "=r"(a3) : "r"(aaddr));
                    #pragma unroll
                    for (int nt = 0; nt < 16; ++nt) {
                        uint32_t baddr = wb32 + (uint32_t)((((kt << 4) + nt) << 8) + (lane << 3));
                        uint32_t b0, b1;
                        asm volatile("ld.shared.v2.b32 {%0,%1}, [%2];"
                                     : "=r"(b0), "=r"(b1) : "r"(baddr));
                        mma16816(acc[nt], a0, a1, a2, a3, b0, b1);
                    }
                }
            }
        }
        if (tid < 256) {
            int gid = lane >> 2, tig = lane & 3;
            const float* bsm = (const float*)(smem + BIAS_FB);
            int o0h = blockIdx.x * 256 + half * 128;
            size_t r0 = (size_t)(o0h + wid * 16 + gid);
            #pragma unroll
            for (int nt = 0; nt < 16; ++nt) {
                int col = nt * 8 + tig * 2;
                float2 bv = *(const float2*)(bsm + col);
                float2 v0 = make_float2(acc[nt][0] + bv.x, acc[nt][1] + bv.y);
                float2 v1 = make_float2(acc[nt][2] + bv.x, acc[nt][3] + bv.y);
                *(float2*)(out + r0 * CH + col) = v0;
                *(float2*)(out + (r0 + 8) * CH + col) = v1;
            }
        }
        __syncthreads();
    }
}
#endif  // TC_PATH

// ---------------- fused prep kernel ----------------
// blocks [0, 6912): rulebook scatter (g_nbr = in_idx+1)
// blocks [6912, 15104): feature fp16 convert, float4-vectorized (+1 row shift)
// blocks [15104, 16832): weight pack (per-path layout)
#define PREP_BLOCKS 16832

__global__ void k_prep(const float* __restrict__ f, const float* __restrict__ w,
                       const int* __restrict__ in_idx, const int* __restrict__ out_idx) {
    int b = blockIdx.x;
    if (b < 6912) {
        int i = b * 256 + threadIdx.x;            // [0, KK*NV)
        int o = out_idx[i];
        if (o < NV) g_nbr[(i / NV) * NV + o] = in_idx[i] + 1;
    } else if (b < 15104) {
        int i = (b - 6912) * 256 + threadIdx.x;   // [0, NV*32) float4 words
        float4 v = ((const float4*)f)[i];
        __half2 h0, h1;
        h0.x = __float2half_rn(v.x); h0.y = __float2half_rn(v.y);
        h1.x = __float2half_rn(v.z); h1.y = __float2half_rn(v.w);
        uint2 pk;
        pk.x = *(uint32_t*)&h0; pk.y = *(uint32_t*)&h1;
        ((uint2*)g_f16)[i + 32] = pk;             // +1 row shift (row 0 stays zero)
    } else {
        int i = (b - 15104) * 256 + threadIdx.x;
#if TC_PATH
        // W[k][cin][cout] -> B[k][cout(row)][cin(col)] fp16, SW128 blocked image
        if (i >= KK * CH * CH) return;
        int k = i >> 14;
        int r = (i >> 7) & 127;   // c_out (N row)
        int c = i & 127;          // c_in  (K col)
        float v = w[(k << 14) + (c << 7) + r];
        uint32_t atom = (uint32_t)(r >> 3) + ((uint32_t)(c >> 6) << 4);
        uint32_t off = atom * 1024u + (uint32_t)(r & 7) * 128u + (uint32_t)(c & 63) * 2u;
        off ^= (off >> 3) & 0x70u;
        g_w16[((uint32_t)k * 32768u + off) >> 1] = __float2half_rn(v);
#else
        // mma.sync B-fragment-ready image: [k][ktile(8)][ntile(16)][lane(32)][reg(2)] u32
        if (i >= KK * 8 * 16 * 32 * 2) return;
        int reg   = i & 1;
        int lane  = (i >> 1) & 31;
        int nt    = (i >> 6) & 15;
        int ktile = (i >> 10) & 7;
        int k     = i >> 13;
        int tig = lane & 3, gid = lane >> 2;
        int n    = nt * 8 + gid;
        int cin0 = ktile * 16 + tig * 2 + reg * 8;
        float w0 = w[(k * CH + cin0) * CH + n];
        float w1 = w[(k * CH + cin0 + 1) * CH + n];
        __half2 h;
        h.x = __float2half_rn(w0);
        h.y = __float2half_rn(w1);
        ((__half2*)g_w16)[i] = h;
#endif
    }
}

// ---------------- launch ----------------
extern "C" void kernel_launch(void* const* d_in, const int* in_sizes, int n_in,
                              void* d_out, int out_size) {
    const float* features = (const float*)d_in[0];
    const float* weight   = (const float*)d_in[1];
    const float* bias     = (const float*)d_in[2];
    const int*   in_idx   = (const int*)d_in[3];
    const int*   out_idx  = (const int*)d_in[4];
    float*       out      = (float*)d_out;

    cudaFuncSetAttribute(k_main, cudaFuncAttributeMaxDynamicSharedMemorySize, SMEM_BYTES);

    k_prep<<<PREP_BLOCKS, 256>>>(features, weight, in_idx, out_idx);
    k_main<<<NV / 256, NTHREADS, SMEM_BYTES>>>(bias, out);
}

// round 11
// speedup vs baseline: 4.7939x; 1.0227x over previous
#include <cuda_runtime.h>
#include <cuda_fp16.h>
#include <cstdint>

#define NV 65536
#define KK 27
#define CH 128

// tcgen05 fast path only in the arch-specific sm_103a pass (plain compute_103
// rejects tcgen05 in ptxas).
#if defined(__CUDA_ARCH__) && (defined(__CUDA_ARCH_FEAT_SM103_ALL) || \
    (defined(__CUDA_ARCH_SPECIFIC__) && (__CUDA_ARCH_SPECIFIC__ == 1030)))
#define TC_PATH 1
#else
#define TC_PATH 0
#endif

// ---------------- scratch (static __device__, no allocs) ----------------
// g_nbr holds (input_row + 1); 0 means "no neighbor" -> reads g_f16 row 0,
// which is statically zero and never written (k_prep writes rows 1..NV).
__device__ __align__(256) int    g_nbr[KK * NV];            // 7 MB, zero-init
__device__ __align__(256) __half g_f16[(NV + 1) * CH];      // row 0 = zeros
__device__ __align__(256) __half g_w16[KK * CH * CH];       // 864 KB, per-path layout

// ---------------- common helpers ----------------
__device__ __forceinline__ uint32_t smem_to_u32(const void* smem_ptr) {
    uint32_t addr;
    asm("{ .reg .u64 tmp; cvta.to.shared.u64 tmp, %1; cvt.u32.u64 %0, tmp; }"
        : "=r"(addr) : "l"(smem_ptr));
    return addr;
}

// TC path: hdr + A stages (2x64KB) + W stages (2x32KB) = 197632 B -> 1 CTA/SM.
#define SMEM_BYTES 197632
#define NTHREADS 288

// cp.async (L1-caching variant) + mbarrier-tracked completion (sm_80+)
#define CP_ASYNC_CA16(dst, src) \
    asm volatile("cp.async.ca.shared.global [%0], [%1], 16;" \
                 :: "r"((uint32_t)(dst)), "l"(src) : "memory")
#define CP_ASYNC_MBAR_ARRIVE_NOINC(mbar) \
    asm volatile("cp.async.mbarrier.arrive.noinc.shared.b64 [%0];" \
                 :: "r"((uint32_t)(mbar)) : "memory")

#if TC_PATH
// ---------------- tcgen05 helpers ----------------
__device__ __forceinline__ uint32_t elect_one_pred() {
    uint32_t pred;
    asm volatile(
        "{\n\t.reg .pred p;\n\t"
        "elect.sync _|p, 0xFFFFFFFF;\n\t"
        "selp.b32 %0, 1, 0, p;\n\t}"
        : "=r"(pred));
    return pred;
}

#define TCGEN05_ALLOC(smem_result_addr, nCols) \
    asm volatile("tcgen05.alloc.cta_group::1.sync.aligned.shared::cta.b32 [%0], %1;" \
                 :: "r"((uint32_t)(smem_result_addr)), "r"((uint32_t)(nCols)) : "memory")
#define TCGEN05_DEALLOC(tmem_addr, nCols) \
    asm volatile("tcgen05.dealloc.cta_group::1.sync.aligned.b32 %0, %1;" \
                 :: "r"(tmem_addr), "r"((uint32_t)(nCols)))
#define TCGEN05_RELINQUISH_ALLOC_PERMIT() \
    asm volatile("tcgen05.relinquish_alloc_permit.cta_group::1.sync.aligned;")
#define TCGEN05_WAIT_LD() asm volatile("tcgen05.wait::ld.sync.aligned;" ::: "memory")
#define TCGEN05_FENCE_AFTER()  asm volatile("tcgen05.fence::after_thread_sync;" ::: "memory")
#define TCGEN05_COMMIT(mbar_smem_addr) \
    asm volatile("tcgen05.commit.cta_group::1.mbarrier::arrive::one.shared::cluster.b64 [%0];" \
                 :: "r"((uint32_t)(mbar_smem_addr)) : "memory")
#define FENCE_PROXY_ASYNC_SHARED_CTA() \
    asm volatile("fence.proxy.async.shared::cta;" ::: "memory")
#define MBARRIER_INIT(mbar_smem_addr, count) \
    asm volatile("mbarrier.init.shared.b64 [%0], %1;" \
                 :: "r"((uint32_t)(mbar_smem_addr)), "r"((uint32_t)(count)) : "memory")
#define MBARRIER_EXPECT_TX(mbar_smem_addr, tx_bytes) \
    asm volatile("mbarrier.arrive.expect_tx.shared.b64 _, [%0], %1;" \
                 :: "r"((uint32_t)(mbar_smem_addr)), "r"((uint32_t)(tx_bytes)) : "memory")
#define CP_BULK_G2S(dst_smem, src_gmem, nbytes, mbar_smem_addr) \
    asm volatile("cp.async.bulk.shared::cluster.global.mbarrier::complete_tx::bytes " \
                 "[%0], [%1], %2, [%3];" \
                 :: "r"((uint32_t)(dst_smem)), "l"(src_gmem), "r"((uint32_t)(nbytes)), \
                    "r"((uint32_t)(mbar_smem_addr)) : "memory")
#define MBARRIER_WAIT_PARITY(mbar_smem_addr, phase_parity) do { \
    uint32_t _mbar = (uint32_t)(mbar_smem_addr); \
    uint32_t _parity = (uint32_t)(phase_parity); \
    uint32_t _done; \
    asm volatile( \
        "{\n\t.reg .pred p;\n\t" \
        "mbarrier.try_wait.parity.acquire.cta.shared::cta.b64 p, [%1], %2;\n\t" \
        "selp.b32 %0, 1, 0, p;\n\t}" \
        : "=r"(_done) : "r"(_mbar), "r"(_parity) : "memory"); \
    if (!_done) { \
        asm volatile( \
            "{\n\t.reg .pred P1;\n\t" \
            "WAIT_LOOP_%=:\n\t" \
            "mbarrier.try_wait.parity.acquire.cta.shared::cta.b64 P1, [%0], %1, 0x989680;\n\t" \
            "@P1 bra.uni WAIT_DONE_%=;\n\t" \
            "bra.uni WAIT_LOOP_%=;\n\t" \
            "WAIT_DONE_%=:\n\t}" \
            :: "r"(_mbar), "r"(_parity) : "memory"); \
    } \
} while(0)

// SS-mode f16 MMA: both A and B as SMEM descriptors.
#define TCGEN05_MMA_F16_SS(d_tmem, a_desc, b_desc, idesc, enable_d) do { \
    uint32_t _enable = (enable_d) ? 1 : 0; \
    uint32_t _zero = 0; \
    asm volatile( \
        "{\n\t.reg .pred p;\n\t" \
        "setp.ne.u32 p, %6, 0;\n\t" \
        "tcgen05.mma.cta_group::1.kind::f16 [%0], %1, %2, %3, " \
        "{%4, %4, %4, %4}, p;\n\t}" \
        :: "r"(d_tmem), "l"(a_desc), "l"(b_desc), "r"(idesc), \
           "r"(_zero), "r"(_zero), "r"(_enable) \
        : "memory"); \
} while(0)

#define TCGEN05_LD_32X32B_X32(r, tmem_addr) \
    asm volatile( \
        "tcgen05.ld.sync.aligned.32x32b.x32.b32 " \
        "{%0, %1, %2, %3, %4, %5, %6, %7, " \
        " %8, %9, %10, %11, %12, %13, %14, %15, " \
        " %16, %17, %18, %19, %20, %21, %22, %23, " \
        " %24, %25, %26, %27, %28, %29, %30, %31}, [%32];" \
        : "=r"((r)[0]),  "=r"((r)[1]),  "=r"((r)[2]),  "=r"((r)[3]), \
          "=r"((r)[4]),  "=r"((r)[5]),  "=r"((r)[6]),  "=r"((r)[7]), \
          "=r"((r)[8]),  "=r"((r)[9]),  "=r"((r)[10]), "=r"((r)[11]), \
          "=r"((r)[12]), "=r"((r)[13]), "=r"((r)[14]), "=r"((r)[15]), \
          "=r"((r)[16]), "=r"((r)[17]), "=r"((r)[18]), "=r"((r)[19]), \
          "=r"((r)[20]), "=r"((r)[21]), "=r"((r)[22]), "=r"((r)[23]), \
          "=r"((r)[24]), "=r"((r)[25]), "=r"((r)[26]), "=r"((r)[27]), \
          "=r"((r)[28]), "=r"((r)[29]), "=r"((r)[30]), "=r"((r)[31]) \
        : "r"(tmem_addr))

static constexpr uint64_t SMEM_DESC_BASE_SW128 =
    (uint64_t(2) << 61) | (uint64_t(1) << 46) | (uint64_t(64) << 32) | (uint64_t(1) << 16);
#define MAKE_SMEM_DESC(base_addr) \
    (SMEM_DESC_BASE_SW128 | ((uint64_t)((base_addr) >> 4) & 0x3FFF))

// kind::f16, f16 inputs, f32 acc, M=128 (8<<24), N=128 (16<<17)
#define MMA_IDESC_F16 0x8200010u

// SMEM layout (TC): [0] tmem ptr,
// full0 mbar @16,24  (half-tile rows 0..127, count 256, cp.async-armed),
// full1 mbar @32,40  (whole tile,             count 256, cp.async-armed),
// empty mbar @48,56 (commit), W mbars @64,72, bias @128..640,
// A stages @1024 (2 x 64KB), W stages @132096 (2 x 32KB). Total 197632.
// A stage: [slice(c>>3)][row 0..255][chunk]; slice stride 32KB; M-block1 at +16KB.
#define MB_FULL0(s) (16u + (uint32_t)(s) * 8u)
#define MB_FULL1(s) (32u + (uint32_t)(s) * 8u)
#define MB_EMPTY(s) (48u + (uint32_t)(s) * 8u)
#define MB_WMB(s)   (64u + (uint32_t)(s) * 8u)
#define BIAS_OFF 128
#define A_OFF(s) (1024u + (uint32_t)(s) * 65536u)
#define W_OFF(s) (132096u + (uint32_t)(s) * 32768u)

__global__ void __launch_bounds__(NTHREADS, 1)
k_main(const float* __restrict__ bias, float* __restrict__ out) {
    extern __shared__ char smem[];
    uint32_t sb = smem_to_u32(smem);
    int tid = threadIdx.x;
    int wid = tid >> 5;
    int lid = tid & 31;
    int o0 = blockIdx.x * 256;

    if (wid == 8) TCGEN05_ALLOC(sb + 0, 256);
    if (tid == 0) {
        MBARRIER_INIT(sb + MB_FULL0(0), 256);
        MBARRIER_INIT(sb + MB_FULL0(1), 256);
        MBARRIER_INIT(sb + MB_FULL1(0), 256);
        MBARRIER_INIT(sb + MB_FULL1(1), 256);
        MBARRIER_INIT(sb + MB_EMPTY(0), 1);
        MBARRIER_INIT(sb + MB_EMPTY(1), 1);
        MBARRIER_INIT(sb + MB_WMB(0), 1);
        MBARRIER_INIT(sb + MB_WMB(1), 1);
    }
    if (tid < 128) ((float*)(smem + BIAS_OFF))[tid] = __ldg(&bias[tid]);
    __syncthreads();
    uint32_t tmem;
    asm volatile("ld.shared.b32 %0, [%1];" : "=r"(tmem) : "r"(sb));
    if (wid == 8) TCGEN05_RELINQUISH_ALLOC_PERMIT();

    if (tid < 256) {
        // ------- producers: 8 warps, fire-and-forget cp.async A fills -------
        // Thread covers chunk c of rows row0+16j; j<8 -> rows 0..127 (half 0).
        const int c = tid & 15;
        const int row0 = tid >> 4;
        const uint4* fbase = (const uint4*)g_f16 + c;
        uint32_t aswz;
        {
            uint32_t off = ((uint32_t)(c >> 3) << 15)      // 32KB K-slice
                         + (uint32_t)row0 * 128u
                         + (uint32_t)((c & 7) << 4);
            off ^= (off >> 3) & 0x70u;                     // SW128 swizzle
            aswz = off;
        }
        // prologue: prefetch nbr(k=0)
        int nbR[16];
        {
            const int* nbk = g_nbr + 0 * NV + o0 + row0;
            #pragma unroll
            for (int j = 0; j < 16; ++j) nbR[j] = __ldg(nbk + 16 * j);
        }
        for (int k = 0; k < KK; ++k) {
            int s = k & 1, n = k >> 1;
            if (k >= 2) MBARRIER_WAIT_PARITY(sb + MB_EMPTY(s), (n - 1) & 1);
            uint32_t As = sb + A_OFF(s) + aswz;
            // half 0 (rows 0..127) -> full0
            #pragma unroll
            for (int j = 0; j < 8; ++j)
                CP_ASYNC_CA16(As + (uint32_t)j * 2048u, fbase + (size_t)nbR[j] * 16);
            CP_ASYNC_MBAR_ARRIVE_NOINC(sb + MB_FULL0(s));
            // half 1 (rows 128..255) -> full1 (tracks all 16)
            #pragma unroll
            for (int j = 8; j < 16; ++j)
                CP_ASYNC_CA16(As + (uint32_t)j * 2048u, fbase + (size_t)nbR[j] * 16);
            CP_ASYNC_MBAR_ARRIVE_NOINC(sb + MB_FULL1(s));
            // prefetch nbr(k+1) for next iteration (off the critical path)
            if (k + 1 < KK) {
                const int* nbk = g_nbr + (k + 1) * NV + o0 + row0;
                #pragma unroll
                for (int j = 0; j < 16; ++j) nbR[j] = __ldg(nbk + 16 * j);
            }
        }
        // wait for all MMAs: stage0 14 commits (parity 1), stage1 13 (parity 0)
        MBARRIER_WAIT_PARITY(sb + MB_EMPTY(0), 1);
        MBARRIER_WAIT_PARITY(sb + MB_EMPTY(1), 0);
        TCGEN05_FENCE_AFTER();
        // ---------------- epilogue: 256 rows, 2 D blocks ----------------
        {
            int blk = wid >> 2;
            int row = blk * 128 + (wid & 3) * 32 + lid;
            uint32_t cbase = (uint32_t)(blk * 128);
            float* orow = out + (size_t)(o0 + row) * CH;
            const float* bsm = (const float*)(smem + BIAS_OFF);
            #pragma unroll
            for (int b = 0; b < 128; b += 32) {
                uint32_t d[32];
                TCGEN05_LD_32X32B_X32(d, tmem + cbase + (uint32_t)b);
                TCGEN05_WAIT_LD();
                #pragma unroll
                for (int cc = 0; cc < 32; cc += 4) {
                    float4 v;
                    v.x = __uint_as_float(d[cc + 0]) + bsm[b + cc + 0];
                    v.y = __uint_as_float(d[cc + 1]) + bsm[b + cc + 1];
                    v.z = __uint_as_float(d[cc + 2]) + bsm[b + cc + 2];
                    v.w = __uint_as_float(d[cc + 3]) + bsm[b + cc + 3];
                    *(float4*)(orow + b + cc) = v;
                }
            }
        }
    } else {
        // ---------------- leader warp: W prefetch + MMA issue ----------------
        uint32_t lead = elect_one_pred();
        for (int k = 0; k < KK; ++k) {
            int s = k & 1, n = k >> 1;
            if (k >= 2) MBARRIER_WAIT_PARITY(sb + MB_EMPTY(s), (n - 1) & 1);
            if (lead) {
                MBARRIER_EXPECT_TX(sb + MB_WMB(s), 32768);
                CP_BULK_G2S(sb + W_OFF(s), (const char*)g_w16 + (size_t)k * 32768,
                            32768, sb + MB_WMB(s));
            }
            uint64_t ad = MAKE_SMEM_DESC(sb + A_OFF(s));
            uint64_t bd = MAKE_SMEM_DESC(sb + W_OFF(s));
            // half-tile 0: start MMAs as soon as rows 0..127 + W land
            MBARRIER_WAIT_PARITY(sb + MB_FULL0(s), n & 1);
            MBARRIER_WAIT_PARITY(sb + MB_WMB(s), n & 1);
            FENCE_PROXY_ASYNC_SHARED_CTA();
            TCGEN05_FENCE_AFTER();
            if (lead) {
                #pragma unroll
                for (int ks = 0; ks < 8; ++ks) {
                    uint64_t aoff = (ks < 4) ? (uint64_t)(2 * ks)
                                             : (uint64_t)(2048 + 2 * (ks - 4));
                    uint64_t boff = (ks < 4) ? (uint64_t)(2 * ks)
                                             : (uint64_t)(1024 + 2 * (ks - 4));
                    TCGEN05_MMA_F16_SS(tmem, ad + aoff, bd + boff, MMA_IDESC_F16,
                                       !(k == 0 && ks == 0));
                }
            }
            // half-tile 1 (rows 128..255 -> M-block1 at +16KB = 1024 units)
            MBARRIER_WAIT_PARITY(sb + MB_FULL1(s), n & 1);
            FENCE_PROXY_ASYNC_SHARED_CTA();
            TCGEN05_FENCE_AFTER();
            if (lead) {
                #pragma unroll
                for (int ks = 0; ks < 8; ++ks) {
                    uint64_t aoff = (uint64_t)1024
                                  + ((ks < 4) ? (uint64_t)(2 * ks)
                                              : (uint64_t)(2048 + 2 * (ks - 4)));
                    uint64_t boff = (ks < 4) ? (uint64_t)(2 * ks)
                                             : (uint64_t)(1024 + 2 * (ks - 4));
                    TCGEN05_MMA_F16_SS(tmem + 128u, ad + aoff, bd + boff, MMA_IDESC_F16,
                                       !(k == 0 && ks == 0));
                }
                TCGEN05_COMMIT(sb + MB_EMPTY(s));
            }
        }
    }
    __syncthreads();
    if (wid == 8) TCGEN05_DEALLOC(tmem, 256);
}

#else  // ---------------- mma.sync fallback path (M=256 via two halves) --------
#define A_FB(w)  ((w) * 4096)
#define W_FB     32768
#define BIAS_FB  65536

__device__ __forceinline__ void mma16816(float* c, uint32_t a0, uint32_t a1,
                                         uint32_t a2, uint32_t a3,
                                         uint32_t b0, uint32_t b1) {
    asm volatile(
        "mma.sync.aligned.m16n8k16.row.col.f32.f16.f16.f32 "
        "{%0,%1,%2,%3}, {%4,%5,%6,%7}, {%8,%9}, {%0,%1,%2,%3};"
        : "+f"(c[0]), "+f"(c[1]), "+f"(c[2]), "+f"(c[3])
        : "r"(a0), "r"(a1), "r"(a2), "r"(a3), "r"(b0), "r"(b1));
}

__global__ void __launch_bounds__(NTHREADS)
k_main(const float* __restrict__ bias, float* __restrict__ out) {
    extern __shared__ char smem[];
    uint32_t sb = smem_to_u32(smem);
    int tid = threadIdx.x;
    int wid = tid >> 5;
    int lane = tid & 31;

    if (tid < 128) ((float*)(smem + BIAS_FB))[tid] = __ldg(&bias[tid]);

    int m = lane >> 3, rl = lane & 7;
    int lrow = rl + ((m & 1) << 3);

    for (int half = 0; half < 2; ++half) {
        int o0 = blockIdx.x * 256 + half * 128;
        float acc[16][4] = {};
        for (int k = 0; k < KK; ++k) {
            __syncthreads();
            if (tid < 256) {
                int nbl = (lane < 16) ? __ldg(&g_nbr[k * NV + o0 + wid * 16 + lane]) : 0;
                char* ab = smem + A_FB(wid);
                #pragma unroll
                for (int i = 0; i < 8; ++i) {
                    int row = i * 2 + (lane >> 4);
                    int rn = __shfl_sync(0xffffffffu, nbl, row);
                    uint4 v = __ldg((const uint4*)(g_f16 + (size_t)rn * CH) + (lane & 15));
                    int c = lane & 15;
                    *(uint4*)(ab + row * 256 + ((c ^ (row & 7)) << 4)) = v;
                }
                const uint4* ws = (const uint4*)((const char*)g_w16 + (size_t)k * 32768)
                                  + wid * 256 + lane;
                uint4* wd = (uint4*)(smem + W_FB) + wid * 256 + lane;
                #pragma unroll
                for (int i = 0; i < 8; ++i) wd[i * 32] = __ldg(ws + i * 32);
            }
            __syncthreads();
            if (tid < 256) {
                uint32_t ab32 = sb + A_FB(wid);
                uint32_t wb32 = sb + W_FB;
                uint32_t arow = ab32 + (uint32_t)lrow * 256u;
                #pragma unroll
                for (int kt = 0; kt < 8; ++kt) {
                    int chunk = kt * 2 + (m >> 1);
                    uint32_t aaddr = arow + (uint32_t)((chunk ^ (lrow & 7)) << 4);
                    uint32_t a0, a1, a2, a3;
                    asm volatile(
                        "ldmatrix.sync.aligned.m8n8.x4.shared.b16 {%0,%1,%2,%3}, [%4];"
                        : "=r"(a0), "=r"(a1), "=r"(a2), "=r"(a3) : "r"(aaddr));
                    #pragma unroll
                    for (int nt = 0; nt < 16; ++nt) {
                        uint32_t baddr = wb32 + (uint32_t)((((kt << 4) + nt) << 8) + (lane << 3));
                        uint32_t b0, b1;
                        asm volatile("ld.shared.v2.b32 {%0,%1}, [%2];"
                                     : "=r"(b0), "=r"(b1) : "r"(baddr));
                        mma16816(acc[nt], a0, a1, a2, a3, b0, b1);
                    }
                }
            }
        }
        if (tid < 256) {
            int gid = lane >> 2, tig = lane & 3;
            const float* bsm = (const float*)(smem + BIAS_FB);
            int o0h = blockIdx.x * 256 + half * 128;
            size_t r0 = (size_t)(o0h + wid * 16 + gid);
            #pragma unroll
            for (int nt = 0; nt < 16; ++nt) {
                int col = nt * 8 + tig * 2;
                float2 bv = *(const float2*)(bsm + col);
                float2 v0 = make_float2(acc[nt][0] + bv.x, acc[nt][1] + bv.y);
                float2 v1 = make_float2(acc[nt][2] + bv.x, acc[nt][3] + bv.y);
                *(float2*)(out + r0 * CH + col) = v0;
                *(float2*)(out + (r0 + 8) * CH + col) = v1;
            }
        }
        __syncthreads();
    }
}
#endif  // TC_PATH

// ---------------- fused prep kernel ----------------
// blocks [0, 6912): rulebook scatter (g_nbr = in_idx+1)
// blocks [6912, 15104): feature fp16 convert, float4-vectorized (+1 row shift)
// blocks [15104, 16832): weight pack (per-path layout)
#define PREP_BLOCKS 16832

__global__ void k_prep(const float* __restrict__ f, const float* __restrict__ w,
                       const int* __restrict__ in_idx, const int* __restrict__ out_idx) {
    int b = blockIdx.x;
    if (b < 6912) {
        int i = b * 256 + threadIdx.x;            // [0, KK*NV)
        int o = out_idx[i];
        if (o < NV) g_nbr[(i / NV) * NV + o] = in_idx[i] + 1;
    } else if (b < 15104) {
        int i = (b - 6912) * 256 + threadIdx.x;   // [0, NV*32) float4 words
        float4 v = ((const float4*)f)[i];
        __half2 h0, h1;
        h0.x = __float2half_rn(v.x); h0.y = __float2half_rn(v.y);
        h1.x = __float2half_rn(v.z); h1.y = __float2half_rn(v.w);
        uint2 pk;
        pk.x = *(uint32_t*)&h0; pk.y = *(uint32_t*)&h1;
        ((uint2*)g_f16)[i + 32] = pk;             // +1 row shift (row 0 stays zero)
    } else {
        int i = (b - 15104) * 256 + threadIdx.x;
#if TC_PATH
        // W[k][cin][cout] -> B[k][cout(row)][cin(col)] fp16, SW128 blocked image
        if (i >= KK * CH * CH) return;
        int k = i >> 14;
        int r = (i >> 7) & 127;   // c_out (N row)
        int c = i & 127;          // c_in  (K col)
        float v = w[(k << 14) + (c << 7) + r];
        uint32_t atom = (uint32_t)(r >> 3) + ((uint32_t)(c >> 6) << 4);
        uint32_t off = atom * 1024u + (uint32_t)(r & 7) * 128u + (uint32_t)(c & 63) * 2u;
        off ^= (off >> 3) & 0x70u;
        g_w16[((uint32_t)k * 32768u + off) >> 1] = __float2half_rn(v);
#else
        // mma.sync B-fragment-ready image: [k][ktile(8)][ntile(16)][lane(32)][reg(2)] u32
        if (i >= KK * 8 * 16 * 32 * 2) return;
        int reg   = i & 1;
        int lane  = (i >> 1) & 31;
        int nt    = (i >> 6) & 15;
        int ktile = (i >> 10) & 7;
        int k     = i >> 13;
        int tig = lane & 3, gid = lane >> 2;
        int n    = nt * 8 + gid;
        int cin0 = ktile * 16 + tig * 2 + reg * 8;
        float w0 = w[(k * CH + cin0) * CH + n];
        float w1 = w[(k * CH + cin0 + 1) * CH + n];
        __half2 h;
        h.x = __float2half_rn(w0);
        h.y = __float2half_rn(w1);
        ((__half2*)g_w16)[i] = h;
#endif
    }
}

// ---------------- launch ----------------
extern "C" void kernel_launch(void* const* d_in, const int* in_sizes, int n_in,
                              void* d_out, int out_size) {
    const float* features = (const float*)d_in[0];
    const float* weight   = (const float*)d_in[1];
    const float* bias     = (const float*)d_in[2];
    const int*   in_idx   = (const int*)d_in[3];
    const int*   out_idx  = (const int*)d_in[4];
    float*       out      = (float*)d_out;

    cudaFuncSetAttribute(k_main, cudaFuncAttributeMaxDynamicSharedMemorySize, SMEM_BYTES);

    k_prep<<<PREP_BLOCKS, 256>>>(features, weight, in_idx, out_idx);
    k_main<<<NV / 256, NTHREADS, SMEM_BYTES>>>(bias, out);
}

// round 13
// speedup vs baseline: 5.7387x; 1.1971x over previous
#include <cuda_runtime.h>
#include <cuda_fp16.h>
#include <cstdint>

#define NV 65536
#define KK 27
#define CH 128

// tcgen05 fast path only in the arch-specific sm_103a pass (plain compute_103
// rejects tcgen05 in ptxas).
#if defined(__CUDA_ARCH__) && (defined(__CUDA_ARCH_FEAT_SM103_ALL) || \
    (defined(__CUDA_ARCH_SPECIFIC__) && (__CUDA_ARCH_SPECIFIC__ == 1030)))
#define TC_PATH 1
#else
#define TC_PATH 0
#endif

// ---------------- scratch (static __device__, no allocs) ----------------
// g_nbr holds (input_row + 1); 0 means "no neighbor" -> reads g_f16 row 0,
// which is statically zero and never written (k_prep writes rows 1..NV).
__device__ __align__(256) int    g_nbr[KK * NV];            // 7 MB, zero-init
__device__ __align__(256) __half g_f16[(NV + 1) * CH];      // row 0 = zeros
__device__ __align__(256) __half g_w16[KK * CH * CH];       // 864 KB, per-path layout

// ---------------- common helpers ----------------
__device__ __forceinline__ uint32_t smem_to_u32(const void* smem_ptr) {
    uint32_t addr;
    asm("{ .reg .u64 tmp; cvta.to.shared.u64 tmp, %1; cvt.u32.u64 %0, tmp; }"
        : "=r"(addr) : "l"(smem_ptr));
    return addr;
}

// TC path: hdr + 4 A tiles (4x32KB) + 2 W stages (2x32KB) = 197632 -> 1 CTA/SM.
#define SMEM_BYTES 197632
#define NTHREADS 288

// cp.async (L1-caching variant) + mbarrier-tracked completion (sm_80+)
#define CP_ASYNC_CA16(dst, src) \
    asm volatile("cp.async.ca.shared.global [%0], [%1], 16;" \
                 :: "r"((uint32_t)(dst)), "l"(src) : "memory")
#define CP_ASYNC_MBAR_ARRIVE_NOINC(mbar) \
    asm volatile("cp.async.mbarrier.arrive.noinc.shared.b64 [%0];" \
                 :: "r"((uint32_t)(mbar)) : "memory")

#if TC_PATH
// ---------------- tcgen05 helpers ----------------
__device__ __forceinline__ uint32_t elect_one_pred() {
    uint32_t pred;
    asm volatile(
        "{\n\t.reg .pred p;\n\t"
        "elect.sync _|p, 0xFFFFFFFF;\n\t"
        "selp.b32 %0, 1, 0, p;\n\t}"
        : "=r"(pred));
    return pred;
}

#define TCGEN05_ALLOC(smem_result_addr, nCols) \
    asm volatile("tcgen05.alloc.cta_group::1.sync.aligned.shared::cta.b32 [%0], %1;" \
                 :: "r"((uint32_t)(smem_result_addr)), "r"((uint32_t)(nCols)) : "memory")
#define TCGEN05_DEALLOC(tmem_addr, nCols) \
    asm volatile("tcgen05.dealloc.cta_group::1.sync.aligned.b32 %0, %1;" \
                 :: "r"(tmem_addr), "r"((uint32_t)(nCols)))
#define TCGEN05_RELINQUISH_ALLOC_PERMIT() \
    asm volatile("tcgen05.relinquish_alloc_permit.cta_group::1.sync.aligned;")
#define TCGEN05_WAIT_LD() asm volatile("tcgen05.wait::ld.sync.aligned;" ::: "memory")
#define TCGEN05_FENCE_AFTER()  asm volatile("tcgen05.fence::after_thread_sync;" ::: "memory")
#define TCGEN05_COMMIT(mbar_smem_addr) \
    asm volatile("tcgen05.commit.cta_group::1.mbarrier::arrive::one.shared::cluster.b64 [%0];" \
                 :: "r"((uint32_t)(mbar_smem_addr)) : "memory")
#define FENCE_PROXY_ASYNC_SHARED_CTA() \
    asm volatile("fence.proxy.async.shared::cta;" ::: "memory")
#define MBARRIER_INIT(mbar_smem_addr, count) \
    asm volatile("mbarrier.init.shared.b64 [%0], %1;" \
                 :: "r"((uint32_t)(mbar_smem_addr)), "r"((uint32_t)(count)) : "memory")
#define MBARRIER_EXPECT_TX(mbar_smem_addr, tx_bytes) \
    asm volatile("mbarrier.arrive.expect_tx.shared.b64 _, [%0], %1;" \
                 :: "r"((uint32_t)(mbar_smem_addr)), "r"((uint32_t)(tx_bytes)) : "memory")
#define CP_BULK_G2S(dst_smem, src_gmem, nbytes, mbar_smem_addr) \
    asm volatile("cp.async.bulk.shared::cluster.global.mbarrier::complete_tx::bytes " \
                 "[%0], [%1], %2, [%3];" \
                 :: "r"((uint32_t)(dst_smem)), "l"(src_gmem), "r"((uint32_t)(nbytes)), \
                    "r"((uint32_t)(mbar_smem_addr)) : "memory")
#define MBARRIER_WAIT_PARITY(mbar_smem_addr, phase_parity) do { \
    uint32_t _mbar = (uint32_t)(mbar_smem_addr); \
    uint32_t _parity = (uint32_t)(phase_parity); \
    uint32_t _done; \
    asm volatile( \
        "{\n\t.reg .pred p;\n\t" \
        "mbarrier.try_wait.parity.acquire.cta.shared::cta.b64 p, [%1], %2;\n\t" \
        "selp.b32 %0, 1, 0, p;\n\t}" \
        : "=r"(_done) : "r"(_mbar), "r"(_parity) : "memory"); \
    if (!_done) { \
        asm volatile( \
            "{\n\t.reg .pred P1;\n\t" \
            "WAIT_LOOP_%=:\n\t" \
            "mbarrier.try_wait.parity.acquire.cta.shared::cta.b64 P1, [%0], %1, 0x989680;\n\t" \
            "@P1 bra.uni WAIT_DONE_%=;\n\t" \
            "bra.uni WAIT_LOOP_%=;\n\t" \
            "WAIT_DONE_%=:\n\t}" \
            :: "r"(_mbar), "r"(_parity) : "memory"); \
    } \
} while(0)

// SS-mode f16 MMA: both A and B as SMEM descriptors.
#define TCGEN05_MMA_F16_SS(d_tmem, a_desc, b_desc, idesc, enable_d) do { \
    uint32_t _enable = (enable_d) ? 1 : 0; \
    uint32_t _zero = 0; \
    asm volatile( \
        "{\n\t.reg .pred p;\n\t" \
        "setp.ne.u32 p, %6, 0;\n\t" \
        "tcgen05.mma.cta_group::1.kind::f16 [%0], %1, %2, %3, " \
        "{%4, %4, %4, %4}, p;\n\t}" \
        :: "r"(d_tmem), "l"(a_desc), "l"(b_desc), "r"(idesc), \
           "r"(_zero), "r"(_zero), "r"(_enable) \
        : "memory"); \
} while(0)

#define TCGEN05_LD_32X32B_X32(r, tmem_addr) \
    asm volatile( \
        "tcgen05.ld.sync.aligned.32x32b.x32.b32 " \
        "{%0, %1, %2, %3, %4, %5, %6, %7, " \
        " %8, %9, %10, %11, %12, %13, %14, %15, " \
        " %16, %17, %18, %19, %20, %21, %22, %23, " \
        " %24, %25, %26, %27, %28, %29, %30, %31}, [%32];" \
        : "=r"((r)[0]),  "=r"((r)[1]),  "=r"((r)[2]),  "=r"((r)[3]), \
          "=r"((r)[4]),  "=r"((r)[5]),  "=r"((r)[6]),  "=r"((r)[7]), \
          "=r"((r)[8]),  "=r"((r)[9]),  "=r"((r)[10]), "=r"((r)[11]), \
          "=r"((r)[12]), "=r"((r)[13]), "=r"((r)[14]), "=r"((r)[15]), \
          "=r"((r)[16]), "=r"((r)[17]), "=r"((r)[18]), "=r"((r)[19]), \
          "=r"((r)[20]), "=r"((r)[21]), "=r"((r)[22]), "=r"((r)[23]), \
          "=r"((r)[24]), "=r"((r)[25]), "=r"((r)[26]), "=r"((r)[27]), \
          "=r"((r)[28]), "=r"((r)[29]), "=r"((r)[30]), "=r"((r)[31]) \
        : "r"(tmem_addr))

static constexpr uint64_t SMEM_DESC_BASE_SW128 =
    (uint64_t(2) << 61) | (uint64_t(1) << 46) | (uint64_t(64) << 32) | (uint64_t(1) << 16);
#define MAKE_SMEM_DESC(base_addr) \
    (SMEM_DESC_BASE_SW128 | ((uint64_t)((base_addr) >> 4) & 0x3FFF))

// kind::f16, f16 inputs, f32 acc, M=128 (8<<24), N=128 (16<<17)
#define MMA_IDESC_F16 0x8200010u

// SMEM layout (TC): [0] tmem ptr,
// full[t]  @16+8t (count 256, cp.async-armed), t = 0..3
// empty[t] @48+8t (tcgen05 commit target)
// W mbars @80,88, bias @128..640,
// A tiles @1024 (4 x 32KB), W stages @132096 (2 x 32KB). Total 197632.
// A tile: 2 K-slices of 16KB (cols 0..63 / 64..127), rows 0..127, SW128 atoms.
// TMEM: tile t accumulator D at cols t*128 (M=128 lanes x N=128 f32).
#define MB_FULL(t)  (16u + (uint32_t)(t) * 8u)
#define MB_EMPTY(t) (48u + (uint32_t)(t) * 8u)
#define MB_WMB(s)   (80u + (uint32_t)(s) * 8u)
#define BIAS_OFF 128
#define A_OFF(t) (1024u + (uint32_t)(t) * 32768u)
#define W_OFF(s) (132096u + (uint32_t)(s) * 32768u)

__global__ void __launch_bounds__(NTHREADS, 1)
k_main(const float* __restrict__ bias, float* __restrict__ out) {
    extern __shared__ char smem[];
    uint32_t sb = smem_to_u32(smem);
    int tid = threadIdx.x;
    int wid = tid >> 5;
    int lid = tid & 31;
    int o0 = blockIdx.x * 512;

    if (wid == 8) TCGEN05_ALLOC(sb + 0, 512);
    if (tid == 0) {
        #pragma unroll
        for (int t = 0; t < 4; ++t) {
            MBARRIER_INIT(sb + MB_FULL(t), 256);
            MBARRIER_INIT(sb + MB_EMPTY(t), 1);
        }
        MBARRIER_INIT(sb + MB_WMB(0), 1);
        MBARRIER_INIT(sb + MB_WMB(1), 1);
    }
    if (tid < 128) ((float*)(smem + BIAS_OFF))[tid] = __ldg(&bias[tid]);
    __syncthreads();
    uint32_t tmem;
    asm volatile("ld.shared.b32 %0, [%1];" : "=r"(tmem) : "r"(sb));
    if (wid == 8) TCGEN05_RELINQUISH_ALLOC_PERMIT();

    if (tid < 256) {
        // ------- producers: 8 warps, fire-and-forget cp.async fills, 4 tiles ----
        const int c = tid & 15;              // 16B chunk within row
        const int row0 = tid >> 4;           // base row in tile (0..15), step 16
        const uint4* fbase = (const uint4*)g_f16 + c;
        uint32_t aswz;
        {
            uint32_t off = ((uint32_t)(c >> 3) << 14)      // 16KB K-slice
                         + (uint32_t)row0 * 128u
                         + (uint32_t)((c & 7) << 4);
            off ^= (off >> 3) & 0x70u;                     // SW128 swizzle
            aswz = off;
        }
        // prologue: prefetch nbr(k=0) for all 4 tiles
        int nbR[32];
        {
            const int* nbk = g_nbr + 0 * NV + o0 + row0;
            #pragma unroll
            for (int t = 0; t < 4; ++t)
                #pragma unroll
                for (int j = 0; j < 8; ++j)
                    nbR[t * 8 + j] = __ldg(nbk + t * 128 + 16 * j);
        }
        for (int k = 0; k < KK; ++k) {
            #pragma unroll
            for (int t = 0; t < 4; ++t) {
                if (k >= 1) MBARRIER_WAIT_PARITY(sb + MB_EMPTY(t), (k - 1) & 1);
                uint32_t As = sb + A_OFF(t) + aswz;
                #pragma unroll
                for (int j = 0; j < 8; ++j)
                    CP_ASYNC_CA16(As + (uint32_t)j * 2048u,
                                  fbase + (size_t)nbR[t * 8 + j] * 16);
                CP_ASYNC_MBAR_ARRIVE_NOINC(sb + MB_FULL(t));
            }
            // prefetch nbr(k+1) off the critical path
            if (k + 1 < KK) {
                const int* nbk = g_nbr + (k + 1) * NV + o0 + row0;
                #pragma unroll
                for (int t = 0; t < 4; ++t)
                    #pragma unroll
                    for (int j = 0; j < 8; ++j)
                        nbR[t * 8 + j] = __ldg(nbk + t * 128 + 16 * j);
            }
        }
        // drain: 27 commits per tile -> last completed phase 26 (parity 0)
        #pragma unroll
        for (int t = 0; t < 4; ++t)
            MBARRIER_WAIT_PARITY(sb + MB_EMPTY(t), 0);
        TCGEN05_FENCE_AFTER();
        // ------- epilogue: 512 rows, tiles 0..3, two passes of 8 warps -------
        const float* bsm = (const float*)(smem + BIAS_OFF);
        #pragma unroll
        for (int pass = 0; pass < 2; ++pass) {
            int t = pass * 2 + (wid >> 2);
            int row = t * 128 + (wid & 3) * 32 + lid;
            uint32_t cbase = (uint32_t)(t * 128);
            float* orow = out + (size_t)(o0 + row) * CH;
            #pragma unroll
            for (int b = 0; b < 128; b += 32) {
                uint32_t d[32];
                TCGEN05_LD_32X32B_X32(d, tmem + cbase + (uint32_t)b);
                TCGEN05_WAIT_LD();
                #pragma unroll
                for (int cc = 0; cc < 32; cc += 4) {
                    float4 v;
                    v.x = __uint_as_float(d[cc + 0]) + bsm[b + cc + 0];
                    v.y = __uint_as_float(d[cc + 1]) + bsm[b + cc + 1];
                    v.z = __uint_as_float(d[cc + 2]) + bsm[b + cc + 2];
                    v.w = __uint_as_float(d[cc + 3]) + bsm[b + cc + 3];
                    *(float4*)(orow + b + cc) = v;
                }
            }
        }
    } else {
        // ---------------- leader warp: W prefetch + round-robin MMA ----------
        uint32_t lead = elect_one_pred();
        // prologue: W(0) and W(1) into their stages
        if (lead) {
            MBARRIER_EXPECT_TX(sb + MB_WMB(0), 32768);
            CP_BULK_G2S(sb + W_OFF(0), (const char*)g_w16, 32768, sb + MB_WMB(0));
            MBARRIER_EXPECT_TX(sb + MB_WMB(1), 32768);
            CP_BULK_G2S(sb + W_OFF(1), (const char*)g_w16 + 32768, 32768, sb + MB_WMB(1));
        }
        for (int k = 0; k < KK; ++k) {
            int s = k & 1;
            // W(k) ready? WMB(s) phases: k = s, s+2, ... -> wait parity (k>>1)&1
            MBARRIER_WAIT_PARITY(sb + MB_WMB(s), (k >> 1) & 1);
            uint64_t bd = MAKE_SMEM_DESC(sb + W_OFF(s));
            #pragma unroll
            for (int t = 0; t < 4; ++t) {
                MBARRIER_WAIT_PARITY(sb + MB_FULL(t), k & 1);
                FENCE_PROXY_ASYNC_SHARED_CTA();
                TCGEN05_FENCE_AFTER();
                if (lead) {
                    uint64_t ad = MAKE_SMEM_DESC(sb + A_OFF(t));
                    #pragma unroll
                    for (int ks = 0; ks < 8; ++ks) {
                        uint64_t doff = (ks < 4) ? (uint64_t)(2 * ks)
                                                 : (uint64_t)(1024 + 2 * (ks - 4));
                        TCGEN05_MMA_F16_SS(tmem + (uint32_t)(t * 128),
                                           ad + doff, bd + doff, MMA_IDESC_F16,
                                           !(k == 0 && ks == 0));
                    }
                    TCGEN05_COMMIT(sb + MB_EMPTY(t));
                }
            }
            // issue W(k+2) into stage s after this iteration's MMAs complete
            // (tile 3 commit of iteration k covers all stage-s reads of W(k)).
            if (k + 2 < KK) {
                MBARRIER_WAIT_PARITY(sb + MB_EMPTY(3), k & 1);
                if (lead) {
                    MBARRIER_EXPECT_TX(sb + MB_WMB(s), 32768);
                    CP_BULK_G2S(sb + W_OFF(s), (const char*)g_w16 + (size_t)(k + 2) * 32768,
                                32768, sb + MB_WMB(s));
                }
            }
        }
    }
    __syncthreads();
    if (wid == 8) TCGEN05_DEALLOC(tmem, 512);
}

#else  // ---------------- mma.sync fallback path (512 rows via 4 halves) -------
#define A_FB(w)  ((w) * 4096)
#define W_FB     32768
#define BIAS_FB  65536

__device__ __forceinline__ void mma16816(float* c, uint32_t a0, uint32_t a1,
                                         uint32_t a2, uint32_t a3,
                                         uint32_t b0, uint32_t b1) {
    asm volatile(
        "mma.sync.aligned.m16n8k16.row.col.f32.f16.f16.f32 "
        "{%0,%1,%2,%3}, {%4,%5,%6,%7}, {%8,%9}, {%0,%1,%2,%3};"
        : "+f"(c[0]), "+f"(c[1]), "+f"(c[2]), "+f"(c[3])
        : "r"(a0), "r"(a1), "r"(a2), "r"(a3), "r"(b0), "r"(b1));
}

__global__ void __launch_bounds__(NTHREADS)
k_main(const float* __restrict__ bias, float* __restrict__ out) {
    extern __shared__ char smem[];
    uint32_t sb = smem_to_u32(smem);
    int tid = threadIdx.x;
    int wid = tid >> 5;
    int lane = tid & 31;

    if (tid < 128) ((float*)(smem + BIAS_FB))[tid] = __ldg(&bias[tid]);

    int m = lane >> 3, rl = lane & 7;
    int lrow = rl + ((m & 1) << 3);

    for (int half = 0; half < 4; ++half) {
        int o0 = blockIdx.x * 512 + half * 128;
        float acc[16][4] = {};
        for (int k = 0; k < KK; ++k) {
            __syncthreads();
            if (tid < 256) {
                int nbl = (lane < 16) ? __ldg(&g_nbr[k * NV + o0 + wid * 16 + lane]) : 0;
                char* ab = smem + A_FB(wid);
                #pragma unroll
                for (int i = 0; i < 8; ++i) {
                    int row = i * 2 + (lane >> 4);
                    int rn = __shfl_sync(0xffffffffu, nbl, row);
                    uint4 v = __ldg((const uint4*)(g_f16 + (size_t)rn * CH) + (lane & 15));
                    int c = lane & 15;
                    *(uint4*)(ab + row * 256 + ((c ^ (row & 7)) << 4)) = v;
                }
                const uint4* ws = (const uint4*)((const char*)g_w16 + (size_t)k * 32768)
                                  + wid * 256 + lane;
                uint4* wd = (uint4*)(smem + W_FB) + wid * 256 + lane;
                #pragma unroll
                for (int i = 0; i < 8; ++i) wd[i * 32] = __ldg(ws + i * 32);
            }
            __syncthreads();
            if (tid < 256) {
                uint32_t ab32 = sb + A_FB(wid);
                uint32_t wb32 = sb + W_FB;
                uint32_t arow = ab32 + (uint32_t)lrow * 256u;
                #pragma unroll
                for (int kt = 0; kt < 8; ++kt) {
                    int chunk = kt * 2 + (m >> 1);
                    uint32_t aaddr = arow + (uint32_t)((chunk ^ (lrow & 7)) << 4);
                    uint32_t a0, a1, a2, a3;
                    asm volatile(
                        "ldmatrix.sync.aligned.m8n8.x4.shared.b16 {%0,%1,%2,%3}, [%4];"
                        : "=r"(a0), "=r"(a1), "=r"(a2), "=r"(a3) : "r"(aaddr));
                    #pragma unroll
                    for (int nt = 0; nt < 16; ++nt) {
                        uint32_t baddr = wb32 + (uint32_t)((((kt << 4) + nt) << 8) + (lane << 3));
                        uint32_t b0, b1;
                        asm volatile("ld.shared.v2.b32 {%0,%1}, [%2];"
                                     : "=r"(b0), "=r"(b1) : "r"(baddr));
                        mma16816(acc[nt], a0, a1, a2, a3, b0, b1);
                    }
                }
            }
        }
        if (tid < 256) {
            int gid = lane >> 2, tig = lane & 3;
            const float* bsm = (const float*)(smem + BIAS_FB);
            size_t r0 = (size_t)(o0 + wid * 16 + gid);
            #pragma unroll
            for (int nt = 0; nt < 16; ++nt) {
                int col = nt * 8 + tig * 2;
                float2 bv = *(const float2*)(bsm + col);
                float2 v0 = make_float2(acc[nt][0] + bv.x, acc[nt][1] + bv.y);
                float2 v1 = make_float2(acc[nt][2] + bv.x, acc[nt][3] + bv.y);
                *(float2*)(out + r0 * CH + col) = v0;
                *(float2*)(out + (r0 + 8) * CH + col) = v1;
            }
        }
        __syncthreads();
    }
}
#endif  // TC_PATH

// ---------------- fused prep kernel ----------------
// blocks [0, 6912): rulebook scatter (g_nbr = in_idx+1)
// blocks [6912, 15104): feature fp16 convert, float4-vectorized (+1 row shift)
// blocks [15104, 16832): weight pack (per-path layout)
#define PREP_BLOCKS 16832

__global__ void k_prep(const float* __restrict__ f, const float* __restrict__ w,
                       const int* __restrict__ in_idx, const int* __restrict__ out_idx) {
    int b = blockIdx.x;
    if (b < 6912) {
        int i = b * 256 + threadIdx.x;            // [0, KK*NV)
        int o = out_idx[i];
        if (o < NV) g_nbr[(i / NV) * NV + o] = in_idx[i] + 1;
    } else if (b < 15104) {
        int i = (b - 6912) * 256 + threadIdx.x;   // [0, NV*32) float4 words
        float4 v = ((const float4*)f)[i];
        __half2 h0, h1;
        h0.x = __float2half_rn(v.x); h0.y = __float2half_rn(v.y);
        h1.x = __float2half_rn(v.z); h1.y = __float2half_rn(v.w);
        uint2 pk;
        pk.x = *(uint32_t*)&h0; pk.y = *(uint32_t*)&h1;
        ((uint2*)g_f16)[i + 32] = pk;             // +1 row shift (row 0 stays zero)
    } else {
        int i = (b - 15104) * 256 + threadIdx.x;
#if TC_PATH
        // W[k][cin][cout] -> B[k][cout(row)][cin(col)] fp16, SW128 blocked image
        if (i >= KK * CH * CH) return;
        int k = i >> 14;
        int r = (i >> 7) & 127;   // c_out (N row)
        int c = i & 127;          // c_in  (K col)
        float v = w[(k << 14) + (c << 7) + r];
        uint32_t atom = (uint32_t)(r >> 3) + ((uint32_t)(c >> 6) << 4);
        uint32_t off = atom * 1024u + (uint32_t)(r & 7) * 128u + (uint32_t)(c & 63) * 2u;
        off ^= (off >> 3) & 0x70u;
        g_w16[((uint32_t)k * 32768u + off) >> 1] = __float2half_rn(v);
#else
        // mma.sync B-fragment-ready image: [k][ktile(8)][ntile(16)][lane(32)][reg(2)] u32
        if (i >= KK * 8 * 16 * 32 * 2) return;
        int reg   = i & 1;
        int lane  = (i >> 1) & 31;
        int nt    = (i >> 6) & 15;
        int ktile = (i >> 10) & 7;
        int k     = i >> 13;
        int tig = lane & 3, gid = lane >> 2;
        int n    = nt * 8 + gid;
        int cin0 = ktile * 16 + tig * 2 + reg * 8;
        float w0 = w[(k * CH + cin0) * CH + n];
        float w1 = w[(k * CH + cin0 + 1) * CH + n];
        __half2 h;
        h.x = __float2half_rn(w0);
        h.y = __float2half_rn(w1);
        ((__half2*)g_w16)[i] = h;
#endif
    }
}

// ---------------- launch ----------------
extern "C" void kernel_launch(void* const* d_in, const int* in_sizes, int n_in,
                              void* d_out, int out_size) {
    const float* features = (const float*)d_in[0];
    const float* weight   = (const float*)d_in[1];
    const float* bias     = (const float*)d_in[2];
    const int*   in_idx   = (const int*)d_in[3];
    const int*   out_idx  = (const int*)d_in[4];
    float*       out      = (float*)d_out;

    cudaFuncSetAttribute(k_main, cudaFuncAttributeMaxDynamicSharedMemorySize, SMEM_BYTES);

    k_prep<<<PREP_BLOCKS, 256>>>(features, weight, in_idx, out_idx);
    k_main<<<NV / 512, NTHREADS, SMEM_BYTES>>>(bias, out);
}

// round 14
// speedup vs baseline: 5.8807x; 1.0247x over previous
#include <cuda_runtime.h>
#include <cuda_fp16.h>
#include <cstdint>

#define NV 65536
#define KK 27
#define CH 128

// tcgen05 fast path only in the arch-specific sm_103a pass (plain compute_103
// rejects tcgen05 in ptxas).
#if defined(__CUDA_ARCH__) && (defined(__CUDA_ARCH_FEAT_SM103_ALL) || \
    (defined(__CUDA_ARCH_SPECIFIC__) && (__CUDA_ARCH_SPECIFIC__ == 1030)))
#define TC_PATH 1
#else
#define TC_PATH 0
#endif

// ---------------- scratch (static __device__, no allocs) ----------------
// g_nbr holds (input_row + 1); 0 means "no neighbor" -> zero-filled via
// cp.async src-size=0 (row 0 of g_f16 is also kept zero as a fallback).
__device__ __align__(256) int    g_nbr[KK * NV];            // 7 MB, zero-init
__device__ __align__(256) __half g_f16[(NV + 1) * CH];      // row 0 = zeros
__device__ __align__(256) __half g_w16[KK * CH * CH];       // 864 KB, per-path layout

// ---------------- common helpers ----------------
__device__ __forceinline__ uint32_t smem_to_u32(const void* smem_ptr) {
    uint32_t addr;
    asm("{ .reg .u64 tmp; cvta.to.shared.u64 tmp, %1; cvt.u32.u64 %0, tmp; }"
        : "=r"(addr) : "l"(smem_ptr));
    return addr;
}

// TC path: hdr + 4 A tiles (4x32KB) + 2 W stages (2x32KB) = 197632 -> 1 CTA/SM.
#define SMEM_BYTES 197632
#define NTHREADS 288

// cp.async (L1-caching variant) + mbarrier-tracked completion (sm_80+)
// src-size variant: sz < 16 zero-fills the remainder (sz=0 -> pure zero-fill,
// no global read issued).
#define CP_ASYNC_CA16_SZ(dst, src, sz) \
    asm volatile("cp.async.ca.shared.global [%0], [%1], 16, %2;" \
                 :: "r"((uint32_t)(dst)), "l"(src), "r"((uint32_t)(sz)) : "memory")
#define CP_ASYNC_MBAR_ARRIVE_NOINC(mbar) \
    asm volatile("cp.async.mbarrier.arrive.noinc.shared.b64 [%0];" \
                 :: "r"((uint32_t)(mbar)) : "memory")

#if TC_PATH
// ---------------- tcgen05 helpers ----------------
__device__ __forceinline__ uint32_t elect_one_pred() {
    uint32_t pred;
    asm volatile(
        "{\n\t.reg .pred p;\n\t"
        "elect.sync _|p, 0xFFFFFFFF;\n\t"
        "selp.b32 %0, 1, 0, p;\n\t}"
        : "=r"(pred));
    return pred;
}

#define TCGEN05_ALLOC(smem_result_addr, nCols) \
    asm volatile("tcgen05.alloc.cta_group::1.sync.aligned.shared::cta.b32 [%0], %1;" \
                 :: "r"((uint32_t)(smem_result_addr)), "r"((uint32_t)(nCols)) : "memory")
#define TCGEN05_DEALLOC(tmem_addr, nCols) \
    asm volatile("tcgen05.dealloc.cta_group::1.sync.aligned.b32 %0, %1;" \
                 :: "r"(tmem_addr), "r"((uint32_t)(nCols)))
#define TCGEN05_RELINQUISH_ALLOC_PERMIT() \
    asm volatile("tcgen05.relinquish_alloc_permit.cta_group::1.sync.aligned;")
#define TCGEN05_WAIT_LD() asm volatile("tcgen05.wait::ld.sync.aligned;" ::: "memory")
#define TCGEN05_FENCE_AFTER()  asm volatile("tcgen05.fence::after_thread_sync;" ::: "memory")
#define TCGEN05_COMMIT(mbar_smem_addr) \
    asm volatile("tcgen05.commit.cta_group::1.mbarrier::arrive::one.shared::cluster.b64 [%0];" \
                 :: "r"((uint32_t)(mbar_smem_addr)) : "memory")
#define FENCE_PROXY_ASYNC_SHARED_CTA() \
    asm volatile("fence.proxy.async.shared::cta;" ::: "memory")
#define MBARRIER_INIT(mbar_smem_addr, count) \
    asm volatile("mbarrier.init.shared.b64 [%0], %1;" \
                 :: "r"((uint32_t)(mbar_smem_addr)), "r"((uint32_t)(count)) : "memory")
#define MBARRIER_EXPECT_TX(mbar_smem_addr, tx_bytes) \
    asm volatile("mbarrier.arrive.expect_tx.shared.b64 _, [%0], %1;" \
                 :: "r"((uint32_t)(mbar_smem_addr)), "r"((uint32_t)(tx_bytes)) : "memory")
#define CP_BULK_G2S(dst_smem, src_gmem, nbytes, mbar_smem_addr) \
    asm volatile("cp.async.bulk.shared::cluster.global.mbarrier::complete_tx::bytes " \
                 "[%0], [%1], %2, [%3];" \
                 :: "r"((uint32_t)(dst_smem)), "l"(src_gmem), "r"((uint32_t)(nbytes)), \
                    "r"((uint32_t)(mbar_smem_addr)) : "memory")
#define MBARRIER_WAIT_PARITY(mbar_smem_addr, phase_parity) do { \
    uint32_t _mbar = (uint32_t)(mbar_smem_addr); \
    uint32_t _parity = (uint32_t)(phase_parity); \
    uint32_t _done; \
    asm volatile( \
        "{\n\t.reg .pred p;\n\t" \
        "mbarrier.try_wait.parity.acquire.cta.shared::cta.b64 p, [%1], %2;\n\t" \
        "selp.b32 %0, 1, 0, p;\n\t}" \
        : "=r"(_done) : "r"(_mbar), "r"(_parity) : "memory"); \
    if (!_done) { \
        asm volatile( \
            "{\n\t.reg .pred P1;\n\t" \
            "WAIT_LOOP_%=:\n\t" \
            "mbarrier.try_wait.parity.acquire.cta.shared::cta.b64 P1, [%0], %1, 0x989680;\n\t" \
            "@P1 bra.uni WAIT_DONE_%=;\n\t" \
            "bra.uni WAIT_LOOP_%=;\n\t" \
            "WAIT_DONE_%=:\n\t}" \
            :: "r"(_mbar), "r"(_parity) : "memory"); \
    } \
} while(0)

// SS-mode f16 MMA: both A and B as SMEM descriptors.
#define TCGEN05_MMA_F16_SS(d_tmem, a_desc, b_desc, idesc, enable_d) do { \
    uint32_t _enable = (enable_d) ? 1 : 0; \
    uint32_t _zero = 0; \
    asm volatile( \
        "{\n\t.reg .pred p;\n\t" \
        "setp.ne.u32 p, %6, 0;\n\t" \
        "tcgen05.mma.cta_group::1.kind::f16 [%0], %1, %2, %3, " \
        "{%4, %4, %4, %4}, p;\n\t}" \
        :: "r"(d_tmem), "l"(a_desc), "l"(b_desc), "r"(idesc), \
           "r"(_zero), "r"(_zero), "r"(_enable) \
        : "memory"); \
} while(0)

#define TCGEN05_LD_32X32B_X32(r, tmem_addr) \
    asm volatile( \
        "tcgen05.ld.sync.aligned.32x32b.x32.b32 " \
        "{%0, %1, %2, %3, %4, %5, %6, %7, " \
        " %8, %9, %10, %11, %12, %13, %14, %15, " \
        " %16, %17, %18, %19, %20, %21, %22, %23, " \
        " %24, %25, %26, %27, %28, %29, %30, %31}, [%32];" \
        : "=r"((r)[0]),  "=r"((r)[1]),  "=r"((r)[2]),  "=r"((r)[3]), \
          "=r"((r)[4]),  "=r"((r)[5]),  "=r"((r)[6]),  "=r"((r)[7]), \
          "=r"((r)[8]),  "=r"((r)[9]),  "=r"((r)[10]), "=r"((r)[11]), \
          "=r"((r)[12]), "=r"((r)[13]), "=r"((r)[14]), "=r"((r)[15]), \
          "=r"((r)[16]), "=r"((r)[17]), "=r"((r)[18]), "=r"((r)[19]), \
          "=r"((r)[20]), "=r"((r)[21]), "=r"((r)[22]), "=r"((r)[23]), \
          "=r"((r)[24]), "=r"((r)[25]), "=r"((r)[26]), "=r"((r)[27]), \
          "=r"((r)[28]), "=r"((r)[29]), "=r"((r)[30]), "=r"((r)[31]) \
        : "r"(tmem_addr))

static constexpr uint64_t SMEM_DESC_BASE_SW128 =
    (uint64_t(2) << 61) | (uint64_t(1) << 46) | (uint64_t(64) << 32) | (uint64_t(1) << 16);
#define MAKE_SMEM_DESC(base_addr) \
    (SMEM_DESC_BASE_SW128 | ((uint64_t)((base_addr) >> 4) & 0x3FFF))

// kind::f16, f16 inputs, f32 acc, M=128 (8<<24), N=128 (16<<17)
#define MMA_IDESC_F16 0x8200010u

// SMEM layout (TC): [0] tmem ptr,
// full[t]  @16+8t (count 256, cp.async-armed), t = 0..3
// empty[t] @48+8t (tcgen05 commit target)
// W mbars @80,88, bias @128..640,
// A tiles @1024 (4 x 32KB), W stages @132096 (2 x 32KB). Total 197632.
// A tile: 2 K-slices of 16KB (cols 0..63 / 64..127), rows 0..127, SW128 atoms.
// TMEM: tile t accumulator D at cols t*128 (M=128 lanes x N=128 f32).
#define MB_FULL(t)  (16u + (uint32_t)(t) * 8u)
#define MB_EMPTY(t) (48u + (uint32_t)(t) * 8u)
#define MB_WMB(s)   (80u + (uint32_t)(s) * 8u)
#define BIAS_OFF 128
#define A_OFF(t) (1024u + (uint32_t)(t) * 32768u)
#define W_OFF(s) (132096u + (uint32_t)(s) * 32768u)

__global__ void __launch_bounds__(NTHREADS, 1)
k_main(const float* __restrict__ bias, float* __restrict__ out) {
    extern __shared__ char smem[];
    uint32_t sb = smem_to_u32(smem);
    int tid = threadIdx.x;
    int wid = tid >> 5;
    int lid = tid & 31;
    int o0 = blockIdx.x * 512;

    if (wid == 8) TCGEN05_ALLOC(sb + 0, 512);
    if (tid == 0) {
        #pragma unroll
        for (int t = 0; t < 4; ++t) {
            MBARRIER_INIT(sb + MB_FULL(t), 256);
            MBARRIER_INIT(sb + MB_EMPTY(t), 1);
        }
        MBARRIER_INIT(sb + MB_WMB(0), 1);
        MBARRIER_INIT(sb + MB_WMB(1), 1);
    }
    if (tid < 128) ((float*)(smem + BIAS_OFF))[tid] = __ldg(&bias[tid]);
    __syncthreads();
    uint32_t tmem;
    asm volatile("ld.shared.b32 %0, [%1];" : "=r"(tmem) : "r"(sb));
    if (wid == 8) TCGEN05_RELINQUISH_ALLOC_PERMIT();

    if (tid < 256) {
        // ------- producers: 8 warps, fire-and-forget cp.async fills, 4 tiles ----
        const int c = tid & 15;              // 16B chunk within row
        const int row0 = tid >> 4;           // base row in tile (0..15), step 16
        const uint4* fbase = (const uint4*)g_f16 + c;
        uint32_t aswz;
        {
            uint32_t off = ((uint32_t)(c >> 3) << 14)      // 16KB K-slice
                         + (uint32_t)row0 * 128u
                         + (uint32_t)((c & 7) << 4);
            off ^= (off >> 3) & 0x70u;                     // SW128 swizzle
            aswz = off;
        }
        // prologue: prefetch nbr(k=0) for all 4 tiles
        int nbR[32];
        {
            const int* nbk = g_nbr + 0 * NV + o0 + row0;
            #pragma unroll
            for (int t = 0; t < 4; ++t)
                #pragma unroll
                for (int j = 0; j < 8; ++j)
                    nbR[t * 8 + j] = __ldg(nbk + t * 128 + 16 * j);
        }
        for (int k = 0; k < KK; ++k) {
            #pragma unroll
            for (int t = 0; t < 4; ++t) {
                if (k >= 1) MBARRIER_WAIT_PARITY(sb + MB_EMPTY(t), (k - 1) & 1);
                uint32_t As = sb + A_OFF(t) + aswz;
                #pragma unroll
                for (int j = 0; j < 8; ++j) {
                    int nb = nbR[t * 8 + j];
                    uint32_t sz = nb ? 16u : 0u;   // missing neighbor: HW zero-fill, no read
                    CP_ASYNC_CA16_SZ(As + (uint32_t)j * 2048u,
                                     fbase + (size_t)nb * 16, sz);
                }
                CP_ASYNC_MBAR_ARRIVE_NOINC(sb + MB_FULL(t));
            }
            // prefetch nbr(k+1) off the critical path
            if (k + 1 < KK) {
                const int* nbk = g_nbr + (k + 1) * NV + o0 + row0;
                #pragma unroll
                for (int t = 0; t < 4; ++t)
                    #pragma unroll
                    for (int j = 0; j < 8; ++j)
                        nbR[t * 8 + j] = __ldg(nbk + t * 128 + 16 * j);
            }
        }
        // ------- per-tile early epilogue: warps 0-3 -> tile 2p, 4-7 -> 2p+1 ----
        const float* bsm = (const float*)(smem + BIAS_OFF);
        #pragma unroll
        for (int pass = 0; pass < 2; ++pass) {
            int t = pass * 2 + (wid >> 2);
            // wait only THIS tile's final commit (27 commits -> phase 26, parity 0)
            MBARRIER_WAIT_PARITY(sb + MB_EMPTY(t), 0);
            TCGEN05_FENCE_AFTER();
            int row = t * 128 + (wid & 3) * 32 + lid;
            uint32_t cbase = (uint32_t)(t * 128);
            float* orow = out + (size_t)(o0 + row) * CH;
            #pragma unroll
            for (int b = 0; b < 128; b += 32) {
                uint32_t d[32];
                TCGEN05_LD_32X32B_X32(d, tmem + cbase + (uint32_t)b);
                TCGEN05_WAIT_LD();
                #pragma unroll
                for (int cc = 0; cc < 32; cc += 4) {
                    float4 v;
                    v.x = __uint_as_float(d[cc + 0]) + bsm[b + cc + 0];
                    v.y = __uint_as_float(d[cc + 1]) + bsm[b + cc + 1];
                    v.z = __uint_as_float(d[cc + 2]) + bsm[b + cc + 2];
                    v.w = __uint_as_float(d[cc + 3]) + bsm[b + cc + 3];
                    *(float4*)(orow + b + cc) = v;
                }
            }
        }
    } else {
        // ---------------- leader warp: W prefetch + round-robin MMA ----------
        uint32_t lead = elect_one_pred();
        // prologue: W(0) and W(1) into their stages
        if (lead) {
            MBARRIER_EXPECT_TX(sb + MB_WMB(0), 32768);
            CP_BULK_G2S(sb + W_OFF(0), (const char*)g_w16, 32768, sb + MB_WMB(0));
            MBARRIER_EXPECT_TX(sb + MB_WMB(1), 32768);
            CP_BULK_G2S(sb + W_OFF(1), (const char*)g_w16 + 32768, 32768, sb + MB_WMB(1));
        }
        for (int k = 0; k < KK; ++k) {
            int s = k & 1;
            // W(k) ready? WMB(s) phases: k = s, s+2, ... -> wait parity (k>>1)&1
            MBARRIER_WAIT_PARITY(sb + MB_WMB(s), (k >> 1) & 1);
            uint64_t bd = MAKE_SMEM_DESC(sb + W_OFF(s));
            #pragma unroll
            for (int t = 0; t < 4; ++t) {
                MBARRIER_WAIT_PARITY(sb + MB_FULL(t), k & 1);
                FENCE_PROXY_ASYNC_SHARED_CTA();
                TCGEN05_FENCE_AFTER();
                if (lead) {
                    uint64_t ad = MAKE_SMEM_DESC(sb + A_OFF(t));
                    #pragma unroll
                    for (int ks = 0; ks < 8; ++ks) {
                        uint64_t doff = (ks < 4) ? (uint64_t)(2 * ks)
                                                 : (uint64_t)(1024 + 2 * (ks - 4));
                        TCGEN05_MMA_F16_SS(tmem + (uint32_t)(t * 128),
                                           ad + doff, bd + doff, MMA_IDESC_F16,
                                           !(k == 0 && ks == 0));
                    }
                    TCGEN05_COMMIT(sb + MB_EMPTY(t));
                }
            }
            // issue W(k+2) into stage s after this iteration's MMAs complete
            // (tile 3 commit of iteration k covers all stage-s reads of W(k)).
            if (k + 2 < KK) {
                MBARRIER_WAIT_PARITY(sb + MB_EMPTY(3), k & 1);
                if (lead) {
                    MBARRIER_EXPECT_TX(sb + MB_WMB(s), 32768);
                    CP_BULK_G2S(sb + W_OFF(s), (const char*)g_w16 + (size_t)(k + 2) * 32768,
                                32768, sb + MB_WMB(s));
                }
            }
        }
    }
    __syncthreads();
    if (wid == 8) TCGEN05_DEALLOC(tmem, 512);
}

#else  // ---------------- mma.sync fallback path (512 rows via 4 halves) -------
#define A_FB(w)  ((w) * 4096)
#define W_FB     32768
#define BIAS_FB  65536

__device__ __forceinline__ void mma16816(float* c, uint32_t a0, uint32_t a1,
                                         uint32_t a2, uint32_t a3,
                                         uint32_t b0, uint32_t b1) {
    asm volatile(
        "mma.sync.aligned.m16n8k16.row.col.f32.f16.f16.f32 "
        "{%0,%1,%2,%3}, {%4,%5,%6,%7}, {%8,%9}, {%0,%1,%2,%3};"
        : "+f"(c[0]), "+f"(c[1]), "+f"(c[2]), "+f"(c[3])
        : "r"(a0), "r"(a1), "r"(a2), "r"(a3), "r"(b0), "r"(b1));
}

__global__ void __launch_bounds__(NTHREADS)
k_main(const float* __restrict__ bias, float* __restrict__ out) {
    extern __shared__ char smem[];
    uint32_t sb = smem_to_u32(smem);
    int tid = threadIdx.x;
    int wid = tid >> 5;
    int lane = tid & 31;

    if (tid < 128) ((float*)(smem + BIAS_FB))[tid] = __ldg(&bias[tid]);

    int m = lane >> 3, rl = lane & 7;
    int lrow = rl + ((m & 1) << 3);

    for (int half = 0; half < 4; ++half) {
        int o0 = blockIdx.x * 512 + half * 128;
        float acc[16][4] = {};
        for (int k = 0; k < KK; ++k) {
            __syncthreads();
            if (tid < 256) {
                int nbl = (lane < 16) ? __ldg(&g_nbr[k * NV + o0 + wid * 16 + lane]) : 0;
                char* ab = smem + A_FB(wid);
                #pragma unroll
                for (int i = 0; i < 8; ++i) {
                    int row = i * 2 + (lane >> 4);
                    int rn = __shfl_sync(0xffffffffu, nbl, row);
                    uint4 v = __ldg((const uint4*)(g_f16 + (size_t)rn * CH) + (lane & 15));
                    int c = lane & 15;
                    *(uint4*)(ab + row * 256 + ((c ^ (row & 7)) << 4)) = v;
                }
                const uint4* ws = (const uint4*)((const char*)g_w16 + (size_t)k * 32768)
                                  + wid * 256 + lane;
                uint4* wd = (uint4*)(smem + W_FB) + wid * 256 + lane;
                #pragma unroll
                for (int i = 0; i < 8; ++i) wd[i * 32] = __ldg(ws + i * 32);
            }
            __syncthreads();
            if (tid < 256) {
                uint32_t ab32 = sb + A_FB(wid);
                uint32_t wb32 = sb + W_FB;
                uint32_t arow = ab32 + (uint32_t)lrow * 256u;
                #pragma unroll
                for (int kt = 0; kt < 8; ++kt) {
                    int chunk = kt * 2 + (m >> 1);
                    uint32_t aaddr = arow + (uint32_t)((chunk ^ (lrow & 7)) << 4);
                    uint32_t a0, a1, a2, a3;
                    asm volatile(
                        "ldmatrix.sync.aligned.m8n8.x4.shared.b16 {%0,%1,%2,%3}, [%4];"
                        : "=r"(a0), "=r"(a1), "=r"(a2), "=r"(a3) : "r"(aaddr));
                    #pragma unroll
                    for (int nt = 0; nt < 16; ++nt) {
                        uint32_t baddr = wb32 + (uint32_t)((((kt << 4) + nt) << 8) + (lane << 3));
                        uint32_t b0, b1;
                        asm volatile("ld.shared.v2.b32 {%0,%1}, [%2];"
                                     : "=r"(b0), "=r"(b1) : "r"(baddr));
                        mma16816(acc[nt], a0, a1, a2, a3, b0, b1);
                    }
                }
            }
        }
        if (tid < 256) {
            int gid = lane >> 2, tig = lane & 3;
            const float* bsm = (const float*)(smem + BIAS_FB);
            size_t r0 = (size_t)(o0 + wid * 16 + gid);
            #pragma unroll
            for (int nt = 0; nt < 16; ++nt) {
                int col = nt * 8 + tig * 2;
                float2 bv = *(const float2*)(bsm + col);
                float2 v0 = make_float2(acc[nt][0] + bv.x, acc[nt][1] + bv.y);
                float2 v1 = make_float2(acc[nt][2] + bv.x, acc[nt][3] + bv.y);
                *(float2*)(out + r0 * CH + col) = v0;
                *(float2*)(out + (r0 + 8) * CH + col) = v1;
            }
        }
        __syncthreads();
    }
}
#endif  // TC_PATH

// ---------------- fused prep kernel ----------------
// blocks [0, 6912): rulebook scatter (g_nbr = in_idx+1)
// blocks [6912, 15104): feature fp16 convert, float4-vectorized (+1 row shift)
// blocks [15104, 16832): weight pack (per-path layout)
#define PREP_BLOCKS 16832

__global__ void k_prep(const float* __restrict__ f, const float* __restrict__ w,
                       const int* __restrict__ in_idx, const int* __restrict__ out_idx) {
    int b = blockIdx.x;
    if (b < 6912) {
        int i = b * 256 + threadIdx.x;            // [0, KK*NV)
        int o = out_idx[i];
        if (o < NV) g_nbr[(i / NV) * NV + o] = in_idx[i] + 1;
    } else if (b < 15104) {
        int i = (b - 6912) * 256 + threadIdx.x;   // [0, NV*32) float4 words
        float4 v = ((const float4*)f)[i];
        __half2 h0, h1;
        h0.x = __float2half_rn(v.x); h0.y = __float2half_rn(v.y);
        h1.x = __float2half_rn(v.z); h1.y = __float2half_rn(v.w);
        uint2 pk;
        pk.x = *(uint32_t*)&h0; pk.y = *(uint32_t*)&h1;
        ((uint2*)g_f16)[i + 32] = pk;             // +1 row shift (row 0 stays zero)
    } else {
        int i = (b - 15104) * 256 + threadIdx.x;
#if TC_PATH
        // W[k][cin][cout] -> B[k][cout(row)][cin(col)] fp16, SW128 blocked image
        if (i >= KK * CH * CH) return;
        int k = i >> 14;
        int r = (i >> 7) & 127;   // c_out (N row)
        int c = i & 127;          // c_in  (K col)
        float v = w[(k << 14) + (c << 7) + r];
        uint32_t atom = (uint32_t)(r >> 3) + ((uint32_t)(c >> 6) << 4);
        uint32_t off = atom * 1024u + (uint32_t)(r & 7) * 128u + (uint32_t)(c & 63) * 2u;
        off ^= (off >> 3) & 0x70u;
        g_w16[((uint32_t)k * 32768u + off) >> 1] = __float2half_rn(v);
#else
        // mma.sync B-fragment-ready image: [k][ktile(8)][ntile(16)][lane(32)][reg(2)] u32
        if (i >= KK * 8 * 16 * 32 * 2) return;
        int reg   = i & 1;
        int lane  = (i >> 1) & 31;
        int nt    = (i >> 6) & 15;
        int ktile = (i >> 10) & 7;
        int k     = i >> 13;
        int tig = lane & 3, gid = lane >> 2;
        int n    = nt * 8 + gid;
        int cin0 = ktile * 16 + tig * 2 + reg * 8;
        float w0 = w[(k * CH + cin0) * CH + n];
        float w1 = w[(k * CH + cin0 + 1) * CH + n];
        __half2 h;
        h.x = __float2half_rn(w0);
        h.y = __float2half_rn(w1);
        ((__half2*)g_w16)[i] = h;
#endif
    }
}

// ---------------- launch ----------------
extern "C" void kernel_launch(void* const* d_in, const int* in_sizes, int n_in,
                              void* d_out, int out_size) {
    const float* features = (const float*)d_in[0];
    const float* weight   = (const float*)d_in[1];
    const float* bias     = (const float*)d_in[2];
    const int*   in_idx   = (const int*)d_in[3];
    const int*   out_idx  = (const int*)d_in[4];
    float*       out      = (float*)d_out;

    cudaFuncSetAttribute(k_main, cudaFuncAttributeMaxDynamicSharedMemorySize, SMEM_BYTES);

    k_prep<<<PREP_BLOCKS, 256>>>(features, weight, in_idx, out_idx);
    k_main<<<NV / 512, NTHREADS, SMEM_BYTES>>>(bias, out);
}